// round 9
// baseline (speedup 1.0000x reference)
#include <cuda_runtime.h>
#include <cuda_fp16.h>
#include <cstdint>
#include <math.h>

// Problem constants
#define NSAMP 256            // B*L
#define W_    128
#define C_    512
#define HD_   256
#define MROWS 32768          // B*W
#define OUT0  ((size_t)16777216)   // B*L*W*C

// ---------------- scratch (static device globals; no allocations) ----------------
__device__ __half g_ZX [(size_t)MROWS * 2048];  // combined intra projections, fp16
__device__ float g_FC [(size_t)MROWS * 512];
__device__ float g_bfc[2048];
__device__ float g_biP[2048];
__device__ unsigned long long g_barG[8 * 16];   // per-group monotonic tickets

// fp16 operand buffers
__device__ __half g_Ah [(size_t)MROWS * 1024];
__device__ __half g_Bt [(size_t)2048 * 1024];
// recurrence state / weights / outputs (fp16)
__device__ __half g_Hh[2][512 * 256];
__device__ __half g_Ut[(size_t)2048 * 256];
__device__ __half g_HSh[(size_t)MROWS * 512];
// fallback h/c buffers when out buffer is small
__device__ float g_HCfb[2][(size_t)MROWS * 512];

__device__ __forceinline__ float hsig(float x) {
    return fminf(fmaxf(fmaf(0.2f, x, 0.5f), 0.0f), 1.0f);
}

// ================= low-level helpers (sm_80-baseline ISA only) =================
__device__ __forceinline__ uint32_t smem_u32(const void* p) {
    uint32_t a;
    asm("{ .reg .u64 t; cvta.to.shared.u64 t, %1; cvt.u32.u64 %0, t; }" : "=r"(a) : "l"(p));
    return a;
}
#define CP_ASYNC16(dst, src) \
    asm volatile("cp.async.cg.shared.global [%0], [%1], 16;" :: "r"(dst), "l"(src) : "memory")
#define CP_COMMIT() asm volatile("cp.async.commit_group;" ::: "memory")
#define CP_WAIT1()  asm volatile("cp.async.wait_group 1;" ::: "memory")
#define CP_WAIT0()  asm volatile("cp.async.wait_group 0;" ::: "memory")

__device__ __forceinline__ void ldmx4(uint32_t* r, uint32_t addr) {
    asm volatile("ldmatrix.sync.aligned.m8n8.x4.shared.b16 {%0,%1,%2,%3}, [%4];"
        : "=r"(r[0]), "=r"(r[1]), "=r"(r[2]), "=r"(r[3]) : "r"(addr));
}
__device__ __forceinline__ void mma_f16(float* d, const uint32_t* a, const uint32_t* b) {
    asm volatile("mma.sync.aligned.m16n8k16.row.col.f32.f16.f16.f32 "
        "{%0,%1,%2,%3}, {%4,%5,%6,%7}, {%8,%9}, {%0,%1,%2,%3};"
        : "+f"(d[0]), "+f"(d[1]), "+f"(d[2]), "+f"(d[3])
        : "r"(a[0]), "r"(a[1]), "r"(a[2]), "r"(a[3]), "r"(b[0]), "r"(b[1]));
}

// ================= 128x128 fp16 GEMM (fc1/fc2) =================
#define TILE_B   10240           // 128*80
#define STG_B    20480
#define GEMM_SMEM  40960

__device__ __forceinline__ void load_chunk(uint32_t stage_base,
    const __half* __restrict__ Ah, const __half* __restrict__ Bh,
    int m0, int n0, int kk, int K, int tid)
{
#pragma unroll
    for (int i = 0; i < 2; i++) {
        const int c = tid + i * 256;
        const int row = c >> 2;
        const int seg = c & 3;
        const uint32_t doff = (uint32_t)(row * 80 + seg * 16);
        const size_t akoff = (size_t)kk + seg * 8;
        CP_ASYNC16(stage_base + 0 * TILE_B + doff, Ah + (size_t)(m0 + row) * K + akoff);
        CP_ASYNC16(stage_base + 1 * TILE_B + doff, Bh + (size_t)(n0 + row) * K + akoff);
    }
}

__global__ __launch_bounds__(256, 2) void tcgemm(
    const __half* __restrict__ Ah, const __half* __restrict__ Bh,
    float* __restrict__ Cmat, const float* __restrict__ bias,
    int M, int N, int K)
{
    extern __shared__ __align__(128) char smem_raw[];
    const uint32_t sb = smem_u32(smem_raw);

    const int tid = threadIdx.x;
    const int lane = tid & 31;
    const int wid = tid >> 5;
    const int wm = wid >> 2;
    const int wn = wid & 3;
    const int m0 = blockIdx.y << 7;
    const int n0 = blockIdx.x << 7;

    const uint32_t a_off = (uint32_t)((wm * 64 + (lane & 15)) * 80 + (lane >> 4) * 16);
    const int bsub = lane >> 3;
    const uint32_t b_off = (uint32_t)((wn * 32 + ((bsub >> 1) << 3) + (lane & 7)) * 80 + (bsub & 1) * 16);

    float acc[4][4][4];
#pragma unroll
    for (int mf = 0; mf < 4; mf++)
#pragma unroll
        for (int nf = 0; nf < 4; nf++)
#pragma unroll
            for (int r = 0; r < 4; r++) acc[mf][nf][r] = 0.0f;

    const int NC = K >> 5;
    load_chunk(sb, Ah, Bh, m0, n0, 0, K, tid);
    CP_COMMIT();
    load_chunk(sb + STG_B, Ah, Bh, m0, n0, 32, K, tid);
    CP_COMMIT();
    for (int c = 0; c < NC; c++) {
        CP_WAIT1();
        __syncthreads();
        const uint32_t st = sb + (c & 1) * STG_B;
#pragma unroll
        for (int ks = 0; ks < 2; ks++) {
            const uint32_t kb = st + ks * 32;
            uint32_t af[4][4], bhf[4][2], t4[4];
#pragma unroll
            for (int nh = 0; nh < 2; nh++) {
                ldmx4(t4, kb + 1 * TILE_B + b_off + nh * 1280);
                bhf[2*nh][0] = t4[0]; bhf[2*nh][1] = t4[1];
                bhf[2*nh+1][0] = t4[2]; bhf[2*nh+1][1] = t4[3];
            }
#pragma unroll
            for (int mf = 0; mf < 4; mf++) ldmx4(af[mf], kb + a_off + mf * 1280);
#pragma unroll
            for (int mf = 0; mf < 4; mf++)
#pragma unroll
                for (int nf = 0; nf < 4; nf++)
                    mma_f16(acc[mf][nf], af[mf], bhf[nf]);
        }
        __syncthreads();
        if (c + 2 < NC)
            load_chunk(sb + (c & 1) * STG_B, Ah, Bh, m0, n0, (c + 2) << 5, K, tid);
        CP_COMMIT();
    }

    const int qr = lane >> 2;
    const int qc = (lane & 3) << 1;
#pragma unroll
    for (int mf = 0; mf < 4; mf++) {
        const int row = m0 + wm * 64 + mf * 16 + qr;
#pragma unroll
        for (int nf = 0; nf < 4; nf++) {
            const int col = n0 + wn * 32 + nf * 8 + qc;
            const float2 bv = *(const float2*)(bias + col);
            float2 v0 = make_float2(acc[mf][nf][0] + bv.x, acc[mf][nf][1] + bv.y);
            float2 v1 = make_float2(acc[mf][nf][2] + bv.x, acc[mf][nf][3] + bv.y);
            *(float2*)(Cmat + (size_t)row * N + col) = v0;
            *(float2*)(Cmat + (size_t)(row + 8) * N + col) = v1;
        }
    }
}

// ================= 256x128 fp16 GEMM machinery =================
#define T256_A   20480           // 256*80
#define T256_STG 30720           // A(256) + B(128)
#define G256_SMEM   61440
#define G256G_SMEM  67584        // gates: max(stages, 128*132*4)

__device__ __forceinline__ void load_chunk256(uint32_t stage_base,
    const __half* __restrict__ Ah, const __half* __restrict__ Bh,
    int m0, int n0, int kk, int K, int tid)
{
#pragma unroll
    for (int i = 0; i < 4; i++) {          // A: 256 rows
        const int c = tid + i * 256;
        const int row = c >> 2;
        const int seg = c & 3;
        CP_ASYNC16(stage_base + (uint32_t)(row * 80 + seg * 16),
                   Ah + (size_t)(m0 + row) * K + kk + seg * 8);
    }
#pragma unroll
    for (int i = 0; i < 2; i++) {          // B: 128 rows
        const int c = tid + i * 256;
        const int row = c >> 2;
        const int seg = c & 3;
        CP_ASYNC16(stage_base + T256_A + (uint32_t)(row * 80 + seg * 16),
                   Bh + (size_t)(n0 + row) * K + kk + seg * 8);
    }
}

// mainloop: warp (wm 0..3, wn 0..1), warp tile 64x64, acc[4][8][4]
#define G256_MAINLOOP(Ah, Bh, m0, n0, K, acc)                                     \
    {                                                                             \
        const int NC = (K) >> 5;                                                  \
        load_chunk256(sb, Ah, Bh, m0, n0, 0, K, tid);                             \
        CP_COMMIT();                                                              \
        load_chunk256(sb + T256_STG, Ah, Bh, m0, n0, 32, K, tid);                 \
        CP_COMMIT();                                                              \
        for (int c = 0; c < NC; c++) {                                            \
            CP_WAIT1();                                                           \
            __syncthreads();                                                      \
            const uint32_t st = sb + (c & 1) * T256_STG;                          \
            _Pragma("unroll")                                                     \
            for (int ks = 0; ks < 2; ks++) {                                      \
                const uint32_t kb = st + ks * 32;                                 \
                uint32_t af[4][4], bhf[8][2], t4[4];                              \
                _Pragma("unroll")                                                 \
                for (int nh = 0; nh < 4; nh++) {                                  \
                    ldmx4(t4, kb + T256_A + b_off + nh * 1280);                   \
                    bhf[2*nh][0] = t4[0]; bhf[2*nh][1] = t4[1];                   \
                    bhf[2*nh+1][0] = t4[2]; bhf[2*nh+1][1] = t4[3];               \
                }                                                                 \
                _Pragma("unroll")                                                 \
                for (int mf = 0; mf < 4; mf++) ldmx4(af[mf], kb + a_off + mf * 1280); \
                _Pragma("unroll")                                                 \
                for (int mf = 0; mf < 4; mf++)                                    \
                    _Pragma("unroll")                                             \
                    for (int nf = 0; nf < 8; nf++)                                \
                        mma_f16(acc[mf][nf], af[mf], bhf[nf]);                    \
            }                                                                     \
            __syncthreads();                                                      \
            if (c + 2 < NC)                                                       \
                load_chunk256(sb + (c & 1) * T256_STG, Ah, Bh, m0, n0, (c + 2) << 5, K, tid); \
            CP_COMMIT();                                                          \
        }                                                                         \
    }

// proj GEMM: 256x128 tiles, fp16 output (+fp32 bias)
__global__ __launch_bounds__(256, 1) void tcgemm256_h(
    const __half* __restrict__ Ah, const __half* __restrict__ Bh,
    __half* __restrict__ Cmat, const float* __restrict__ bias,
    int M, int N, int K)
{
    extern __shared__ __align__(128) char smem_raw[];
    const uint32_t sb = smem_u32(smem_raw);

    const int tid = threadIdx.x;
    const int lane = tid & 31;
    const int wid = tid >> 5;
    const int wm = wid & 3;          // 4 m-warps
    const int wn = wid >> 2;         // 2 n-warps
    const int m0 = blockIdx.y << 8;
    const int n0 = blockIdx.x << 7;

    const uint32_t a_off = (uint32_t)((wm * 64 + (lane & 15)) * 80 + (lane >> 4) * 16);
    const int bsub = lane >> 3;
    const uint32_t b_off = (uint32_t)((wn * 64 + ((bsub >> 1) << 3) + (lane & 7)) * 80 + (bsub & 1) * 16);

    float acc[4][8][4];
#pragma unroll
    for (int mf = 0; mf < 4; mf++)
#pragma unroll
        for (int nf = 0; nf < 8; nf++)
#pragma unroll
            for (int r = 0; r < 4; r++) acc[mf][nf][r] = 0.0f;

    G256_MAINLOOP(Ah, Bh, m0, n0, K, acc);

    const int qr = lane >> 2;
    const int qc = (lane & 3) << 1;
#pragma unroll
    for (int mf = 0; mf < 4; mf++) {
        const int row = m0 + wm * 64 + mf * 16 + qr;
#pragma unroll
        for (int nf = 0; nf < 8; nf++) {
            const int col = n0 + wn * 64 + nf * 8 + qc;
            const float2 bv = *(const float2*)(bias + col);
            *(__half2*)(Cmat + (size_t)row * N + col) =
                __half2(__float2half_rn(acc[mf][nf][0] + bv.x),
                        __float2half_rn(acc[mf][nf][1] + bv.y));
            *(__half2*)(Cmat + (size_t)(row + 8) * N + col) =
                __half2(__float2half_rn(acc[mf][nf][2] + bv.x),
                        __float2half_rn(acc[mf][nf][3] + bv.y));
        }
    }
}

// inter GEMM 256x128 with fused LSTM gate epilogue (two 128-row passes)
__global__ __launch_bounds__(256, 1) void tcgemm_gates256(
    const __half* __restrict__ Ah, const __half* __restrict__ Bh,
    const float* __restrict__ biasP, const float* __restrict__ c0,
    float* __restrict__ h_out, float* __restrict__ c_out,
    __half* __restrict__ hh_out, int K)
{
    extern __shared__ __align__(128) char smem_raw[];
    const uint32_t sb = smem_u32(smem_raw);

    const int tid = threadIdx.x;
    const int lane = tid & 31;
    const int wid = tid >> 5;
    const int wm = wid & 3;
    const int wn = wid >> 2;
    const int m0 = blockIdx.y << 8;
    const int n0 = blockIdx.x << 7;
    const int hid0 = blockIdx.x << 5;

    const uint32_t a_off = (uint32_t)((wm * 64 + (lane & 15)) * 80 + (lane >> 4) * 16);
    const int bsub = lane >> 3;
    const uint32_t b_off = (uint32_t)((wn * 64 + ((bsub >> 1) << 3) + (lane & 7)) * 80 + (bsub & 1) * 16);

    float acc[4][8][4];
#pragma unroll
    for (int mf = 0; mf < 4; mf++)
#pragma unroll
        for (int nf = 0; nf < 8; nf++)
#pragma unroll
            for (int r = 0; r < 4; r++) acc[mf][nf][r] = 0.0f;

    G256_MAINLOOP(Ah, Bh, m0, n0, K, acc);

    float* stg = (float*)smem_raw;    // 128 x 132 per pass
    const int qr = lane >> 2;
    const int qc = (lane & 3) << 1;

#pragma unroll
    for (int p = 0; p < 2; p++) {
        __syncthreads();
        // warps with wm in {2p, 2p+1} stage their 64-row halves
        if ((wm >> 1) == p) {
            const int mbase = (wm & 1) * 64;
#pragma unroll
            for (int mf = 0; mf < 4; mf++) {
                const int rl = mbase + mf * 16 + qr;
#pragma unroll
                for (int nf = 0; nf < 8; nf++) {
                    const int col = wn * 64 + nf * 8 + qc;
                    const float2 bv = *(const float2*)(biasP + n0 + col);
                    stg[rl * 132 + col]           = acc[mf][nf][0] + bv.x;
                    stg[rl * 132 + col + 1]       = acc[mf][nf][1] + bv.y;
                    stg[(rl + 8) * 132 + col]     = acc[mf][nf][2] + bv.x;
                    stg[(rl + 8) * 132 + col + 1] = acc[mf][nf][3] + bv.y;
                }
            }
        }
        __syncthreads();
        // gate update for 128 rows
        {
            const int c = lane;
#pragma unroll
            for (int i = 0; i < 16; i++) {
                const int r = wid * 16 + i;
                const float zi = stg[r * 132 + c];
                const float zf = stg[r * 132 + 32 + c];
                const float zg = stg[r * 132 + 64 + c];
                const float zo = stg[r * 132 + 96 + c];
                const size_t go = (size_t)(m0 + p * 128 + r) * 512 + hid0 + c;
                const float cn = hsig(zf) * c0[go] + hsig(zi) * tanhf(zg);
                const float hv = hsig(zo) * tanhf(cn);
                c_out[go] = cn;
                h_out[go] = hv;
                hh_out[go] = __float2half_rn(hv);
            }
        }
    }
}

// ================= convert kernels =================
__global__ __launch_bounds__(256) void cvt_kernel(
    const float* __restrict__ in, __half* __restrict__ out, int n4)
{
    const int i = blockIdx.x * blockDim.x + threadIdx.x;
    if (i >= n4) return;
    const float4 v = ((const float4*)in)[i];
    ((__half2*)out)[2 * i]     = __half2(__float2half_rn(v.x), __float2half_rn(v.y));
    ((__half2*)out)[2 * i + 1] = __half2(__float2half_rn(v.z), __float2half_rn(v.w));
}

// h0 [32768,512] -> g_Ah at row*1024 + 512 + col
__global__ __launch_bounds__(256) void cvt_off_kernel(
    const float* __restrict__ in, __half* __restrict__ out)
{
    const int q = blockIdx.x * blockDim.x + threadIdx.x;
    const int row = q >> 7;
    const int col = (q & 127) << 2;
    const float4 v = ((const float4*)in)[q];
    const size_t o = (size_t)row * 1024 + 512 + col;
    *(__half2*)(out + o)     = __half2(__float2half_rn(v.x), __float2half_rn(v.y));
    *(__half2*)(out + o + 2) = __half2(__float2half_rn(v.z), __float2half_rn(v.w));
}

// transpose-convert: W [K,N] fp32 -> [N,K] fp16
__global__ void cvtT_kernel(const float* __restrict__ Wm,
                            __half* __restrict__ dst, int K, int N)
{
    __shared__ float t[32][33];
    const int kb = blockIdx.y * 32, nb = blockIdx.x * 32;
    const int tx = threadIdx.x, ty = threadIdx.y;
    for (int r = ty; r < 32; r += 8)
        t[r][tx] = Wm[(size_t)(kb + r) * N + nb + tx];
    __syncthreads();
    for (int r = ty; r < 32; r += 8)
        dst[(size_t)(nb + r) * K + kb + tx] = __float2half_rn(t[tx][r]);
}

// transpose-convert with gate-interleave permutation
__global__ void cvtT_perm_kernel(const float* __restrict__ Wm,
                                 __half* __restrict__ dst, int N, int Kout, int koff)
{
    __shared__ float t[32][33];
    const int kb = blockIdx.y * 32, nb = blockIdx.x * 32;
    const int tx = threadIdx.x, ty = threadIdx.y;
    for (int r = ty; r < 32; r += 8)
        t[r][tx] = Wm[(size_t)(kb + r) * N + nb + tx];
    __syncthreads();
    for (int r = ty; r < 32; r += 8) {
        const int n = nb + r;
        const int g = n >> 9, s = n & 511;
        const int nr = ((s >> 5) << 7) + (g << 5) + (s & 31);
        dst[(size_t)nr * Kout + koff + kb + tx] = __float2half_rn(t[tx][r]);
    }
}

__global__ void bias_prep(const float* __restrict__ bf, const float* __restrict__ bb,
                          const float* __restrict__ bi,
                          float* __restrict__ bfc, float* __restrict__ biP)
{
    const int i = blockIdx.x * blockDim.x + threadIdx.x;
    if (i < 1024) bfc[i] = bf[i];
    else if (i < 2048) bfc[i] = bb[i - 1024];
    else {
        const int n = i - 2048;
        const int g = n >> 9, s = n & 511;
        const int nr = ((s >> 5) << 7) + (g << 5) + (s & 31);
        biP[nr] = bi[n];
    }
}

// ---------------- group barrier (16 CTAs per group) ----------------
__device__ __forceinline__ void group_barrier(int grp) {
    __threadfence();
    __syncthreads();
    if (threadIdx.x == 0) {
        unsigned long long* ctr = &g_barG[grp * 16];
        unsigned long long t = atomicAdd(ctr, 1ULL) + 1ULL;
        unsigned long long target = ((t + 15ULL) >> 4) << 4;
        volatile unsigned long long* p = ctr;
        while (*p < target) { __nanosleep(32); }
        __threadfence();
    }
    __syncthreads();
}

// ---------------- persistent bidirectional LSTM recurrence (pure fp16, fp16 zx) ----------------
#define RA_STR   528
#define ROFF_BHI 33792
#define ROFF_STG 67584
#define ROFF_ZX  84992           // 8KB fp16 zx tile
#define RSMEM    93184

__global__ __launch_bounds__(256) void recurrence2(const __half* __restrict__ Ut)
{
    extern __shared__ __align__(128) char rsm[];
    const uint32_t sb = smem_u32(rsm);
    const int tid = threadIdx.x, lane = tid & 31, wid = tid >> 5;
    const int blk = blockIdx.x;
    const int tile_m = blk >> 4;
    const int tile_n = blk & 15;
    const int row0 = tile_m << 6;
    const int dir = (tile_m >= 4) ? 1 : 0;
    const int j0 = tile_n << 4;
    const int wm = wid & 3, wn = wid >> 2;

    for (int i = tid; i < 2048; i += 256) {
        const int r = i >> 5, seg = i & 31;
        const int g = r >> 4, c = r & 15;
        const size_t gr = ((size_t)(dir * 1024 + g * 256 + j0 + c)) * 256 + seg * 8;
        *(uint4*)(rsm + ROFF_BHI + r * RA_STR + seg * 16) = *(const uint4*)(Ut + gr);
    }

    if (tile_n == 0) {
        uint32_t* h0 = (uint32_t*)&g_Hh[0][row0 * 256];
        for (int i = tid; i < 8192; i += 256) h0[i] = 0u;
    }

    const uint32_t a_off = (uint32_t)((wm * 16 + (lane & 15)) * RA_STR + (lane >> 4) * 16);
    const int bsub = lane >> 3;
    const uint32_t b_off = (uint32_t)((wn * 32 + ((bsub >> 1) << 3) + (lane & 7)) * RA_STR + (bsub & 1) * 16);

    const int r_up = tid >> 2;
    const int c_up = (tid & 3) << 2;
    const int Rr = row0 + r_up;
    const int n_up = Rr & 255;
    float* stg = (float*)(rsm + ROFF_STG);
    const __half* zxs = (const __half*)(rsm + ROFF_ZX);
    float creg[4] = {0.0f, 0.0f, 0.0f, 0.0f};

    group_barrier(tile_m);

    for (int t = 0; t < 128; t++) {
        const int pb = t & 1;
        const int w = dir ? (127 - t) : t;
        const __half* hh = g_Hh[pb];

        // ---- commit group 1: H k 0..127 ----
#pragma unroll
        for (int ii = 0; ii < 4; ii++) {
            const int i = tid + ii * 256;
            const int r = i >> 4, seg = i & 15;
            CP_ASYNC16(sb + r * RA_STR + seg * 16, hh + (size_t)(row0 + r) * 256 + seg * 8);
        }
        CP_COMMIT();
        // ---- commit group 2: H k 128..255 + fp16 zx prefetch ----
#pragma unroll
        for (int ii = 0; ii < 4; ii++) {
            const int i = tid + ii * 256;
            const int r = i >> 4, seg = 16 + (i & 15);
            CP_ASYNC16(sb + r * RA_STR + seg * 16, hh + (size_t)(row0 + r) * 256 + seg * 8);
        }
        {
            // 64 rows x 4 gates x 16 halfs = 8KB = 512 x 16B; 2 reqs/thread
            const __half* zxg = g_ZX + ((size_t)n_up * 128 + w) * 2048 + dir * 1024 + j0;
#pragma unroll
            for (int ii = 0; ii < 2; ii++) {
                const int q = tid + ii * 256;           // 0..511
                const int r = q >> 3;                   // 0..63
                const int rem = q & 7;
                const int g = rem >> 1;
                const int part = rem & 1;
                // NOTE: source row must match r, not this thread's n_up;
                // recompute from the CTA's row block:
                const int rr = row0 + r;
                const __half* src = g_ZX + ((size_t)(rr & 255) * 128 + w) * 2048
                                   + dir * 1024 + j0 + g * 256 + part * 8;
                CP_ASYNC16(sb + ROFF_ZX + (uint32_t)(r * 128 + g * 32 + part * 16), src);
            }
            (void)zxg;
        }
        CP_COMMIT();

        float acc[4][4];
#pragma unroll
        for (int nf = 0; nf < 4; nf++)
#pragma unroll
            for (int r = 0; r < 4; r++) acc[nf][r] = 0.0f;

        CP_WAIT1();
        __syncthreads();
#pragma unroll
        for (int ks = 0; ks < 8; ks++) {
            const uint32_t kb = ks * 32;
            uint32_t ah[4], bh[4][2], t4[4];
            ldmx4(ah, sb + a_off + kb);
#pragma unroll
            for (int nh = 0; nh < 2; nh++) {
                ldmx4(t4, sb + ROFF_BHI + b_off + kb + nh * 16 * RA_STR);
                bh[2 * nh][0] = t4[0]; bh[2 * nh][1] = t4[1];
                bh[2 * nh + 1][0] = t4[2]; bh[2 * nh + 1][1] = t4[3];
            }
#pragma unroll
            for (int nf = 0; nf < 4; nf++)
                mma_f16(acc[nf], ah, bh[nf]);
        }
        CP_WAIT0();
        __syncthreads();
#pragma unroll
        for (int ks = 8; ks < 16; ks++) {
            const uint32_t kb = ks * 32;
            uint32_t ah[4], bh[4][2], t4[4];
            ldmx4(ah, sb + a_off + kb);
#pragma unroll
            for (int nh = 0; nh < 2; nh++) {
                ldmx4(t4, sb + ROFF_BHI + b_off + kb + nh * 16 * RA_STR);
                bh[2 * nh][0] = t4[0]; bh[2 * nh][1] = t4[1];
                bh[2 * nh + 1][0] = t4[2]; bh[2 * nh + 1][1] = t4[3];
            }
#pragma unroll
            for (int nf = 0; nf < 4; nf++)
                mma_f16(acc[nf], ah, bh[nf]);
        }

        {
            const int qr = lane >> 2, qc = (lane & 3) << 1;
#pragma unroll
            for (int nf = 0; nf < 4; nf++) {
                const int col = wn * 32 + nf * 8 + qc;
                stg[(wm * 16 + qr) * 68 + col]     = acc[nf][0];
                stg[(wm * 16 + qr) * 68 + col + 1] = acc[nf][1];
                stg[(wm * 16 + qr + 8) * 68 + col]     = acc[nf][2];
                stg[(wm * 16 + qr + 8) * 68 + col + 1] = acc[nf][3];
            }
        }
        __syncthreads();

        {
            __half* dhh = &g_Hh[pb ^ 1][(size_t)Rr * 256 + j0 + c_up];
            const size_t hsoff = ((size_t)n_up * 128 + w) * 512 + dir * 256 + j0 + c_up;
            const __half* zx = zxs + r_up * 64 + c_up;   // [g*16 + c]
            float hv[4];
#pragma unroll
            for (int l = 0; l < 4; l++) {
                const float* sr = &stg[r_up * 68 + c_up + l];
                const float zi = sr[0]  + __half2float(zx[l]);
                const float zf = sr[16] + __half2float(zx[16 + l]);
                const float zg = sr[32] + __half2float(zx[32 + l]);
                const float zo = sr[48] + __half2float(zx[48 + l]);
                const float cn = hsig(zf) * creg[l] + hsig(zi) * tanhf(zg);
                creg[l] = cn;
                hv[l] = hsig(zo) * tanhf(cn);
            }
            const __half2 p0 = __half2(__float2half_rn(hv[0]), __float2half_rn(hv[1]));
            const __half2 p1 = __half2(__float2half_rn(hv[2]), __float2half_rn(hv[3]));
            *(__half2*)(dhh)     = p0;
            *(__half2*)(dhh + 2) = p1;
            *(__half2*)(g_HSh + hsoff)     = p0;
            *(__half2*)(g_HSh + hsoff + 2) = p1;
        }

        if (t < 127) group_barrier(tile_m);
    }
}

// ---------------- LayerNorm over (W,C)=65536, optional fused fp16 convert (stride 1024) ----------------
__global__ __launch_bounds__(256) void ln_kernel(
    const float* __restrict__ pre, const float* __restrict__ xres,
    const float* __restrict__ gamma, const float* __restrict__ beta,
    float* __restrict__ out, __half* __restrict__ sh, int mode)
{
    __shared__ float red[256];
    const int tid = threadIdx.x;
    const size_t base = (size_t)blockIdx.x * 65536;

    float s = 0.0f, ss = 0.0f;
    for (int i = tid * 4; i < 65536; i += 1024) {
        float4 v = *(const float4*)(pre + base + i);
        s  += v.x + v.y + v.z + v.w;
        ss += v.x * v.x + v.y * v.y + v.z * v.z + v.w * v.w;
    }
    red[tid] = s; __syncthreads();
    for (int off = 128; off; off >>= 1) { if (tid < off) red[tid] += red[tid + off]; __syncthreads(); }
    const float mean = red[0] * (1.0f / 65536.0f);
    __syncthreads();
    red[tid] = ss; __syncthreads();
    for (int off = 128; off; off >>= 1) { if (tid < off) red[tid] += red[tid + off]; __syncthreads(); }
    const float var = red[0] * (1.0f / 65536.0f) - mean * mean;
    const float rstd = rsqrtf(var + 1e-3f);

    for (int i = tid * 4; i < 65536; i += 1024) {
        float4 v = *(const float4*)(pre + base + i);
        float4 g = *(const float4*)(gamma + i);
        float4 bb = *(const float4*)(beta + i);
        float4 r;
        r.x = (v.x - mean) * rstd * g.x + bb.x;
        r.y = (v.y - mean) * rstd * g.y + bb.y;
        r.z = (v.z - mean) * rstd * g.z + bb.z;
        r.w = (v.w - mean) * rstd * g.w + bb.w;
        if (mode == 0) {
            float4 xr = *(const float4*)(xres + base + i);
            r.x += xr.x; r.y += xr.y; r.z += xr.z; r.w += xr.w;
        } else {
            float4 o = *(const float4*)(out + base + i);
            r.x += o.x; r.y += o.y; r.z += o.z; r.w += o.w;
        }
        *(float4*)(out + base + i) = r;
        if (sh) {
            const size_t f = base + i;
            const size_t so = (f >> 9) * 1024 + (f & 511);
            *(__half2*)(sh + so)     = __half2(__float2half_rn(r.x), __float2half_rn(r.y));
            *(__half2*)(sh + so + 2) = __half2(__float2half_rn(r.z), __float2half_rn(r.w));
        }
    }
}

// ---------------- launch ----------------
extern "C" void kernel_launch(void* const* d_in, const int* in_sizes, int n_in,
                              void* d_out, int out_size)
{
    const float* x    = (const float*)d_in[0];
    const float* h0   = (const float*)d_in[1];
    const float* c0   = (const float*)d_in[2];
    const float* Wf   = (const float*)d_in[3];
    const float* Uf   = (const float*)d_in[4];
    const float* bf   = (const float*)d_in[5];
    const float* Wb   = (const float*)d_in[6];
    const float* Ub   = (const float*)d_in[7];
    const float* bb   = (const float*)d_in[8];
    const float* Wfc1 = (const float*)d_in[9];
    const float* bfc1 = (const float*)d_in[10];
    const float* g1   = (const float*)d_in[11];
    const float* b1   = (const float*)d_in[12];
    const float* Wi   = (const float*)d_in[13];
    const float* Ui   = (const float*)d_in[14];
    const float* bi   = (const float*)d_in[15];
    const float* Wfc2 = (const float*)d_in[16];
    const float* bfc2 = (const float*)d_in[17];
    const float* g2   = (const float*)d_in[18];
    const float* b2   = (const float*)d_in[19];

    float* out = (float*)d_out;
    float* h_out = out + OUT0;
    float* c_out = out + 2 * OUT0;
    const int full_out = (out_size >= (int)(3 * OUT0)) || out_size <= 0;

    float *fc, *bfc, *biP, *hcfb;
    __half *zx, *ah, *bt, *ut, *hsh;
    cudaGetSymbolAddress((void**)&zx,  g_ZX);
    cudaGetSymbolAddress((void**)&fc,  g_FC);
    cudaGetSymbolAddress((void**)&bfc, g_bfc);
    cudaGetSymbolAddress((void**)&biP, g_biP);
    cudaGetSymbolAddress((void**)&ah,  g_Ah);
    cudaGetSymbolAddress((void**)&bt,  g_Bt);
    cudaGetSymbolAddress((void**)&ut,  g_Ut);
    cudaGetSymbolAddress((void**)&hsh, g_HSh);
    cudaGetSymbolAddress((void**)&hcfb, g_HCfb);

    cudaFuncSetAttribute(tcgemm, cudaFuncAttributeMaxDynamicSharedMemorySize, GEMM_SMEM);
    cudaFuncSetAttribute(tcgemm256_h, cudaFuncAttributeMaxDynamicSharedMemorySize, G256_SMEM);
    cudaFuncSetAttribute(tcgemm_gates256, cudaFuncAttributeMaxDynamicSharedMemorySize, G256G_SMEM);
    cudaFuncSetAttribute(recurrence2, cudaFuncAttributeMaxDynamicSharedMemorySize, RSMEM);

    const int n4A = MROWS * 512 / 4;

    // ---- combined intra input projection: ZX(fp16) = x @ [Wf|Wb] + [bf|bb] ----
    cvt_kernel<<<n4A / 256, 256>>>(x, ah, n4A);
    bias_prep<<<16, 256>>>(bf, bb, bi, bfc, biP);
    cvtT_kernel<<<dim3(32, 16), dim3(32, 8)>>>(Wf, bt, 512, 1024);
    cvtT_kernel<<<dim3(32, 16), dim3(32, 8)>>>(Wb, bt + (size_t)1024 * 512, 512, 1024);
    tcgemm256_h<<<dim3(16, 128), 256, G256_SMEM>>>(ah, bt, zx, bfc, MROWS, 2048, 512);

    // ---- recurrent weights + recurrence ----
    cvtT_kernel<<<dim3(32, 8), dim3(32, 8)>>>(Uf, ut, 256, 1024);
    cvtT_kernel<<<dim3(32, 8), dim3(32, 8)>>>(Ub, ut + 1024 * 256, 256, 1024);
    recurrence2<<<128, 256, RSMEM>>>(ut);

    // ---- fc1 (A = HS) ----
    cvtT_kernel<<<dim3(16, 16), dim3(32, 8)>>>(Wfc1, bt, 512, 512);
    tcgemm<<<dim3(4, 256), 256, GEMM_SMEM>>>(hsh, bt, fc, bfc1, MROWS, 512, 512);

    // ---- LN1 + residual -> out, fused convert (concat A cols 0..511) ----
    ln_kernel<<<256, 256>>>(fc, x, g1, b1, out, ah, 0);

    // ---- inter: single K=1024 GEMM with fused gates ----
    cvt_off_kernel<<<16384, 256>>>(h0, ah);
    cvtT_perm_kernel<<<dim3(64, 16), dim3(32, 8)>>>(Wi, bt, 2048, 1024, 0);
    cvtT_perm_kernel<<<dim3(64, 16), dim3(32, 8)>>>(Ui, bt, 2048, 1024, 512);
    float* hptr = full_out ? h_out : hcfb;
    float* cptr = full_out ? c_out : (hcfb + (size_t)MROWS * 512);
    tcgemm_gates256<<<dim3(16, 128), 256, G256G_SMEM>>>(ah, bt, biP, c0,
                                                        hptr, cptr, hsh, 1024);

    // ---- fc2 (A = h in g_HSh) ----
    cvtT_kernel<<<dim3(16, 16), dim3(32, 8)>>>(Wfc2, bt, 512, 512);
    tcgemm<<<dim3(4, 256), 256, GEMM_SMEM>>>(hsh, bt, fc, bfc2, MROWS, 512, 512);

    // ---- LN2 accumulate into out ----
    ln_kernel<<<256, 256>>>(fc, nullptr, g2, b2, out, nullptr, 1);
}

// round 10
// speedup vs baseline: 1.1102x; 1.1102x over previous
#include <cuda_runtime.h>
#include <cuda_fp16.h>
#include <cstdint>
#include <math.h>

// Problem constants
#define NSAMP 256            // B*L
#define W_    128
#define C_    512
#define HD_   256
#define MROWS 32768          // B*W
#define OUT0  ((size_t)16777216)   // B*L*W*C

// ---------------- scratch (static device globals; no allocations) ----------------
__device__ __half g_ZX [(size_t)MROWS * 2048];  // combined intra projections, fp16
__device__ float g_FC [(size_t)MROWS * 512];
__device__ float g_bfc[2048];
__device__ float g_biP[2048];
__device__ unsigned long long g_barG[8 * 16];   // per-group monotonic tickets

// fp16 operand buffers
__device__ __half g_Ah [(size_t)MROWS * 1024];
__device__ __half g_Bt [(size_t)2048 * 1024];
// recurrence state / weights / outputs (fp16)
__device__ __half g_Hh[2][512 * 256];
__device__ __half g_Ut[(size_t)2048 * 256];
__device__ __half g_HSh[(size_t)MROWS * 512];
// fallback h/c buffers when out buffer is small
__device__ float g_HCfb[2][(size_t)MROWS * 512];

__device__ __forceinline__ float hsig(float x) {
    return fminf(fmaxf(fmaf(0.2f, x, 0.5f), 0.0f), 1.0f);
}

// ================= low-level helpers (sm_80-baseline ISA only) =================
__device__ __forceinline__ uint32_t smem_u32(const void* p) {
    uint32_t a;
    asm("{ .reg .u64 t; cvta.to.shared.u64 t, %1; cvt.u32.u64 %0, t; }" : "=r"(a) : "l"(p));
    return a;
}
#define CP_ASYNC16(dst, src) \
    asm volatile("cp.async.cg.shared.global [%0], [%1], 16;" :: "r"(dst), "l"(src) : "memory")
#define CP_COMMIT() asm volatile("cp.async.commit_group;" ::: "memory")
#define CP_WAIT1()  asm volatile("cp.async.wait_group 1;" ::: "memory")
#define CP_WAIT0()  asm volatile("cp.async.wait_group 0;" ::: "memory")

__device__ __forceinline__ void ldmx4(uint32_t* r, uint32_t addr) {
    asm volatile("ldmatrix.sync.aligned.m8n8.x4.shared.b16 {%0,%1,%2,%3}, [%4];"
        : "=r"(r[0]), "=r"(r[1]), "=r"(r[2]), "=r"(r[3]) : "r"(addr));
}
__device__ __forceinline__ void mma_f16(float* d, const uint32_t* a, const uint32_t* b) {
    asm volatile("mma.sync.aligned.m16n8k16.row.col.f32.f16.f16.f32 "
        "{%0,%1,%2,%3}, {%4,%5,%6,%7}, {%8,%9}, {%0,%1,%2,%3};"
        : "+f"(d[0]), "+f"(d[1]), "+f"(d[2]), "+f"(d[3])
        : "r"(a[0]), "r"(a[1]), "r"(a[2]), "r"(a[3]), "r"(b[0]), "r"(b[1]));
}

// ================= 128x128 fp16 GEMM (2 CTAs/SM) =================
#define TILE_B   10240           // 128*80
#define STG_B    20480
#define GEMM_SMEM  40960
#define GATES_SMEM 67584         // epilogue stg 128*132*4

__device__ __forceinline__ void load_chunk(uint32_t stage_base,
    const __half* __restrict__ Ah, const __half* __restrict__ Bh,
    int m0, int n0, int kk, int K, int tid)
{
#pragma unroll
    for (int i = 0; i < 2; i++) {
        const int c = tid + i * 256;
        const int row = c >> 2;
        const int seg = c & 3;
        const uint32_t doff = (uint32_t)(row * 80 + seg * 16);
        const size_t akoff = (size_t)kk + seg * 8;
        CP_ASYNC16(stage_base + 0 * TILE_B + doff, Ah + (size_t)(m0 + row) * K + akoff);
        CP_ASYNC16(stage_base + 1 * TILE_B + doff, Bh + (size_t)(n0 + row) * K + akoff);
    }
}

#define GEMM_MAINLOOP(Ah, Bh, m0, n0, K, acc)                                     \
    {                                                                             \
        const int NC = (K) >> 5;                                                  \
        load_chunk(sb, Ah, Bh, m0, n0, 0, K, tid);                                \
        CP_COMMIT();                                                              \
        load_chunk(sb + STG_B, Ah, Bh, m0, n0, 32, K, tid);                       \
        CP_COMMIT();                                                              \
        for (int c = 0; c < NC; c++) {                                            \
            CP_WAIT1();                                                           \
            __syncthreads();                                                      \
            const uint32_t st = sb + (c & 1) * STG_B;                             \
            _Pragma("unroll")                                                     \
            for (int ks = 0; ks < 2; ks++) {                                      \
                const uint32_t kb = st + ks * 32;                                 \
                uint32_t af[4][4], bhf[4][2], t4[4];                              \
                _Pragma("unroll")                                                 \
                for (int nh = 0; nh < 2; nh++) {                                  \
                    ldmx4(t4, kb + 1 * TILE_B + b_off + nh * 1280);               \
                    bhf[2*nh][0] = t4[0]; bhf[2*nh][1] = t4[1];                   \
                    bhf[2*nh+1][0] = t4[2]; bhf[2*nh+1][1] = t4[3];               \
                }                                                                 \
                _Pragma("unroll")                                                 \
                for (int mf = 0; mf < 4; mf++) ldmx4(af[mf], kb + a_off + mf * 1280); \
                _Pragma("unroll")                                                 \
                for (int mf = 0; mf < 4; mf++)                                    \
                    _Pragma("unroll")                                             \
                    for (int nf = 0; nf < 4; nf++)                                \
                        mma_f16(acc[mf][nf], af[mf], bhf[nf]);                    \
            }                                                                     \
            __syncthreads();                                                      \
            if (c + 2 < NC)                                                       \
                load_chunk(sb + (c & 1) * STG_B, Ah, Bh, m0, n0, (c + 2) << 5, K, tid); \
            CP_COMMIT();                                                          \
        }                                                                         \
    }

// fp32-output GEMM (fc1/fc2)
__global__ __launch_bounds__(256, 2) void tcgemm(
    const __half* __restrict__ Ah, const __half* __restrict__ Bh,
    float* __restrict__ Cmat, const float* __restrict__ bias,
    int M, int N, int K)
{
    extern __shared__ __align__(128) char smem_raw[];
    const uint32_t sb = smem_u32(smem_raw);

    const int tid = threadIdx.x;
    const int lane = tid & 31;
    const int wid = tid >> 5;
    const int wm = wid >> 2;
    const int wn = wid & 3;
    const int m0 = blockIdx.y << 7;
    const int n0 = blockIdx.x << 7;

    const uint32_t a_off = (uint32_t)((wm * 64 + (lane & 15)) * 80 + (lane >> 4) * 16);
    const int bsub = lane >> 3;
    const uint32_t b_off = (uint32_t)((wn * 32 + ((bsub >> 1) << 3) + (lane & 7)) * 80 + (bsub & 1) * 16);

    float acc[4][4][4];
#pragma unroll
    for (int mf = 0; mf < 4; mf++)
#pragma unroll
        for (int nf = 0; nf < 4; nf++)
#pragma unroll
            for (int r = 0; r < 4; r++) acc[mf][nf][r] = 0.0f;

    GEMM_MAINLOOP(Ah, Bh, m0, n0, K, acc);

    const int qr = lane >> 2;
    const int qc = (lane & 3) << 1;
#pragma unroll
    for (int mf = 0; mf < 4; mf++) {
        const int row = m0 + wm * 64 + mf * 16 + qr;
#pragma unroll
        for (int nf = 0; nf < 4; nf++) {
            const int col = n0 + wn * 32 + nf * 8 + qc;
            const float2 bv = *(const float2*)(bias + col);
            float2 v0 = make_float2(acc[mf][nf][0] + bv.x, acc[mf][nf][1] + bv.y);
            float2 v1 = make_float2(acc[mf][nf][2] + bv.x, acc[mf][nf][3] + bv.y);
            *(float2*)(Cmat + (size_t)row * N + col) = v0;
            *(float2*)(Cmat + (size_t)(row + 8) * N + col) = v1;
        }
    }
}

// fp16-output GEMM (intra projection -> ZX)
__global__ __launch_bounds__(256, 2) void tcgemm_h(
    const __half* __restrict__ Ah, const __half* __restrict__ Bh,
    __half* __restrict__ Cmat, const float* __restrict__ bias,
    int M, int N, int K)
{
    extern __shared__ __align__(128) char smem_raw[];
    const uint32_t sb = smem_u32(smem_raw);

    const int tid = threadIdx.x;
    const int lane = tid & 31;
    const int wid = tid >> 5;
    const int wm = wid >> 2;
    const int wn = wid & 3;
    const int m0 = blockIdx.y << 7;
    const int n0 = blockIdx.x << 7;

    const uint32_t a_off = (uint32_t)((wm * 64 + (lane & 15)) * 80 + (lane >> 4) * 16);
    const int bsub = lane >> 3;
    const uint32_t b_off = (uint32_t)((wn * 32 + ((bsub >> 1) << 3) + (lane & 7)) * 80 + (bsub & 1) * 16);

    float acc[4][4][4];
#pragma unroll
    for (int mf = 0; mf < 4; mf++)
#pragma unroll
        for (int nf = 0; nf < 4; nf++)
#pragma unroll
            for (int r = 0; r < 4; r++) acc[mf][nf][r] = 0.0f;

    GEMM_MAINLOOP(Ah, Bh, m0, n0, K, acc);

    const int qr = lane >> 2;
    const int qc = (lane & 3) << 1;
#pragma unroll
    for (int mf = 0; mf < 4; mf++) {
        const int row = m0 + wm * 64 + mf * 16 + qr;
#pragma unroll
        for (int nf = 0; nf < 4; nf++) {
            const int col = n0 + wn * 32 + nf * 8 + qc;
            const float2 bv = *(const float2*)(bias + col);
            *(__half2*)(Cmat + (size_t)row * N + col) =
                __half2(__float2half_rn(acc[mf][nf][0] + bv.x),
                        __float2half_rn(acc[mf][nf][1] + bv.y));
            *(__half2*)(Cmat + (size_t)(row + 8) * N + col) =
                __half2(__float2half_rn(acc[mf][nf][2] + bv.x),
                        __float2half_rn(acc[mf][nf][3] + bv.y));
        }
    }
}

// ---- inter GEMM with fused LSTM gate epilogue (gate-interleaved B layout) ----
__global__ __launch_bounds__(256, 2) void tcgemm_gates(
    const __half* __restrict__ Ah, const __half* __restrict__ Bh,
    const float* __restrict__ biasP, const float* __restrict__ c0,
    float* __restrict__ h_out, float* __restrict__ c_out,
    __half* __restrict__ hh_out, int K)
{
    extern __shared__ __align__(128) char smem_raw[];
    const uint32_t sb = smem_u32(smem_raw);

    const int tid = threadIdx.x;
    const int lane = tid & 31;
    const int wid = tid >> 5;
    const int wm = wid >> 2;
    const int wn = wid & 3;
    const int m0 = blockIdx.y << 7;
    const int n0 = blockIdx.x << 7;
    const int hid0 = blockIdx.x << 5;

    const uint32_t a_off = (uint32_t)((wm * 64 + (lane & 15)) * 80 + (lane >> 4) * 16);
    const int bsub = lane >> 3;
    const uint32_t b_off = (uint32_t)((wn * 32 + ((bsub >> 1) << 3) + (lane & 7)) * 80 + (bsub & 1) * 16);

    float acc[4][4][4];
#pragma unroll
    for (int mf = 0; mf < 4; mf++)
#pragma unroll
        for (int nf = 0; nf < 4; nf++)
#pragma unroll
            for (int r = 0; r < 4; r++) acc[mf][nf][r] = 0.0f;

    GEMM_MAINLOOP(Ah, Bh, m0, n0, K, acc);

    __syncthreads();
    float* stg = (float*)smem_raw;    // 128 x 132
    const int qr = lane >> 2;
    const int qc = (lane & 3) << 1;
#pragma unroll
    for (int mf = 0; mf < 4; mf++) {
        const int rl = wm * 64 + mf * 16 + qr;
#pragma unroll
        for (int nf = 0; nf < 4; nf++) {
            const int col = wn * 32 + nf * 8 + qc;
            const float2 bv = *(const float2*)(biasP + n0 + col);
            stg[rl * 132 + col]           = acc[mf][nf][0] + bv.x;
            stg[rl * 132 + col + 1]       = acc[mf][nf][1] + bv.y;
            stg[(rl + 8) * 132 + col]     = acc[mf][nf][2] + bv.x;
            stg[(rl + 8) * 132 + col + 1] = acc[mf][nf][3] + bv.y;
        }
    }
    __syncthreads();

    {
        const int c = lane;
#pragma unroll
        for (int i = 0; i < 16; i++) {
            const int r = wid * 16 + i;
            const float zi = stg[r * 132 + c];
            const float zf = stg[r * 132 + 32 + c];
            const float zg = stg[r * 132 + 64 + c];
            const float zo = stg[r * 132 + 96 + c];
            const size_t go = (size_t)(m0 + r) * 512 + hid0 + c;
            const float cn = hsig(zf) * c0[go] + hsig(zi) * tanhf(zg);
            const float hv = hsig(zo) * tanhf(cn);
            c_out[go] = cn;
            h_out[go] = hv;
            hh_out[go] = __float2half_rn(hv);
        }
    }
}

// ================= convert kernels =================
__global__ __launch_bounds__(256) void cvt_kernel(
    const float* __restrict__ in, __half* __restrict__ out, int n4)
{
    const int i = blockIdx.x * blockDim.x + threadIdx.x;
    if (i >= n4) return;
    const float4 v = ((const float4*)in)[i];
    ((__half2*)out)[2 * i]     = __half2(__float2half_rn(v.x), __float2half_rn(v.y));
    ((__half2*)out)[2 * i + 1] = __half2(__float2half_rn(v.z), __float2half_rn(v.w));
}

// h0 [32768,512] -> g_Ah at row*1024 + 512 + col
__global__ __launch_bounds__(256) void cvt_off_kernel(
    const float* __restrict__ in, __half* __restrict__ out)
{
    const int q = blockIdx.x * blockDim.x + threadIdx.x;
    const int row = q >> 7;
    const int col = (q & 127) << 2;
    const float4 v = ((const float4*)in)[q];
    const size_t o = (size_t)row * 1024 + 512 + col;
    *(__half2*)(out + o)     = __half2(__float2half_rn(v.x), __float2half_rn(v.y));
    *(__half2*)(out + o + 2) = __half2(__float2half_rn(v.z), __float2half_rn(v.w));
}

// transpose-convert: W [K,N] fp32 -> [N,K] fp16
__global__ void cvtT_kernel(const float* __restrict__ Wm,
                            __half* __restrict__ dst, int K, int N)
{
    __shared__ float t[32][33];
    const int kb = blockIdx.y * 32, nb = blockIdx.x * 32;
    const int tx = threadIdx.x, ty = threadIdx.y;
    for (int r = ty; r < 32; r += 8)
        t[r][tx] = Wm[(size_t)(kb + r) * N + nb + tx];
    __syncthreads();
    for (int r = ty; r < 32; r += 8)
        dst[(size_t)(nb + r) * K + kb + tx] = __float2half_rn(t[tx][r]);
}

// transpose-convert with gate-interleave permutation
__global__ void cvtT_perm_kernel(const float* __restrict__ Wm,
                                 __half* __restrict__ dst, int N, int Kout, int koff)
{
    __shared__ float t[32][33];
    const int kb = blockIdx.y * 32, nb = blockIdx.x * 32;
    const int tx = threadIdx.x, ty = threadIdx.y;
    for (int r = ty; r < 32; r += 8)
        t[r][tx] = Wm[(size_t)(kb + r) * N + nb + tx];
    __syncthreads();
    for (int r = ty; r < 32; r += 8) {
        const int n = nb + r;
        const int g = n >> 9, s = n & 511;
        const int nr = ((s >> 5) << 7) + (g << 5) + (s & 31);
        dst[(size_t)nr * Kout + koff + kb + tx] = __float2half_rn(t[tx][r]);
    }
}

__global__ void bias_prep(const float* __restrict__ bf, const float* __restrict__ bb,
                          const float* __restrict__ bi,
                          float* __restrict__ bfc, float* __restrict__ biP)
{
    const int i = blockIdx.x * blockDim.x + threadIdx.x;
    if (i < 1024) bfc[i] = bf[i];
    else if (i < 2048) bfc[i] = bb[i - 1024];
    else {
        const int n = i - 2048;
        const int g = n >> 9, s = n & 511;
        const int nr = ((s >> 5) << 7) + (g << 5) + (s & 31);
        biP[nr] = bi[n];
    }
}

// ---------------- group barrier (16 CTAs per group) ----------------
__device__ __forceinline__ void group_barrier(int grp) {
    __threadfence();
    __syncthreads();
    if (threadIdx.x == 0) {
        unsigned long long* ctr = &g_barG[grp * 16];
        unsigned long long t = atomicAdd(ctr, 1ULL) + 1ULL;
        unsigned long long target = ((t + 15ULL) >> 4) << 4;
        volatile unsigned long long* p = ctr;
        while (*p < target) { __nanosleep(32); }
        __threadfence();
    }
    __syncthreads();
}

// ---------------- persistent bidirectional LSTM recurrence (pure fp16, fp16 zx) ----------------
#define RA_STR   528
#define ROFF_BHI 33792
#define ROFF_STG 67584
#define ROFF_ZX  84992           // 8KB fp16 zx tile
#define RSMEM    93184

__global__ __launch_bounds__(256) void recurrence2(const __half* __restrict__ Ut)
{
    extern __shared__ __align__(128) char rsm[];
    const uint32_t sb = smem_u32(rsm);
    const int tid = threadIdx.x, lane = tid & 31, wid = tid >> 5;
    const int blk = blockIdx.x;
    const int tile_m = blk >> 4;
    const int tile_n = blk & 15;
    const int row0 = tile_m << 6;
    const int dir = (tile_m >= 4) ? 1 : 0;
    const int j0 = tile_n << 4;
    const int wm = wid & 3, wn = wid >> 2;

    for (int i = tid; i < 2048; i += 256) {
        const int r = i >> 5, seg = i & 31;
        const int g = r >> 4, c = r & 15;
        const size_t gr = ((size_t)(dir * 1024 + g * 256 + j0 + c)) * 256 + seg * 8;
        *(uint4*)(rsm + ROFF_BHI + r * RA_STR + seg * 16) = *(const uint4*)(Ut + gr);
    }

    if (tile_n == 0) {
        uint32_t* h0 = (uint32_t*)&g_Hh[0][row0 * 256];
        for (int i = tid; i < 8192; i += 256) h0[i] = 0u;
    }

    const uint32_t a_off = (uint32_t)((wm * 16 + (lane & 15)) * RA_STR + (lane >> 4) * 16);
    const int bsub = lane >> 3;
    const uint32_t b_off = (uint32_t)((wn * 32 + ((bsub >> 1) << 3) + (lane & 7)) * RA_STR + (bsub & 1) * 16);

    const int r_up = tid >> 2;
    const int c_up = (tid & 3) << 2;
    const int Rr = row0 + r_up;
    const int n_up = Rr & 255;
    float* stg = (float*)(rsm + ROFF_STG);
    const __half* zxs = (const __half*)(rsm + ROFF_ZX);
    float creg[4] = {0.0f, 0.0f, 0.0f, 0.0f};

    group_barrier(tile_m);

    for (int t = 0; t < 128; t++) {
        const int pb = t & 1;
        const int w = dir ? (127 - t) : t;
        const __half* hh = g_Hh[pb];

        // ---- commit group 1: H k 0..127 ----
#pragma unroll
        for (int ii = 0; ii < 4; ii++) {
            const int i = tid + ii * 256;
            const int r = i >> 4, seg = i & 15;
            CP_ASYNC16(sb + r * RA_STR + seg * 16, hh + (size_t)(row0 + r) * 256 + seg * 8);
        }
        CP_COMMIT();
        // ---- commit group 2: H k 128..255 + fp16 zx prefetch ----
#pragma unroll
        for (int ii = 0; ii < 4; ii++) {
            const int i = tid + ii * 256;
            const int r = i >> 4, seg = 16 + (i & 15);
            CP_ASYNC16(sb + r * RA_STR + seg * 16, hh + (size_t)(row0 + r) * 256 + seg * 8);
        }
        {
            // 64 rows x 4 gates x 16 halfs = 8KB = 512 x 16B; 2 reqs/thread
#pragma unroll
            for (int ii = 0; ii < 2; ii++) {
                const int q = tid + ii * 256;           // 0..511
                const int r = q >> 3;                   // 0..63
                const int rem = q & 7;
                const int g = rem >> 1;
                const int part = rem & 1;
                const int rr = row0 + r;
                const __half* src = g_ZX + ((size_t)(rr & 255) * 128 + w) * 2048
                                   + dir * 1024 + j0 + g * 256 + part * 8;
                CP_ASYNC16(sb + ROFF_ZX + (uint32_t)(r * 128 + g * 32 + part * 16), src);
            }
        }
        CP_COMMIT();

        float acc[4][4];
#pragma unroll
        for (int nf = 0; nf < 4; nf++)
#pragma unroll
            for (int r = 0; r < 4; r++) acc[nf][r] = 0.0f;

        CP_WAIT1();
        __syncthreads();
#pragma unroll
        for (int ks = 0; ks < 8; ks++) {
            const uint32_t kb = ks * 32;
            uint32_t ah[4], bh[4][2], t4[4];
            ldmx4(ah, sb + a_off + kb);
#pragma unroll
            for (int nh = 0; nh < 2; nh++) {
                ldmx4(t4, sb + ROFF_BHI + b_off + kb + nh * 16 * RA_STR);
                bh[2 * nh][0] = t4[0]; bh[2 * nh][1] = t4[1];
                bh[2 * nh + 1][0] = t4[2]; bh[2 * nh + 1][1] = t4[3];
            }
#pragma unroll
            for (int nf = 0; nf < 4; nf++)
                mma_f16(acc[nf], ah, bh[nf]);
        }
        CP_WAIT0();
        __syncthreads();
#pragma unroll
        for (int ks = 8; ks < 16; ks++) {
            const uint32_t kb = ks * 32;
            uint32_t ah[4], bh[4][2], t4[4];
            ldmx4(ah, sb + a_off + kb);
#pragma unroll
            for (int nh = 0; nh < 2; nh++) {
                ldmx4(t4, sb + ROFF_BHI + b_off + kb + nh * 16 * RA_STR);
                bh[2 * nh][0] = t4[0]; bh[2 * nh][1] = t4[1];
                bh[2 * nh + 1][0] = t4[2]; bh[2 * nh + 1][1] = t4[3];
            }
#pragma unroll
            for (int nf = 0; nf < 4; nf++)
                mma_f16(acc[nf], ah, bh[nf]);
        }

        {
            const int qr = lane >> 2, qc = (lane & 3) << 1;
#pragma unroll
            for (int nf = 0; nf < 4; nf++) {
                const int col = wn * 32 + nf * 8 + qc;
                stg[(wm * 16 + qr) * 68 + col]     = acc[nf][0];
                stg[(wm * 16 + qr) * 68 + col + 1] = acc[nf][1];
                stg[(wm * 16 + qr + 8) * 68 + col]     = acc[nf][2];
                stg[(wm * 16 + qr + 8) * 68 + col + 1] = acc[nf][3];
            }
        }
        __syncthreads();

        {
            __half* dhh = &g_Hh[pb ^ 1][(size_t)Rr * 256 + j0 + c_up];
            const size_t hsoff = ((size_t)n_up * 128 + w) * 512 + dir * 256 + j0 + c_up;
            const __half* zx = zxs + r_up * 64 + c_up;   // [g*16 + c]
            float hv[4];
#pragma unroll
            for (int l = 0; l < 4; l++) {
                const float* sr = &stg[r_up * 68 + c_up + l];
                const float zi = sr[0]  + __half2float(zx[l]);
                const float zf = sr[16] + __half2float(zx[16 + l]);
                const float zg = sr[32] + __half2float(zx[32 + l]);
                const float zo = sr[48] + __half2float(zx[48 + l]);
                const float cn = hsig(zf) * creg[l] + hsig(zi) * tanhf(zg);
                creg[l] = cn;
                hv[l] = hsig(zo) * tanhf(cn);
            }
            const __half2 p0 = __half2(__float2half_rn(hv[0]), __float2half_rn(hv[1]));
            const __half2 p1 = __half2(__float2half_rn(hv[2]), __float2half_rn(hv[3]));
            *(__half2*)(dhh)     = p0;
            *(__half2*)(dhh + 2) = p1;
            *(__half2*)(g_HSh + hsoff)     = p0;
            *(__half2*)(g_HSh + hsoff + 2) = p1;
        }

        if (t < 127) group_barrier(tile_m);
    }
}

// ---------------- LayerNorm over (W,C)=65536, optional fused fp16 convert (stride 1024) ----------------
__global__ __launch_bounds__(256) void ln_kernel(
    const float* __restrict__ pre, const float* __restrict__ xres,
    const float* __restrict__ gamma, const float* __restrict__ beta,
    float* __restrict__ out, __half* __restrict__ sh, int mode)
{
    __shared__ float red[256];
    const int tid = threadIdx.x;
    const size_t base = (size_t)blockIdx.x * 65536;

    float s = 0.0f, ss = 0.0f;
    for (int i = tid * 4; i < 65536; i += 1024) {
        float4 v = *(const float4*)(pre + base + i);
        s  += v.x + v.y + v.z + v.w;
        ss += v.x * v.x + v.y * v.y + v.z * v.z + v.w * v.w;
    }
    red[tid] = s; __syncthreads();
    for (int off = 128; off; off >>= 1) { if (tid < off) red[tid] += red[tid + off]; __syncthreads(); }
    const float mean = red[0] * (1.0f / 65536.0f);
    __syncthreads();
    red[tid] = ss; __syncthreads();
    for (int off = 128; off; off >>= 1) { if (tid < off) red[tid] += red[tid + off]; __syncthreads(); }
    const float var = red[0] * (1.0f / 65536.0f) - mean * mean;
    const float rstd = rsqrtf(var + 1e-3f);

    for (int i = tid * 4; i < 65536; i += 1024) {
        float4 v = *(const float4*)(pre + base + i);
        float4 g = *(const float4*)(gamma + i);
        float4 bb = *(const float4*)(beta + i);
        float4 r;
        r.x = (v.x - mean) * rstd * g.x + bb.x;
        r.y = (v.y - mean) * rstd * g.y + bb.y;
        r.z = (v.z - mean) * rstd * g.z + bb.z;
        r.w = (v.w - mean) * rstd * g.w + bb.w;
        if (mode == 0) {
            float4 xr = *(const float4*)(xres + base + i);
            r.x += xr.x; r.y += xr.y; r.z += xr.z; r.w += xr.w;
        } else {
            float4 o = *(const float4*)(out + base + i);
            r.x += o.x; r.y += o.y; r.z += o.z; r.w += o.w;
        }
        *(float4*)(out + base + i) = r;
        if (sh) {
            const size_t f = base + i;
            const size_t so = (f >> 9) * 1024 + (f & 511);
            *(__half2*)(sh + so)     = __half2(__float2half_rn(r.x), __float2half_rn(r.y));
            *(__half2*)(sh + so + 2) = __half2(__float2half_rn(r.z), __float2half_rn(r.w));
        }
    }
}

// ---------------- launch ----------------
extern "C" void kernel_launch(void* const* d_in, const int* in_sizes, int n_in,
                              void* d_out, int out_size)
{
    const float* x    = (const float*)d_in[0];
    const float* h0   = (const float*)d_in[1];
    const float* c0   = (const float*)d_in[2];
    const float* Wf   = (const float*)d_in[3];
    const float* Uf   = (const float*)d_in[4];
    const float* bf   = (const float*)d_in[5];
    const float* Wb   = (const float*)d_in[6];
    const float* Ub   = (const float*)d_in[7];
    const float* bb   = (const float*)d_in[8];
    const float* Wfc1 = (const float*)d_in[9];
    const float* bfc1 = (const float*)d_in[10];
    const float* g1   = (const float*)d_in[11];
    const float* b1   = (const float*)d_in[12];
    const float* Wi   = (const float*)d_in[13];
    const float* Ui   = (const float*)d_in[14];
    const float* bi   = (const float*)d_in[15];
    const float* Wfc2 = (const float*)d_in[16];
    const float* bfc2 = (const float*)d_in[17];
    const float* g2   = (const float*)d_in[18];
    const float* b2   = (const float*)d_in[19];

    float* out = (float*)d_out;
    float* h_out = out + OUT0;
    float* c_out = out + 2 * OUT0;
    const int full_out = (out_size >= (int)(3 * OUT0)) || out_size <= 0;

    float *fc, *bfc, *biP, *hcfb;
    __half *zx, *ah, *bt, *ut, *hsh;
    cudaGetSymbolAddress((void**)&zx,  g_ZX);
    cudaGetSymbolAddress((void**)&fc,  g_FC);
    cudaGetSymbolAddress((void**)&bfc, g_bfc);
    cudaGetSymbolAddress((void**)&biP, g_biP);
    cudaGetSymbolAddress((void**)&ah,  g_Ah);
    cudaGetSymbolAddress((void**)&bt,  g_Bt);
    cudaGetSymbolAddress((void**)&ut,  g_Ut);
    cudaGetSymbolAddress((void**)&hsh, g_HSh);
    cudaGetSymbolAddress((void**)&hcfb, g_HCfb);

    cudaFuncSetAttribute(tcgemm, cudaFuncAttributeMaxDynamicSharedMemorySize, GEMM_SMEM);
    cudaFuncSetAttribute(tcgemm_h, cudaFuncAttributeMaxDynamicSharedMemorySize, GEMM_SMEM);
    cudaFuncSetAttribute(tcgemm_gates, cudaFuncAttributeMaxDynamicSharedMemorySize, GATES_SMEM);
    cudaFuncSetAttribute(recurrence2, cudaFuncAttributeMaxDynamicSharedMemorySize, RSMEM);

    const int n4A = MROWS * 512 / 4;

    // ---- combined intra input projection: ZX(fp16) = x @ [Wf|Wb] + [bf|bb] ----
    cvt_kernel<<<n4A / 256, 256>>>(x, ah, n4A);
    bias_prep<<<16, 256>>>(bf, bb, bi, bfc, biP);
    cvtT_kernel<<<dim3(32, 16), dim3(32, 8)>>>(Wf, bt, 512, 1024);
    cvtT_kernel<<<dim3(32, 16), dim3(32, 8)>>>(Wb, bt + (size_t)1024 * 512, 512, 1024);
    tcgemm_h<<<dim3(16, 256), 256, GEMM_SMEM>>>(ah, bt, zx, bfc, MROWS, 2048, 512);

    // ---- recurrent weights + recurrence ----
    cvtT_kernel<<<dim3(32, 8), dim3(32, 8)>>>(Uf, ut, 256, 1024);
    cvtT_kernel<<<dim3(32, 8), dim3(32, 8)>>>(Ub, ut + 1024 * 256, 256, 1024);
    recurrence2<<<128, 256, RSMEM>>>(ut);

    // ---- fc1 (A = HS) ----
    cvtT_kernel<<<dim3(16, 16), dim3(32, 8)>>>(Wfc1, bt, 512, 512);
    tcgemm<<<dim3(4, 256), 256, GEMM_SMEM>>>(hsh, bt, fc, bfc1, MROWS, 512, 512);

    // ---- LN1 + residual -> out, fused convert (concat A cols 0..511) ----
    ln_kernel<<<256, 256>>>(fc, x, g1, b1, out, ah, 0);

    // ---- inter: single K=1024 GEMM with fused gates ----
    cvt_off_kernel<<<16384, 256>>>(h0, ah);
    cvtT_perm_kernel<<<dim3(64, 16), dim3(32, 8)>>>(Wi, bt, 2048, 1024, 0);
    cvtT_perm_kernel<<<dim3(64, 16), dim3(32, 8)>>>(Ui, bt, 2048, 1024, 512);
    float* hptr = full_out ? h_out : hcfb;
    float* cptr = full_out ? c_out : (hcfb + (size_t)MROWS * 512);
    tcgemm_gates<<<dim3(16, 256), 256, GATES_SMEM>>>(ah, bt, biP, c0,
                                                     hptr, cptr, hsh, 1024);

    // ---- fc2 (A = h in g_HSh) ----
    cvtT_kernel<<<dim3(16, 16), dim3(32, 8)>>>(Wfc2, bt, 512, 512);
    tcgemm<<<dim3(4, 256), 256, GEMM_SMEM>>>(hsh, bt, fc, bfc2, MROWS, 512, 512);

    // ---- LN2 accumulate into out ----
    ln_kernel<<<256, 256>>>(fc, nullptr, g2, b2, out, nullptr, 1);
}

// round 11
// speedup vs baseline: 1.1284x; 1.0165x over previous
#include <cuda_runtime.h>
#include <cuda_fp16.h>
#include <cstdint>
#include <math.h>

// Problem constants
#define NSAMP 256            // B*L
#define W_    128
#define C_    512
#define HD_   256
#define MROWS 32768          // B*W
#define OUT0  ((size_t)16777216)   // B*L*W*C

// B-region offsets inside g_Bt (in halfs)
#define OFF_INTER 1048576          // 2048 rows x 1024 K
#define OFF_FC1   3145728          // 512 x 512
#define OFF_FC2   3407872          // 512 x 512

// ---------------- scratch (static device globals; no allocations) ----------------
__device__ __half g_ZX [(size_t)MROWS * 2048];  // combined intra projections, fp16
__device__ float g_FC [(size_t)MROWS * 512];
__device__ float g_bfc[2048];
__device__ float g_biP[2048];
__device__ unsigned long long g_barG[8 * 16];   // per-group monotonic tickets

// fp16 operand buffers
__device__ __half g_Ah [(size_t)MROWS * 1024];
__device__ __half g_Bt [(size_t)3670016];       // proj | inter | fc1 | fc2 regions
// recurrence state / weights / outputs (fp16)
__device__ __half g_Hh[2][512 * 256];
__device__ __half g_Ut[(size_t)2048 * 256];
__device__ __half g_HSh[(size_t)MROWS * 512];
// fallback h/c buffers when out buffer is small
__device__ float g_HCfb[2][(size_t)MROWS * 512];

__device__ __forceinline__ float hsig(float x) {
    return fminf(fmaxf(fmaf(0.2f, x, 0.5f), 0.0f), 1.0f);
}

// ================= low-level helpers (sm_80-baseline ISA only) =================
__device__ __forceinline__ uint32_t smem_u32(const void* p) {
    uint32_t a;
    asm("{ .reg .u64 t; cvta.to.shared.u64 t, %1; cvt.u32.u64 %0, t; }" : "=r"(a) : "l"(p));
    return a;
}
#define CP_ASYNC16(dst, src) \
    asm volatile("cp.async.cg.shared.global [%0], [%1], 16;" :: "r"(dst), "l"(src) : "memory")
#define CP_COMMIT() asm volatile("cp.async.commit_group;" ::: "memory")
#define CP_WAIT2()  asm volatile("cp.async.wait_group 2;" ::: "memory")
#define CP_WAIT1()  asm volatile("cp.async.wait_group 1;" ::: "memory")
#define CP_WAIT0()  asm volatile("cp.async.wait_group 0;" ::: "memory")

__device__ __forceinline__ void ldmx4(uint32_t* r, uint32_t addr) {
    asm volatile("ldmatrix.sync.aligned.m8n8.x4.shared.b16 {%0,%1,%2,%3}, [%4];"
        : "=r"(r[0]), "=r"(r[1]), "=r"(r[2]), "=r"(r[3]) : "r"(addr));
}
__device__ __forceinline__ void mma_f16(float* d, const uint32_t* a, const uint32_t* b) {
    asm volatile("mma.sync.aligned.m16n8k16.row.col.f32.f16.f16.f32 "
        "{%0,%1,%2,%3}, {%4,%5,%6,%7}, {%8,%9}, {%0,%1,%2,%3};"
        : "+f"(d[0]), "+f"(d[1]), "+f"(d[2]), "+f"(d[3])
        : "r"(a[0]), "r"(a[1]), "r"(a[2]), "r"(a[3]), "r"(b[0]), "r"(b[1]));
}

// ================= 128x128 fp16 GEMM (2 CTAs/SM, 3-stage pipeline) =================
#define TILE_B   10240           // 128*80
#define STG_B    20480
#define GEMM_SMEM  61440         // 3 stages
#define GATES_SMEM 67584         // epilogue stg 128*132*4

__device__ __forceinline__ void load_chunk(uint32_t stage_base,
    const __half* __restrict__ Ah, const __half* __restrict__ Bh,
    int m0, int n0, int kk, int K, int tid)
{
#pragma unroll
    for (int i = 0; i < 2; i++) {
        const int c = tid + i * 256;
        const int row = c >> 2;
        const int seg = c & 3;
        const uint32_t doff = (uint32_t)(row * 80 + seg * 16);
        const size_t akoff = (size_t)kk + seg * 8;
        CP_ASYNC16(stage_base + 0 * TILE_B + doff, Ah + (size_t)(m0 + row) * K + akoff);
        CP_ASYNC16(stage_base + 1 * TILE_B + doff, Bh + (size_t)(n0 + row) * K + akoff);
    }
}

#define GEMM_MAINLOOP(Ah, Bh, m0, n0, K, acc)                                     \
    {                                                                             \
        const int NC = (K) >> 5;                                                  \
        load_chunk(sb + 0 * STG_B, Ah, Bh, m0, n0, 0, K, tid);                    \
        CP_COMMIT();                                                              \
        load_chunk(sb + 1 * STG_B, Ah, Bh, m0, n0, 32, K, tid);                   \
        CP_COMMIT();                                                              \
        load_chunk(sb + 2 * STG_B, Ah, Bh, m0, n0, 64, K, tid);                   \
        CP_COMMIT();                                                              \
        int stage = 0;                                                            \
        for (int c = 0; c < NC; c++) {                                            \
            CP_WAIT2();                                                           \
            __syncthreads();                                                      \
            const uint32_t st = sb + stage * STG_B;                               \
            _Pragma("unroll")                                                     \
            for (int ks = 0; ks < 2; ks++) {                                      \
                const uint32_t kb = st + ks * 32;                                 \
                uint32_t af[4][4], bhf[4][2], t4[4];                              \
                _Pragma("unroll")                                                 \
                for (int nh = 0; nh < 2; nh++) {                                  \
                    ldmx4(t4, kb + 1 * TILE_B + b_off + nh * 1280);               \
                    bhf[2*nh][0] = t4[0]; bhf[2*nh][1] = t4[1];                   \
                    bhf[2*nh+1][0] = t4[2]; bhf[2*nh+1][1] = t4[3];               \
                }                                                                 \
                _Pragma("unroll")                                                 \
                for (int mf = 0; mf < 4; mf++) ldmx4(af[mf], kb + a_off + mf * 1280); \
                _Pragma("unroll")                                                 \
                for (int mf = 0; mf < 4; mf++)                                    \
                    _Pragma("unroll")                                             \
                    for (int nf = 0; nf < 4; nf++)                                \
                        mma_f16(acc[mf][nf], af[mf], bhf[nf]);                    \
            }                                                                     \
            __syncthreads();                                                      \
            if (c + 3 < NC)                                                       \
                load_chunk(st, Ah, Bh, m0, n0, (c + 3) << 5, K, tid);             \
            CP_COMMIT();                                                          \
            stage = (stage == 2) ? 0 : stage + 1;                                 \
        }                                                                         \
    }

// fp32-output GEMM (fc1/fc2)
__global__ __launch_bounds__(256, 2) void tcgemm(
    const __half* __restrict__ Ah, const __half* __restrict__ Bh,
    float* __restrict__ Cmat, const float* __restrict__ bias,
    int M, int N, int K)
{
    extern __shared__ __align__(128) char smem_raw[];
    const uint32_t sb = smem_u32(smem_raw);

    const int tid = threadIdx.x;
    const int lane = tid & 31;
    const int wid = tid >> 5;
    const int wm = wid >> 2;
    const int wn = wid & 3;
    const int m0 = blockIdx.y << 7;
    const int n0 = blockIdx.x << 7;

    const uint32_t a_off = (uint32_t)((wm * 64 + (lane & 15)) * 80 + (lane >> 4) * 16);
    const int bsub = lane >> 3;
    const uint32_t b_off = (uint32_t)((wn * 32 + ((bsub >> 1) << 3) + (lane & 7)) * 80 + (bsub & 1) * 16);

    float acc[4][4][4];
#pragma unroll
    for (int mf = 0; mf < 4; mf++)
#pragma unroll
        for (int nf = 0; nf < 4; nf++)
#pragma unroll
            for (int r = 0; r < 4; r++) acc[mf][nf][r] = 0.0f;

    GEMM_MAINLOOP(Ah, Bh, m0, n0, K, acc);

    const int qr = lane >> 2;
    const int qc = (lane & 3) << 1;
#pragma unroll
    for (int mf = 0; mf < 4; mf++) {
        const int row = m0 + wm * 64 + mf * 16 + qr;
#pragma unroll
        for (int nf = 0; nf < 4; nf++) {
            const int col = n0 + wn * 32 + nf * 8 + qc;
            const float2 bv = *(const float2*)(bias + col);
            float2 v0 = make_float2(acc[mf][nf][0] + bv.x, acc[mf][nf][1] + bv.y);
            float2 v1 = make_float2(acc[mf][nf][2] + bv.x, acc[mf][nf][3] + bv.y);
            *(float2*)(Cmat + (size_t)row * N + col) = v0;
            *(float2*)(Cmat + (size_t)(row + 8) * N + col) = v1;
        }
    }
}

// fp16-output GEMM (intra projection -> ZX)
__global__ __launch_bounds__(256, 2) void tcgemm_h(
    const __half* __restrict__ Ah, const __half* __restrict__ Bh,
    __half* __restrict__ Cmat, const float* __restrict__ bias,
    int M, int N, int K)
{
    extern __shared__ __align__(128) char smem_raw[];
    const uint32_t sb = smem_u32(smem_raw);

    const int tid = threadIdx.x;
    const int lane = tid & 31;
    const int wid = tid >> 5;
    const int wm = wid >> 2;
    const int wn = wid & 3;
    const int m0 = blockIdx.y << 7;
    const int n0 = blockIdx.x << 7;

    const uint32_t a_off = (uint32_t)((wm * 64 + (lane & 15)) * 80 + (lane >> 4) * 16);
    const int bsub = lane >> 3;
    const uint32_t b_off = (uint32_t)((wn * 32 + ((bsub >> 1) << 3) + (lane & 7)) * 80 + (bsub & 1) * 16);

    float acc[4][4][4];
#pragma unroll
    for (int mf = 0; mf < 4; mf++)
#pragma unroll
        for (int nf = 0; nf < 4; nf++)
#pragma unroll
            for (int r = 0; r < 4; r++) acc[mf][nf][r] = 0.0f;

    GEMM_MAINLOOP(Ah, Bh, m0, n0, K, acc);

    const int qr = lane >> 2;
    const int qc = (lane & 3) << 1;
#pragma unroll
    for (int mf = 0; mf < 4; mf++) {
        const int row = m0 + wm * 64 + mf * 16 + qr;
#pragma unroll
        for (int nf = 0; nf < 4; nf++) {
            const int col = n0 + wn * 32 + nf * 8 + qc;
            const float2 bv = *(const float2*)(bias + col);
            *(__half2*)(Cmat + (size_t)row * N + col) =
                __half2(__float2half_rn(acc[mf][nf][0] + bv.x),
                        __float2half_rn(acc[mf][nf][1] + bv.y));
            *(__half2*)(Cmat + (size_t)(row + 8) * N + col) =
                __half2(__float2half_rn(acc[mf][nf][2] + bv.x),
                        __float2half_rn(acc[mf][nf][3] + bv.y));
        }
    }
}

// ---- inter GEMM with fused LSTM gate epilogue (gate-interleaved B layout) ----
__global__ __launch_bounds__(256, 2) void tcgemm_gates(
    const __half* __restrict__ Ah, const __half* __restrict__ Bh,
    const float* __restrict__ biasP, const float* __restrict__ c0,
    float* __restrict__ h_out, float* __restrict__ c_out,
    __half* __restrict__ hh_out, int K)
{
    extern __shared__ __align__(128) char smem_raw[];
    const uint32_t sb = smem_u32(smem_raw);

    const int tid = threadIdx.x;
    const int lane = tid & 31;
    const int wid = tid >> 5;
    const int wm = wid >> 2;
    const int wn = wid & 3;
    const int m0 = blockIdx.y << 7;
    const int n0 = blockIdx.x << 7;
    const int hid0 = blockIdx.x << 5;

    const uint32_t a_off = (uint32_t)((wm * 64 + (lane & 15)) * 80 + (lane >> 4) * 16);
    const int bsub = lane >> 3;
    const uint32_t b_off = (uint32_t)((wn * 32 + ((bsub >> 1) << 3) + (lane & 7)) * 80 + (bsub & 1) * 16);

    float acc[4][4][4];
#pragma unroll
    for (int mf = 0; mf < 4; mf++)
#pragma unroll
        for (int nf = 0; nf < 4; nf++)
#pragma unroll
            for (int r = 0; r < 4; r++) acc[mf][nf][r] = 0.0f;

    GEMM_MAINLOOP(Ah, Bh, m0, n0, K, acc);

    __syncthreads();
    float* stg = (float*)smem_raw;    // 128 x 132
    const int qr = lane >> 2;
    const int qc = (lane & 3) << 1;
#pragma unroll
    for (int mf = 0; mf < 4; mf++) {
        const int rl = wm * 64 + mf * 16 + qr;
#pragma unroll
        for (int nf = 0; nf < 4; nf++) {
            const int col = wn * 32 + nf * 8 + qc;
            const float2 bv = *(const float2*)(biasP + n0 + col);
            stg[rl * 132 + col]           = acc[mf][nf][0] + bv.x;
            stg[rl * 132 + col + 1]       = acc[mf][nf][1] + bv.y;
            stg[(rl + 8) * 132 + col]     = acc[mf][nf][2] + bv.x;
            stg[(rl + 8) * 132 + col + 1] = acc[mf][nf][3] + bv.y;
        }
    }
    __syncthreads();

    {
        const int c = lane;
#pragma unroll
        for (int i = 0; i < 16; i++) {
            const int r = wid * 16 + i;
            const float zi = stg[r * 132 + c];
            const float zf = stg[r * 132 + 32 + c];
            const float zg = stg[r * 132 + 64 + c];
            const float zo = stg[r * 132 + 96 + c];
            const size_t go = (size_t)(m0 + r) * 512 + hid0 + c;
            const float cn = hsig(zf) * c0[go] + hsig(zi) * tanhf(zg);
            const float hv = hsig(zo) * tanhf(cn);
            c_out[go] = cn;
            h_out[go] = hv;
            hh_out[go] = __float2half_rn(hv);
        }
    }
}

// ================= convert kernels =================
__global__ __launch_bounds__(256) void cvt_kernel(
    const float* __restrict__ in, __half* __restrict__ out, int n4)
{
    const int i = blockIdx.x * blockDim.x + threadIdx.x;
    if (i >= n4) return;
    const float4 v = ((const float4*)in)[i];
    ((__half2*)out)[2 * i]     = __half2(__float2half_rn(v.x), __float2half_rn(v.y));
    ((__half2*)out)[2 * i + 1] = __half2(__float2half_rn(v.z), __float2half_rn(v.w));
}

// h0 [32768,512] -> g_Ah at row*1024 + 512 + col
__global__ __launch_bounds__(256) void cvt_off_kernel(
    const float* __restrict__ in, __half* __restrict__ out)
{
    const int q = blockIdx.x * blockDim.x + threadIdx.x;
    const int row = q >> 7;
    const int col = (q & 127) << 2;
    const float4 v = ((const float4*)in)[q];
    const size_t o = (size_t)row * 1024 + 512 + col;
    *(__half2*)(out + o)     = __half2(__float2half_rn(v.x), __float2half_rn(v.y));
    *(__half2*)(out + o + 2) = __half2(__float2half_rn(v.z), __float2half_rn(v.w));
}

// ---- unified weight/bias prep: blockIdx.z selects job ----
__device__ __forceinline__ void cvtT_tile(const float* __restrict__ Wm,
                                          __half* __restrict__ dst,
                                          int K, int N, int bx, int by,
                                          int tx, int ty)
{
    __shared__ float t[32][33];
    const int kb = by * 32, nb = bx * 32;
    for (int r = ty; r < 32; r += 8)
        t[r][tx] = Wm[(size_t)(kb + r) * N + nb + tx];
    __syncthreads();
    for (int r = ty; r < 32; r += 8)
        dst[(size_t)(nb + r) * K + kb + tx] = __float2half_rn(t[tx][r]);
}

__device__ __forceinline__ void cvtT_perm_tile(const float* __restrict__ Wm,
                                               __half* __restrict__ dst,
                                               int N, int Kout, int koff,
                                               int bx, int by, int tx, int ty)
{
    __shared__ float t[32][33];
    const int kb = by * 32, nb = bx * 32;
    for (int r = ty; r < 32; r += 8)
        t[r][tx] = Wm[(size_t)(kb + r) * N + nb + tx];
    __syncthreads();
    for (int r = ty; r < 32; r += 8) {
        const int n = nb + r;
        const int g = n >> 9, s = n & 511;
        const int nr = ((s >> 5) << 7) + (g << 5) + (s & 31);
        dst[(size_t)nr * Kout + koff + kb + tx] = __float2half_rn(t[tx][r]);
    }
}

__global__ void prep_all(
    const float* __restrict__ Wf, const float* __restrict__ Wb,
    const float* __restrict__ Uf, const float* __restrict__ Ub,
    const float* __restrict__ Wfc1, const float* __restrict__ Wfc2,
    const float* __restrict__ Wi, const float* __restrict__ Ui,
    const float* __restrict__ bf, const float* __restrict__ bb,
    const float* __restrict__ bi,
    __half* __restrict__ bt, __half* __restrict__ ut,
    float* __restrict__ bfc, float* __restrict__ biP)
{
    const int bx = blockIdx.x, by = blockIdx.y, job = blockIdx.z;
    const int tx = threadIdx.x, ty = threadIdx.y;
    switch (job) {
        case 0: if (bx < 32 && by < 16) cvtT_tile(Wf, bt, 512, 1024, bx, by, tx, ty); break;
        case 1: if (bx < 32 && by < 16) cvtT_tile(Wb, bt + (size_t)1024 * 512, 512, 1024, bx, by, tx, ty); break;
        case 2: if (bx < 32 && by < 8)  cvtT_tile(Uf, ut, 256, 1024, bx, by, tx, ty); break;
        case 3: if (bx < 32 && by < 8)  cvtT_tile(Ub, ut + 1024 * 256, 256, 1024, bx, by, tx, ty); break;
        case 4: if (bx < 16 && by < 16) cvtT_tile(Wfc1, bt + OFF_FC1, 512, 512, bx, by, tx, ty); break;
        case 5: if (bx < 16 && by < 16) cvtT_tile(Wfc2, bt + OFF_FC2, 512, 512, bx, by, tx, ty); break;
        case 6: if (bx < 64 && by < 16) cvtT_perm_tile(Wi, bt + OFF_INTER, 2048, 1024, 0, bx, by, tx, ty); break;
        case 7: if (bx < 64 && by < 16) cvtT_perm_tile(Ui, bt + OFF_INTER, 2048, 1024, 512, bx, by, tx, ty); break;
        case 8: {
            if (by == 0 && bx < 16) {
                const int i = bx * 256 + ty * 32 + tx;
                if (i < 1024) bfc[i] = bf[i];
                else if (i < 2048) bfc[i] = bb[i - 1024];
                else {
                    const int n = i - 2048;
                    const int g = n >> 9, s = n & 511;
                    const int nr = ((s >> 5) << 7) + (g << 5) + (s & 31);
                    biP[nr] = bi[n];
                }
            }
            break;
        }
    }
}

// ---------------- group barrier (16 CTAs per group) ----------------
__device__ __forceinline__ void group_barrier(int grp) {
    __threadfence();
    __syncthreads();
    if (threadIdx.x == 0) {
        unsigned long long* ctr = &g_barG[grp * 16];
        unsigned long long t = atomicAdd(ctr, 1ULL) + 1ULL;
        unsigned long long target = ((t + 15ULL) >> 4) << 4;
        volatile unsigned long long* p = ctr;
        while (*p < target) { __nanosleep(32); }
        __threadfence();
    }
    __syncthreads();
}

// ---------------- persistent bidirectional LSTM recurrence (fp16, zx double-buffered) ----------------
#define RA_STR   528
#define ROFF_BHI 33792
#define ROFF_STG 67584
#define ROFF_ZX  84992           // 2 x 8KB fp16 zx buffers
#define RSMEM    101376

__global__ __launch_bounds__(256) void recurrence2(const __half* __restrict__ Ut)
{
    extern __shared__ __align__(128) char rsm[];
    const uint32_t sb = smem_u32(rsm);
    const int tid = threadIdx.x, lane = tid & 31, wid = tid >> 5;
    const int blk = blockIdx.x;
    const int tile_m = blk >> 4;
    const int tile_n = blk & 15;
    const int row0 = tile_m << 6;
    const int dir = (tile_m >= 4) ? 1 : 0;
    const int j0 = tile_n << 4;
    const int wm = wid & 3, wn = wid >> 2;

    for (int i = tid; i < 2048; i += 256) {
        const int r = i >> 5, seg = i & 31;
        const int g = r >> 4, c = r & 15;
        const size_t gr = ((size_t)(dir * 1024 + g * 256 + j0 + c)) * 256 + seg * 8;
        *(uint4*)(rsm + ROFF_BHI + r * RA_STR + seg * 16) = *(const uint4*)(Ut + gr);
    }

    if (tile_n == 0) {
        uint32_t* h0 = (uint32_t*)&g_Hh[0][row0 * 256];
        for (int i = tid; i < 8192; i += 256) h0[i] = 0u;
    }

    const uint32_t a_off = (uint32_t)((wm * 16 + (lane & 15)) * RA_STR + (lane >> 4) * 16);
    const int bsub = lane >> 3;
    const uint32_t b_off = (uint32_t)((wn * 32 + ((bsub >> 1) << 3) + (lane & 7)) * RA_STR + (bsub & 1) * 16);

    const int r_up = tid >> 2;
    const int c_up = (tid & 3) << 2;
    const int Rr = row0 + r_up;
    const int n_up = Rr & 255;
    float* stg = (float*)(rsm + ROFF_STG);
    float creg[4] = {0.0f, 0.0f, 0.0f, 0.0f};

    // ---- prefetch zx(0) into buffer 0 (independent of barrier/H) ----
    {
        const int w0 = dir ? 127 : 0;
#pragma unroll
        for (int ii = 0; ii < 2; ii++) {
            const int q = tid + ii * 256;
            const int r = q >> 3;
            const int rem = q & 7;
            const int g = rem >> 1;
            const int part = rem & 1;
            const int rr = row0 + r;
            const __half* src = g_ZX + ((size_t)(rr & 255) * 128 + w0) * 2048
                               + dir * 1024 + j0 + g * 256 + part * 8;
            CP_ASYNC16(sb + ROFF_ZX + (uint32_t)(r * 128 + g * 32 + part * 16), src);
        }
    }
    CP_COMMIT();

    group_barrier(tile_m);

    for (int t = 0; t < 128; t++) {
        const int pb = t & 1;
        const int w = dir ? (127 - t) : t;
        const __half* hh = g_Hh[pb];
        const __half* zxs = (const __half*)(rsm + ROFF_ZX + (t & 1) * 8192);

        // ---- commit group: H k 0..127 ----
#pragma unroll
        for (int ii = 0; ii < 4; ii++) {
            const int i = tid + ii * 256;
            const int r = i >> 4, seg = i & 15;
            CP_ASYNC16(sb + r * RA_STR + seg * 16, hh + (size_t)(row0 + r) * 256 + seg * 8);
        }
        CP_COMMIT();
        // ---- commit group: H k 128..255 ----
#pragma unroll
        for (int ii = 0; ii < 4; ii++) {
            const int i = tid + ii * 256;
            const int r = i >> 4, seg = 16 + (i & 15);
            CP_ASYNC16(sb + r * RA_STR + seg * 16, hh + (size_t)(row0 + r) * 256 + seg * 8);
        }
        CP_COMMIT();

        float acc[4][4];
#pragma unroll
        for (int nf = 0; nf < 4; nf++)
#pragma unroll
            for (int r = 0; r < 4; r++) acc[nf][r] = 0.0f;

        // wait: zx(t) + H first half done; H second half may be in flight
        CP_WAIT1();
        __syncthreads();
#pragma unroll
        for (int ks = 0; ks < 8; ks++) {
            const uint32_t kb = ks * 32;
            uint32_t ah[4], bh[4][2], t4[4];
            ldmx4(ah, sb + a_off + kb);
#pragma unroll
            for (int nh = 0; nh < 2; nh++) {
                ldmx4(t4, sb + ROFF_BHI + b_off + kb + nh * 16 * RA_STR);
                bh[2 * nh][0] = t4[0]; bh[2 * nh][1] = t4[1];
                bh[2 * nh + 1][0] = t4[2]; bh[2 * nh + 1][1] = t4[3];
            }
#pragma unroll
            for (int nf = 0; nf < 4; nf++)
                mma_f16(acc[nf], ah, bh[nf]);
        }
        CP_WAIT0();
        __syncthreads();
#pragma unroll
        for (int ks = 8; ks < 16; ks++) {
            const uint32_t kb = ks * 32;
            uint32_t ah[4], bh[4][2], t4[4];
            ldmx4(ah, sb + a_off + kb);
#pragma unroll
            for (int nh = 0; nh < 2; nh++) {
                ldmx4(t4, sb + ROFF_BHI + b_off + kb + nh * 16 * RA_STR);
                bh[2 * nh][0] = t4[0]; bh[2 * nh][1] = t4[1];
                bh[2 * nh + 1][0] = t4[2]; bh[2 * nh + 1][1] = t4[3];
            }
#pragma unroll
            for (int nf = 0; nf < 4; nf++)
                mma_f16(acc[nf], ah, bh[nf]);
        }

        {
            const int qr = lane >> 2, qc = (lane & 3) << 1;
#pragma unroll
            for (int nf = 0; nf < 4; nf++) {
                const int col = wn * 32 + nf * 8 + qc;
                stg[(wm * 16 + qr) * 68 + col]     = acc[nf][0];
                stg[(wm * 16 + qr) * 68 + col + 1] = acc[nf][1];
                stg[(wm * 16 + qr + 8) * 68 + col]     = acc[nf][2];
                stg[(wm * 16 + qr + 8) * 68 + col + 1] = acc[nf][3];
            }
        }
        __syncthreads();

        {
            __half* dhh = &g_Hh[pb ^ 1][(size_t)Rr * 256 + j0 + c_up];
            const size_t hsoff = ((size_t)n_up * 128 + w) * 512 + dir * 256 + j0 + c_up;
            const __half* zx = zxs + r_up * 64 + c_up;
            float hv[4];
#pragma unroll
            for (int l = 0; l < 4; l++) {
                const float* sr = &stg[r_up * 68 + c_up + l];
                const float zi = sr[0]  + __half2float(zx[l]);
                const float zf = sr[16] + __half2float(zx[16 + l]);
                const float zg = sr[32] + __half2float(zx[32 + l]);
                const float zo = sr[48] + __half2float(zx[48 + l]);
                const float cn = hsig(zf) * creg[l] + hsig(zi) * tanhf(zg);
                creg[l] = cn;
                hv[l] = hsig(zo) * tanhf(cn);
            }
            const __half2 p0 = __half2(__float2half_rn(hv[0]), __float2half_rn(hv[1]));
            const __half2 p1 = __half2(__float2half_rn(hv[2]), __float2half_rn(hv[3]));
            *(__half2*)(dhh)     = p0;
            *(__half2*)(dhh + 2) = p1;
            *(__half2*)(g_HSh + hsoff)     = p0;
            *(__half2*)(g_HSh + hsoff + 2) = p1;
        }

        if (t < 127) {
            // ---- prefetch zx(t+1) into the other buffer BEFORE the barrier ----
            const int wn1 = dir ? (127 - (t + 1)) : (t + 1);
            const uint32_t zdst = sb + ROFF_ZX + (uint32_t)(((t + 1) & 1) * 8192);
#pragma unroll
            for (int ii = 0; ii < 2; ii++) {
                const int q = tid + ii * 256;
                const int r = q >> 3;
                const int rem = q & 7;
                const int g = rem >> 1;
                const int part = rem & 1;
                const int rr = row0 + r;
                const __half* src = g_ZX + ((size_t)(rr & 255) * 128 + wn1) * 2048
                                   + dir * 1024 + j0 + g * 256 + part * 8;
                CP_ASYNC16(zdst + (uint32_t)(r * 128 + g * 32 + part * 16), src);
            }
            CP_COMMIT();
            group_barrier(tile_m);
        }
    }
}

// ---------------- LayerNorm over (W,C)=65536, optional fused fp16 convert (stride 1024) ----------------
__global__ __launch_bounds__(256) void ln_kernel(
    const float* __restrict__ pre, const float* __restrict__ xres,
    const float* __restrict__ gamma, const float* __restrict__ beta,
    float* __restrict__ out, __half* __restrict__ sh, int mode)
{
    __shared__ float red[256];
    const int tid = threadIdx.x;
    const size_t base = (size_t)blockIdx.x * 65536;

    float s = 0.0f, ss = 0.0f;
    for (int i = tid * 4; i < 65536; i += 1024) {
        float4 v = *(const float4*)(pre + base + i);
        s  += v.x + v.y + v.z + v.w;
        ss += v.x * v.x + v.y * v.y + v.z * v.z + v.w * v.w;
    }
    red[tid] = s; __syncthreads();
    for (int off = 128; off; off >>= 1) { if (tid < off) red[tid] += red[tid + off]; __syncthreads(); }
    const float mean = red[0] * (1.0f / 65536.0f);
    __syncthreads();
    red[tid] = ss; __syncthreads();
    for (int off = 128; off; off >>= 1) { if (tid < off) red[tid] += red[tid + off]; __syncthreads(); }
    const float var = red[0] * (1.0f / 65536.0f) - mean * mean;
    const float rstd = rsqrtf(var + 1e-3f);

    for (int i = tid * 4; i < 65536; i += 1024) {
        float4 v = *(const float4*)(pre + base + i);
        float4 g = *(const float4*)(gamma + i);
        float4 bb = *(const float4*)(beta + i);
        float4 r;
        r.x = (v.x - mean) * rstd * g.x + bb.x;
        r.y = (v.y - mean) * rstd * g.y + bb.y;
        r.z = (v.z - mean) * rstd * g.z + bb.z;
        r.w = (v.w - mean) * rstd * g.w + bb.w;
        if (mode == 0) {
            float4 xr = *(const float4*)(xres + base + i);
            r.x += xr.x; r.y += xr.y; r.z += xr.z; r.w += xr.w;
        } else {
            float4 o = *(const float4*)(out + base + i);
            r.x += o.x; r.y += o.y; r.z += o.z; r.w += o.w;
        }
        *(float4*)(out + base + i) = r;
        if (sh) {
            const size_t f = base + i;
            const size_t so = (f >> 9) * 1024 + (f & 511);
            *(__half2*)(sh + so)     = __half2(__float2half_rn(r.x), __float2half_rn(r.y));
            *(__half2*)(sh + so + 2) = __half2(__float2half_rn(r.z), __float2half_rn(r.w));
        }
    }
}

// ---------------- launch ----------------
extern "C" void kernel_launch(void* const* d_in, const int* in_sizes, int n_in,
                              void* d_out, int out_size)
{
    const float* x    = (const float*)d_in[0];
    const float* h0   = (const float*)d_in[1];
    const float* c0   = (const float*)d_in[2];
    const float* Wf   = (const float*)d_in[3];
    const float* Uf   = (const float*)d_in[4];
    const float* bf   = (const float*)d_in[5];
    const float* Wb   = (const float*)d_in[6];
    const float* Ub   = (const float*)d_in[7];
    const float* bb   = (const float*)d_in[8];
    const float* Wfc1 = (const float*)d_in[9];
    const float* bfc1 = (const float*)d_in[10];
    const float* g1   = (const float*)d_in[11];
    const float* b1   = (const float*)d_in[12];
    const float* Wi   = (const float*)d_in[13];
    const float* Ui   = (const float*)d_in[14];
    const float* bi   = (const float*)d_in[15];
    const float* Wfc2 = (const float*)d_in[16];
    const float* bfc2 = (const float*)d_in[17];
    const float* g2   = (const float*)d_in[18];
    const float* b2   = (const float*)d_in[19];

    float* out = (float*)d_out;
    float* h_out = out + OUT0;
    float* c_out = out + 2 * OUT0;
    const int full_out = (out_size >= (int)(3 * OUT0)) || out_size <= 0;

    float *fc, *bfc, *biP, *hcfb;
    __half *zx, *ah, *bt, *ut, *hsh;
    cudaGetSymbolAddress((void**)&zx,  g_ZX);
    cudaGetSymbolAddress((void**)&fc,  g_FC);
    cudaGetSymbolAddress((void**)&bfc, g_bfc);
    cudaGetSymbolAddress((void**)&biP, g_biP);
    cudaGetSymbolAddress((void**)&ah,  g_Ah);
    cudaGetSymbolAddress((void**)&bt,  g_Bt);
    cudaGetSymbolAddress((void**)&ut,  g_Ut);
    cudaGetSymbolAddress((void**)&hsh, g_HSh);
    cudaGetSymbolAddress((void**)&hcfb, g_HCfb);

    cudaFuncSetAttribute(tcgemm, cudaFuncAttributeMaxDynamicSharedMemorySize, GEMM_SMEM);
    cudaFuncSetAttribute(tcgemm_h, cudaFuncAttributeMaxDynamicSharedMemorySize, GEMM_SMEM);
    cudaFuncSetAttribute(tcgemm_gates, cudaFuncAttributeMaxDynamicSharedMemorySize, GATES_SMEM);
    cudaFuncSetAttribute(recurrence2, cudaFuncAttributeMaxDynamicSharedMemorySize, RSMEM);

    const int n4A = MROWS * 512 / 4;

    // ---- all weight/bias prep in ONE launch ----
    prep_all<<<dim3(64, 16, 9), dim3(32, 8)>>>(Wf, Wb, Uf, Ub, Wfc1, Wfc2, Wi, Ui,
                                               bf, bb, bi, bt, ut, bfc, biP);

    // ---- combined intra input projection: ZX(fp16) = x @ [Wf|Wb] + [bf|bb] ----
    cvt_kernel<<<n4A / 256, 256>>>(x, ah, n4A);
    tcgemm_h<<<dim3(16, 256), 256, GEMM_SMEM>>>(ah, bt, zx, bfc, MROWS, 2048, 512);

    // ---- recurrence ----
    recurrence2<<<128, 256, RSMEM>>>(ut);

    // ---- fc1 (A = HS) ----
    tcgemm<<<dim3(4, 256), 256, GEMM_SMEM>>>(hsh, bt + OFF_FC1, fc, bfc1, MROWS, 512, 512);

    // ---- LN1 + residual -> out, fused convert (concat A cols 0..511) ----
    ln_kernel<<<256, 256>>>(fc, x, g1, b1, out, ah, 0);

    // ---- inter: single K=1024 GEMM with fused gates ----
    cvt_off_kernel<<<16384, 256>>>(h0, ah);
    float* hptr = full_out ? h_out : hcfb;
    float* cptr = full_out ? c_out : (hcfb + (size_t)MROWS * 512);
    tcgemm_gates<<<dim3(16, 256), 256, GATES_SMEM>>>(ah, bt + OFF_INTER, biP, c0,
                                                     hptr, cptr, hsh, 1024);

    // ---- fc2 (A = h in g_HSh) ----
    tcgemm<<<dim3(4, 256), 256, GEMM_SMEM>>>(hsh, bt + OFF_FC2, fc, bfc2, MROWS, 512, 512);

    // ---- LN2 accumulate into out ----
    ln_kernel<<<256, 256>>>(fc, nullptr, g2, b2, out, nullptr, 1);
}

// round 12
// speedup vs baseline: 1.1824x; 1.0478x over previous
#include <cuda_runtime.h>
#include <cuda_fp16.h>
#include <cstdint>
#include <math.h>

// Problem constants
#define NSAMP 256            // B*L
#define W_    128
#define C_    512
#define HD_   256
#define MROWS 32768          // B*W
#define OUT0  ((size_t)16777216)   // B*L*W*C

// B-region offsets inside g_Bt (in halfs)
#define OFF_INTER 1048576          // 2048 rows x 1024 K
#define OFF_FC1   3145728          // 512 x 512
#define OFF_FC2   3407872          // 512 x 512

// ---------------- scratch (static device globals; no allocations) ----------------
__device__ __half g_ZX [(size_t)MROWS * 2048];  // combined intra projections, fp16
__device__ float g_FC [(size_t)MROWS * 512];
__device__ float g_bfc[2048];
__device__ float g_biP[2048];
__device__ unsigned long long g_barG[8 * 16];   // per-group monotonic tickets

// fp16 operand buffers
__device__ __half g_Ah [(size_t)MROWS * 1024];
__device__ __half g_Bt [(size_t)3670016];       // proj | inter | fc1 | fc2 regions
// recurrence state / weights / outputs (fp16)
__device__ __half g_Hh[2][512 * 256];
__device__ __half g_Ut[(size_t)2048 * 256];
__device__ __half g_HSh[(size_t)MROWS * 512];
// fallback h/c buffers when out buffer is small
__device__ float g_HCfb[2][(size_t)MROWS * 512];

__device__ __forceinline__ float hsig(float x) {
    return fminf(fmaxf(fmaf(0.2f, x, 0.5f), 0.0f), 1.0f);
}
// fast tanh: 1 - 2/(e^{2x}+1); rel err ~1e-6 (MUFU ex2 + rcp), saturates correctly
__device__ __forceinline__ float fast_tanh(float x) {
    const float e = __expf(2.0f * x);
    return 1.0f - __fdividef(2.0f, e + 1.0f);
}

// ================= low-level helpers (sm_80-baseline ISA only) =================
__device__ __forceinline__ uint32_t smem_u32(const void* p) {
    uint32_t a;
    asm("{ .reg .u64 t; cvta.to.shared.u64 t, %1; cvt.u32.u64 %0, t; }" : "=r"(a) : "l"(p));
    return a;
}
#define CP_ASYNC16(dst, src) \
    asm volatile("cp.async.cg.shared.global [%0], [%1], 16;" :: "r"(dst), "l"(src) : "memory")
#define CP_COMMIT() asm volatile("cp.async.commit_group;" ::: "memory")
#define CP_WAIT2()  asm volatile("cp.async.wait_group 2;" ::: "memory")
#define CP_WAIT1()  asm volatile("cp.async.wait_group 1;" ::: "memory")
#define CP_WAIT0()  asm volatile("cp.async.wait_group 0;" ::: "memory")

__device__ __forceinline__ void ldmx4(uint32_t* r, uint32_t addr) {
    asm volatile("ldmatrix.sync.aligned.m8n8.x4.shared.b16 {%0,%1,%2,%3}, [%4];"
        : "=r"(r[0]), "=r"(r[1]), "=r"(r[2]), "=r"(r[3]) : "r"(addr));
}
__device__ __forceinline__ void mma_f16(float* d, const uint32_t* a, const uint32_t* b) {
    asm volatile("mma.sync.aligned.m16n8k16.row.col.f32.f16.f16.f32 "
        "{%0,%1,%2,%3}, {%4,%5,%6,%7}, {%8,%9}, {%0,%1,%2,%3};"
        : "+f"(d[0]), "+f"(d[1]), "+f"(d[2]), "+f"(d[3])
        : "r"(a[0]), "r"(a[1]), "r"(a[2]), "r"(a[3]), "r"(b[0]), "r"(b[1]));
}
__device__ __forceinline__ unsigned long long ld_acquire(const unsigned long long* p) {
    unsigned long long v;
    asm volatile("ld.acquire.gpu.u64 %0, [%1];" : "=l"(v) : "l"(p) : "memory");
    return v;
}

// ================= 128x128 fp16 GEMM (2 CTAs/SM, 3-stage pipeline) =================
#define TILE_B   10240           // 128*80
#define STG_B    20480
#define GEMM_SMEM  61440         // 3 stages
#define GATES_SMEM 67584         // epilogue stg 128*132*4

__device__ __forceinline__ void load_chunk(uint32_t stage_base,
    const __half* __restrict__ Ah, const __half* __restrict__ Bh,
    int m0, int n0, int kk, int K, int tid)
{
#pragma unroll
    for (int i = 0; i < 2; i++) {
        const int c = tid + i * 256;
        const int row = c >> 2;
        const int seg = c & 3;
        const uint32_t doff = (uint32_t)(row * 80 + seg * 16);
        const size_t akoff = (size_t)kk + seg * 8;
        CP_ASYNC16(stage_base + 0 * TILE_B + doff, Ah + (size_t)(m0 + row) * K + akoff);
        CP_ASYNC16(stage_base + 1 * TILE_B + doff, Bh + (size_t)(n0 + row) * K + akoff);
    }
}

#define GEMM_MAINLOOP(Ah, Bh, m0, n0, K, acc)                                     \
    {                                                                             \
        const int NC = (K) >> 5;                                                  \
        load_chunk(sb + 0 * STG_B, Ah, Bh, m0, n0, 0, K, tid);                    \
        CP_COMMIT();                                                              \
        load_chunk(sb + 1 * STG_B, Ah, Bh, m0, n0, 32, K, tid);                   \
        CP_COMMIT();                                                              \
        load_chunk(sb + 2 * STG_B, Ah, Bh, m0, n0, 64, K, tid);                   \
        CP_COMMIT();                                                              \
        int stage = 0;                                                            \
        for (int c = 0; c < NC; c++) {                                            \
            CP_WAIT2();                                                           \
            __syncthreads();                                                      \
            const uint32_t st = sb + stage * STG_B;                               \
            _Pragma("unroll")                                                     \
            for (int ks = 0; ks < 2; ks++) {                                      \
                const uint32_t kb = st + ks * 32;                                 \
                uint32_t af[4][4], bhf[4][2], t4[4];                              \
                _Pragma("unroll")                                                 \
                for (int nh = 0; nh < 2; nh++) {                                  \
                    ldmx4(t4, kb + 1 * TILE_B + b_off + nh * 1280);               \
                    bhf[2*nh][0] = t4[0]; bhf[2*nh][1] = t4[1];                   \
                    bhf[2*nh+1][0] = t4[2]; bhf[2*nh+1][1] = t4[3];               \
                }                                                                 \
                _Pragma("unroll")                                                 \
                for (int mf = 0; mf < 4; mf++) ldmx4(af[mf], kb + a_off + mf * 1280); \
                _Pragma("unroll")                                                 \
                for (int mf = 0; mf < 4; mf++)                                    \
                    _Pragma("unroll")                                             \
                    for (int nf = 0; nf < 4; nf++)                                \
                        mma_f16(acc[mf][nf], af[mf], bhf[nf]);                    \
            }                                                                     \
            __syncthreads();                                                      \
            if (c + 3 < NC)                                                       \
                load_chunk(st, Ah, Bh, m0, n0, (c + 3) << 5, K, tid);             \
            CP_COMMIT();                                                          \
            stage = (stage == 2) ? 0 : stage + 1;                                 \
        }                                                                         \
    }

// fp32-output GEMM (fc1/fc2)
__global__ __launch_bounds__(256, 2) void tcgemm(
    const __half* __restrict__ Ah, const __half* __restrict__ Bh,
    float* __restrict__ Cmat, const float* __restrict__ bias,
    int M, int N, int K)
{
    extern __shared__ __align__(128) char smem_raw[];
    const uint32_t sb = smem_u32(smem_raw);

    const int tid = threadIdx.x;
    const int lane = tid & 31;
    const int wid = tid >> 5;
    const int wm = wid >> 2;
    const int wn = wid & 3;
    const int m0 = blockIdx.y << 7;
    const int n0 = blockIdx.x << 7;

    const uint32_t a_off = (uint32_t)((wm * 64 + (lane & 15)) * 80 + (lane >> 4) * 16);
    const int bsub = lane >> 3;
    const uint32_t b_off = (uint32_t)((wn * 32 + ((bsub >> 1) << 3) + (lane & 7)) * 80 + (bsub & 1) * 16);

    float acc[4][4][4];
#pragma unroll
    for (int mf = 0; mf < 4; mf++)
#pragma unroll
        for (int nf = 0; nf < 4; nf++)
#pragma unroll
            for (int r = 0; r < 4; r++) acc[mf][nf][r] = 0.0f;

    GEMM_MAINLOOP(Ah, Bh, m0, n0, K, acc);

    const int qr = lane >> 2;
    const int qc = (lane & 3) << 1;
#pragma unroll
    for (int mf = 0; mf < 4; mf++) {
        const int row = m0 + wm * 64 + mf * 16 + qr;
#pragma unroll
        for (int nf = 0; nf < 4; nf++) {
            const int col = n0 + wn * 32 + nf * 8 + qc;
            const float2 bv = *(const float2*)(bias + col);
            float2 v0 = make_float2(acc[mf][nf][0] + bv.x, acc[mf][nf][1] + bv.y);
            float2 v1 = make_float2(acc[mf][nf][2] + bv.x, acc[mf][nf][3] + bv.y);
            *(float2*)(Cmat + (size_t)row * N + col) = v0;
            *(float2*)(Cmat + (size_t)(row + 8) * N + col) = v1;
        }
    }
}

// fp16-output GEMM (intra projection -> ZX)
__global__ __launch_bounds__(256, 2) void tcgemm_h(
    const __half* __restrict__ Ah, const __half* __restrict__ Bh,
    __half* __restrict__ Cmat, const float* __restrict__ bias,
    int M, int N, int K)
{
    extern __shared__ __align__(128) char smem_raw[];
    const uint32_t sb = smem_u32(smem_raw);

    const int tid = threadIdx.x;
    const int lane = tid & 31;
    const int wid = tid >> 5;
    const int wm = wid >> 2;
    const int wn = wid & 3;
    const int m0 = blockIdx.y << 7;
    const int n0 = blockIdx.x << 7;

    const uint32_t a_off = (uint32_t)((wm * 64 + (lane & 15)) * 80 + (lane >> 4) * 16);
    const int bsub = lane >> 3;
    const uint32_t b_off = (uint32_t)((wn * 32 + ((bsub >> 1) << 3) + (lane & 7)) * 80 + (bsub & 1) * 16);

    float acc[4][4][4];
#pragma unroll
    for (int mf = 0; mf < 4; mf++)
#pragma unroll
        for (int nf = 0; nf < 4; nf++)
#pragma unroll
            for (int r = 0; r < 4; r++) acc[mf][nf][r] = 0.0f;

    GEMM_MAINLOOP(Ah, Bh, m0, n0, K, acc);

    const int qr = lane >> 2;
    const int qc = (lane & 3) << 1;
#pragma unroll
    for (int mf = 0; mf < 4; mf++) {
        const int row = m0 + wm * 64 + mf * 16 + qr;
#pragma unroll
        for (int nf = 0; nf < 4; nf++) {
            const int col = n0 + wn * 32 + nf * 8 + qc;
            const float2 bv = *(const float2*)(bias + col);
            *(__half2*)(Cmat + (size_t)row * N + col) =
                __half2(__float2half_rn(acc[mf][nf][0] + bv.x),
                        __float2half_rn(acc[mf][nf][1] + bv.y));
            *(__half2*)(Cmat + (size_t)(row + 8) * N + col) =
                __half2(__float2half_rn(acc[mf][nf][2] + bv.x),
                        __float2half_rn(acc[mf][nf][3] + bv.y));
        }
    }
}

// ---- inter GEMM with fused LSTM gate epilogue (gate-interleaved B layout) ----
__global__ __launch_bounds__(256, 2) void tcgemm_gates(
    const __half* __restrict__ Ah, const __half* __restrict__ Bh,
    const float* __restrict__ biasP, const float* __restrict__ c0,
    float* __restrict__ h_out, float* __restrict__ c_out,
    __half* __restrict__ hh_out, int K)
{
    extern __shared__ __align__(128) char smem_raw[];
    const uint32_t sb = smem_u32(smem_raw);

    const int tid = threadIdx.x;
    const int lane = tid & 31;
    const int wid = tid >> 5;
    const int wm = wid >> 2;
    const int wn = wid & 3;
    const int m0 = blockIdx.y << 7;
    const int n0 = blockIdx.x << 7;
    const int hid0 = blockIdx.x << 5;

    const uint32_t a_off = (uint32_t)((wm * 64 + (lane & 15)) * 80 + (lane >> 4) * 16);
    const int bsub = lane >> 3;
    const uint32_t b_off = (uint32_t)((wn * 32 + ((bsub >> 1) << 3) + (lane & 7)) * 80 + (bsub & 1) * 16);

    float acc[4][4][4];
#pragma unroll
    for (int mf = 0; mf < 4; mf++)
#pragma unroll
        for (int nf = 0; nf < 4; nf++)
#pragma unroll
            for (int r = 0; r < 4; r++) acc[mf][nf][r] = 0.0f;

    GEMM_MAINLOOP(Ah, Bh, m0, n0, K, acc);

    __syncthreads();
    float* stg = (float*)smem_raw;    // 128 x 132
    const int qr = lane >> 2;
    const int qc = (lane & 3) << 1;
#pragma unroll
    for (int mf = 0; mf < 4; mf++) {
        const int rl = wm * 64 + mf * 16 + qr;
#pragma unroll
        for (int nf = 0; nf < 4; nf++) {
            const int col = wn * 32 + nf * 8 + qc;
            const float2 bv = *(const float2*)(biasP + n0 + col);
            stg[rl * 132 + col]           = acc[mf][nf][0] + bv.x;
            stg[rl * 132 + col + 1]       = acc[mf][nf][1] + bv.y;
            stg[(rl + 8) * 132 + col]     = acc[mf][nf][2] + bv.x;
            stg[(rl + 8) * 132 + col + 1] = acc[mf][nf][3] + bv.y;
        }
    }
    __syncthreads();

    {
        const int c = lane;
#pragma unroll
        for (int i = 0; i < 16; i++) {
            const int r = wid * 16 + i;
            const float zi = stg[r * 132 + c];
            const float zf = stg[r * 132 + 32 + c];
            const float zg = stg[r * 132 + 64 + c];
            const float zo = stg[r * 132 + 96 + c];
            const size_t go = (size_t)(m0 + r) * 512 + hid0 + c;
            const float cn = hsig(zf) * c0[go] + hsig(zi) * fast_tanh(zg);
            const float hv = hsig(zo) * fast_tanh(cn);
            c_out[go] = cn;
            h_out[go] = hv;
            hh_out[go] = __float2half_rn(hv);
        }
    }
}

// ================= convert kernels =================
__global__ __launch_bounds__(256) void cvt_kernel(
    const float* __restrict__ in, __half* __restrict__ out, int n4)
{
    const int i = blockIdx.x * blockDim.x + threadIdx.x;
    if (i >= n4) return;
    const float4 v = ((const float4*)in)[i];
    ((__half2*)out)[2 * i]     = __half2(__float2half_rn(v.x), __float2half_rn(v.y));
    ((__half2*)out)[2 * i + 1] = __half2(__float2half_rn(v.z), __float2half_rn(v.w));
}

// h0 [32768,512] -> g_Ah at row*1024 + 512 + col
__global__ __launch_bounds__(256) void cvt_off_kernel(
    const float* __restrict__ in, __half* __restrict__ out)
{
    const int q = blockIdx.x * blockDim.x + threadIdx.x;
    const int row = q >> 7;
    const int col = (q & 127) << 2;
    const float4 v = ((const float4*)in)[q];
    const size_t o = (size_t)row * 1024 + 512 + col;
    *(__half2*)(out + o)     = __half2(__float2half_rn(v.x), __float2half_rn(v.y));
    *(__half2*)(out + o + 2) = __half2(__float2half_rn(v.z), __float2half_rn(v.w));
}

// ---- unified weight/bias prep: blockIdx.z selects job ----
__device__ __forceinline__ void cvtT_tile(const float* __restrict__ Wm,
                                          __half* __restrict__ dst,
                                          int K, int N, int bx, int by,
                                          int tx, int ty)
{
    __shared__ float t[32][33];
    const int kb = by * 32, nb = bx * 32;
    for (int r = ty; r < 32; r += 8)
        t[r][tx] = Wm[(size_t)(kb + r) * N + nb + tx];
    __syncthreads();
    for (int r = ty; r < 32; r += 8)
        dst[(size_t)(nb + r) * K + kb + tx] = __float2half_rn(t[tx][r]);
}

__device__ __forceinline__ void cvtT_perm_tile(const float* __restrict__ Wm,
                                               __half* __restrict__ dst,
                                               int N, int Kout, int koff,
                                               int bx, int by, int tx, int ty)
{
    __shared__ float t[32][33];
    const int kb = by * 32, nb = bx * 32;
    for (int r = ty; r < 32; r += 8)
        t[r][tx] = Wm[(size_t)(kb + r) * N + nb + tx];
    __syncthreads();
    for (int r = ty; r < 32; r += 8) {
        const int n = nb + r;
        const int g = n >> 9, s = n & 511;
        const int nr = ((s >> 5) << 7) + (g << 5) + (s & 31);
        dst[(size_t)nr * Kout + koff + kb + tx] = __float2half_rn(t[tx][r]);
    }
}

__global__ void prep_all(
    const float* __restrict__ Wf, const float* __restrict__ Wb,
    const float* __restrict__ Uf, const float* __restrict__ Ub,
    const float* __restrict__ Wfc1, const float* __restrict__ Wfc2,
    const float* __restrict__ Wi, const float* __restrict__ Ui,
    const float* __restrict__ bf, const float* __restrict__ bb,
    const float* __restrict__ bi,
    __half* __restrict__ bt, __half* __restrict__ ut,
    float* __restrict__ bfc, float* __restrict__ biP)
{
    const int bx = blockIdx.x, by = blockIdx.y, job = blockIdx.z;
    const int tx = threadIdx.x, ty = threadIdx.y;
    switch (job) {
        case 0: if (bx < 32 && by < 16) cvtT_tile(Wf, bt, 512, 1024, bx, by, tx, ty); break;
        case 1: if (bx < 32 && by < 16) cvtT_tile(Wb, bt + (size_t)1024 * 512, 512, 1024, bx, by, tx, ty); break;
        case 2: if (bx < 32 && by < 8)  cvtT_tile(Uf, ut, 256, 1024, bx, by, tx, ty); break;
        case 3: if (bx < 32 && by < 8)  cvtT_tile(Ub, ut + 1024 * 256, 256, 1024, bx, by, tx, ty); break;
        case 4: if (bx < 16 && by < 16) cvtT_tile(Wfc1, bt + OFF_FC1, 512, 512, bx, by, tx, ty); break;
        case 5: if (bx < 16 && by < 16) cvtT_tile(Wfc2, bt + OFF_FC2, 512, 512, bx, by, tx, ty); break;
        case 6: if (bx < 64 && by < 16) cvtT_perm_tile(Wi, bt + OFF_INTER, 2048, 1024, 0, bx, by, tx, ty); break;
        case 7: if (bx < 64 && by < 16) cvtT_perm_tile(Ui, bt + OFF_INTER, 2048, 1024, 512, bx, by, tx, ty); break;
        case 8: {
            if (by == 0 && bx < 16) {
                const int i = bx * 256 + ty * 32 + tx;
                if (i < 1024) bfc[i] = bf[i];
                else if (i < 2048) bfc[i] = bb[i - 1024];
                else {
                    const int n = i - 2048;
                    const int g = n >> 9, s = n & 511;
                    const int nr = ((s >> 5) << 7) + (g << 5) + (s & 31);
                    biP[nr] = bi[n];
                }
            }
            break;
        }
    }
}

// ---------------- group barrier (16 CTAs per group; used pre-loop only) ----------------
__device__ __forceinline__ void group_barrier(int grp) {
    __threadfence();
    __syncthreads();
    if (threadIdx.x == 0) {
        unsigned long long* ctr = &g_barG[grp * 16];
        unsigned long long t = atomicAdd(ctr, 1ULL) + 1ULL;
        unsigned long long target = ((t + 15ULL) >> 4) << 4;
        while (ld_acquire(ctr) < target) { }
    }
    __syncthreads();
}

// ---------------- persistent bidirectional LSTM recurrence ----------------
// fp16, B(U) fragments register-resident, arrive-early split barrier.
#define RA_STR   528
#define ROFF_BHI 33792
#define ROFF_STG 67584
#define ROFF_ZX  84992           // 2 x 8KB fp16 zx buffers
#define RSMEM    101376

__global__ __launch_bounds__(256) void recurrence2(const __half* __restrict__ Ut)
{
    extern __shared__ __align__(128) char rsm[];
    const uint32_t sb = smem_u32(rsm);
    const int tid = threadIdx.x, lane = tid & 31, wid = tid >> 5;
    const int blk = blockIdx.x;
    const int tile_m = blk >> 4;
    const int tile_n = blk & 15;
    const int row0 = tile_m << 6;
    const int dir = (tile_m >= 4) ? 1 : 0;
    const int j0 = tile_n << 4;
    const int wm = wid & 3, wn = wid >> 2;
    unsigned long long* const ctr = &g_barG[tile_m * 16];

    for (int i = tid; i < 2048; i += 256) {
        const int r = i >> 5, seg = i & 31;
        const int g = r >> 4, c = r & 15;
        const size_t gr = ((size_t)(dir * 1024 + g * 256 + j0 + c)) * 256 + seg * 8;
        *(uint4*)(rsm + ROFF_BHI + r * RA_STR + seg * 16) = *(const uint4*)(Ut + gr);
    }

    if (tile_n == 0) {
        uint32_t* h0 = (uint32_t*)&g_Hh[0][row0 * 256];
        for (int i = tid; i < 8192; i += 256) h0[i] = 0u;
    }

    const uint32_t a_off = (uint32_t)((wm * 16 + (lane & 15)) * RA_STR + (lane >> 4) * 16);
    const int bsub = lane >> 3;
    const uint32_t b_off = (uint32_t)((wn * 32 + ((bsub >> 1) << 3) + (lane & 7)) * RA_STR + (bsub & 1) * 16);

    const int r_up = tid >> 2;
    const int c_up = (tid & 3) << 2;
    const int Rr = row0 + r_up;
    const int n_up = Rr & 255;
    float* stg = (float*)(rsm + ROFF_STG);
    float creg[4] = {0.0f, 0.0f, 0.0f, 0.0f};

    // ---- prefetch zx(0) into buffer 0 ----
    {
        const int w0 = dir ? 127 : 0;
#pragma unroll
        for (int ii = 0; ii < 2; ii++) {
            const int q = tid + ii * 256;
            const int r = q >> 3;
            const int rem = q & 7;
            const int g = rem >> 1;
            const int part = rem & 1;
            const int rr = row0 + r;
            const __half* src = g_ZX + ((size_t)(rr & 255) * 128 + w0) * 2048
                               + dir * 1024 + j0 + g * 256 + part * 8;
            CP_ASYNC16(sb + ROFF_ZX + (uint32_t)(r * 128 + g * 32 + part * 16), src);
        }
    }
    CP_COMMIT();

    group_barrier(tile_m);

    // ---- cache ALL B (U) fragments in registers: constant across all 128 steps ----
    uint32_t breg[16][4][2];
#pragma unroll
    for (int ks = 0; ks < 16; ks++) {
        uint32_t t4[4];
        ldmx4(t4, sb + ROFF_BHI + b_off + ks * 32);
        breg[ks][0][0] = t4[0]; breg[ks][0][1] = t4[1];
        breg[ks][1][0] = t4[2]; breg[ks][1][1] = t4[3];
        ldmx4(t4, sb + ROFF_BHI + b_off + ks * 32 + 16 * RA_STR);
        breg[ks][2][0] = t4[0]; breg[ks][2][1] = t4[1];
        breg[ks][3][0] = t4[2]; breg[ks][3][1] = t4[3];
    }

    unsigned long long spin_target = 0;

    for (int t = 0; t < 128; t++) {
        const int pb = t & 1;
        const int w = dir ? (127 - t) : t;
        const __half* hh = g_Hh[pb];
        const __half* zxs = (const __half*)(rsm + ROFF_ZX + (t & 1) * 8192);

        // ---- commit group: H k 0..127 ----
#pragma unroll
        for (int ii = 0; ii < 4; ii++) {
            const int i = tid + ii * 256;
            const int r = i >> 4, seg = i & 15;
            CP_ASYNC16(sb + r * RA_STR + seg * 16, hh + (size_t)(row0 + r) * 256 + seg * 8);
        }
        CP_COMMIT();
        // ---- commit group: H k 128..255 ----
#pragma unroll
        for (int ii = 0; ii < 4; ii++) {
            const int i = tid + ii * 256;
            const int r = i >> 4, seg = 16 + (i & 15);
            CP_ASYNC16(sb + r * RA_STR + seg * 16, hh + (size_t)(row0 + r) * 256 + seg * 8);
        }
        CP_COMMIT();

        float acc[4][4];
#pragma unroll
        for (int nf = 0; nf < 4; nf++)
#pragma unroll
            for (int r = 0; r < 4; r++) acc[nf][r] = 0.0f;

        // wait: zx(t) + H first half done; H second half may be in flight
        CP_WAIT1();
        __syncthreads();
#pragma unroll
        for (int ks = 0; ks < 8; ks++) {
            uint32_t ah[4];
            ldmx4(ah, sb + a_off + ks * 32);
#pragma unroll
            for (int nf = 0; nf < 4; nf++)
                mma_f16(acc[nf], ah, breg[ks][nf]);
        }
        CP_WAIT0();
        __syncthreads();
#pragma unroll
        for (int ks = 8; ks < 16; ks++) {
            uint32_t ah[4];
            ldmx4(ah, sb + a_off + ks * 32);
#pragma unroll
            for (int nf = 0; nf < 4; nf++)
                mma_f16(acc[nf], ah, breg[ks][nf]);
        }

        {
            const int qr = lane >> 2, qc = (lane & 3) << 1;
#pragma unroll
            for (int nf = 0; nf < 4; nf++) {
                const int col = wn * 32 + nf * 8 + qc;
                stg[(wm * 16 + qr) * 68 + col]     = acc[nf][0];
                stg[(wm * 16 + qr) * 68 + col + 1] = acc[nf][1];
                stg[(wm * 16 + qr + 8) * 68 + col]     = acc[nf][2];
                stg[(wm * 16 + qr + 8) * 68 + col + 1] = acc[nf][3];
            }
        }
        __syncthreads();

        // ---- update phase: compute h/c, store H state FIRST ----
        __half2 p0, p1;
        {
            __half* dhh = &g_Hh[pb ^ 1][(size_t)Rr * 256 + j0 + c_up];
            const __half* zx = zxs + r_up * 64 + c_up;
            float hv[4];
#pragma unroll
            for (int l = 0; l < 4; l++) {
                const float* sr = &stg[r_up * 68 + c_up + l];
                const float zi = sr[0]  + __half2float(zx[l]);
                const float zf = sr[16] + __half2float(zx[16 + l]);
                const float zg = sr[32] + __half2float(zx[32 + l]);
                const float zo = sr[48] + __half2float(zx[48 + l]);
                const float cn = hsig(zf) * creg[l] + hsig(zi) * fast_tanh(zg);
                creg[l] = cn;
                hv[l] = hsig(zo) * fast_tanh(cn);
            }
            p0 = __half2(__float2half_rn(hv[0]), __float2half_rn(hv[1]));
            p1 = __half2(__float2half_rn(hv[2]), __float2half_rn(hv[3]));
            *(__half2*)(dhh)     = p0;
            *(__half2*)(dhh + 2) = p1;
        }

        if (t < 127) {
            // arrive EARLY: H written; HS stores + zx prefetch ride under peer skew
            __threadfence();
            __syncthreads();
            if (tid == 0) {
                unsigned long long my = atomicAdd(ctr, 1ULL) + 1ULL;
                spin_target = ((my + 15ULL) >> 4) << 4;
            }
        }

        // HS output stores (not on cross-CTA critical path)
        {
            const size_t hsoff = ((size_t)n_up * 128 + w) * 512 + dir * 256 + j0 + c_up;
            *(__half2*)(g_HSh + hsoff)     = p0;
            *(__half2*)(g_HSh + hsoff + 2) = p1;
        }

        if (t < 127) {
            // zx(t+1) prefetch into the other buffer
            const int wn1 = dir ? (127 - (t + 1)) : (t + 1);
            const uint32_t zdst = sb + ROFF_ZX + (uint32_t)(((t + 1) & 1) * 8192);
#pragma unroll
            for (int ii = 0; ii < 2; ii++) {
                const int q = tid + ii * 256;
                const int r = q >> 3;
                const int rem = q & 7;
                const int g = rem >> 1;
                const int part = rem & 1;
                const int rr = row0 + r;
                const __half* src = g_ZX + ((size_t)(rr & 255) * 128 + wn1) * 2048
                                   + dir * 1024 + j0 + g * 256 + part * 8;
                CP_ASYNC16(zdst + (uint32_t)(r * 128 + g * 32 + part * 16), src);
            }
            CP_COMMIT();
            if (tid == 0) {
                while (ld_acquire(ctr) < spin_target) { }
            }
            __syncthreads();
        }
    }
}

// ---------------- LayerNorm over (W,C)=65536, optional fused fp16 convert (stride 1024) ----------------
__global__ __launch_bounds__(256) void ln_kernel(
    const float* __restrict__ pre, const float* __restrict__ xres,
    const float* __restrict__ gamma, const float* __restrict__ beta,
    float* __restrict__ out, __half* __restrict__ sh, int mode)
{
    __shared__ float red[256];
    const int tid = threadIdx.x;
    const size_t base = (size_t)blockIdx.x * 65536;

    float s = 0.0f, ss = 0.0f;
    for (int i = tid * 4; i < 65536; i += 1024) {
        float4 v = *(const float4*)(pre + base + i);
        s  += v.x + v.y + v.z + v.w;
        ss += v.x * v.x + v.y * v.y + v.z * v.z + v.w * v.w;
    }
    red[tid] = s; __syncthreads();
    for (int off = 128; off; off >>= 1) { if (tid < off) red[tid] += red[tid + off]; __syncthreads(); }
    const float mean = red[0] * (1.0f / 65536.0f);
    __syncthreads();
    red[tid] = ss; __syncthreads();
    for (int off = 128; off; off >>= 1) { if (tid < off) red[tid] += red[tid + off]; __syncthreads(); }
    const float var = red[0] * (1.0f / 65536.0f) - mean * mean;
    const float rstd = rsqrtf(var + 1e-3f);

    for (int i = tid * 4; i < 65536; i += 1024) {
        float4 v = *(const float4*)(pre + base + i);
        float4 g = *(const float4*)(gamma + i);
        float4 bb = *(const float4*)(beta + i);
        float4 r;
        r.x = (v.x - mean) * rstd * g.x + bb.x;
        r.y = (v.y - mean) * rstd * g.y + bb.y;
        r.z = (v.z - mean) * rstd * g.z + bb.z;
        r.w = (v.w - mean) * rstd * g.w + bb.w;
        if (mode == 0) {
            float4 xr = *(const float4*)(xres + base + i);
            r.x += xr.x; r.y += xr.y; r.z += xr.z; r.w += xr.w;
        } else {
            float4 o = *(const float4*)(out + base + i);
            r.x += o.x; r.y += o.y; r.z += o.z; r.w += o.w;
        }
        *(float4*)(out + base + i) = r;
        if (sh) {
            const size_t f = base + i;
            const size_t so = (f >> 9) * 1024 + (f & 511);
            *(__half2*)(sh + so)     = __half2(__float2half_rn(r.x), __float2half_rn(r.y));
            *(__half2*)(sh + so + 2) = __half2(__float2half_rn(r.z), __float2half_rn(r.w));
        }
    }
}

// ---------------- launch ----------------
extern "C" void kernel_launch(void* const* d_in, const int* in_sizes, int n_in,
                              void* d_out, int out_size)
{
    const float* x    = (const float*)d_in[0];
    const float* h0   = (const float*)d_in[1];
    const float* c0   = (const float*)d_in[2];
    const float* Wf   = (const float*)d_in[3];
    const float* Uf   = (const float*)d_in[4];
    const float* bf   = (const float*)d_in[5];
    const float* Wb   = (const float*)d_in[6];
    const float* Ub   = (const float*)d_in[7];
    const float* bb   = (const float*)d_in[8];
    const float* Wfc1 = (const float*)d_in[9];
    const float* bfc1 = (const float*)d_in[10];
    const float* g1   = (const float*)d_in[11];
    const float* b1   = (const float*)d_in[12];
    const float* Wi   = (const float*)d_in[13];
    const float* Ui   = (const float*)d_in[14];
    const float* bi   = (const float*)d_in[15];
    const float* Wfc2 = (const float*)d_in[16];
    const float* bfc2 = (const float*)d_in[17];
    const float* g2   = (const float*)d_in[18];
    const float* b2   = (const float*)d_in[19];

    float* out = (float*)d_out;
    float* h_out = out + OUT0;
    float* c_out = out + 2 * OUT0;
    const int full_out = (out_size >= (int)(3 * OUT0)) || out_size <= 0;

    float *fc, *bfc, *biP, *hcfb;
    __half *zx, *ah, *bt, *ut, *hsh;
    cudaGetSymbolAddress((void**)&zx,  g_ZX);
    cudaGetSymbolAddress((void**)&fc,  g_FC);
    cudaGetSymbolAddress((void**)&bfc, g_bfc);
    cudaGetSymbolAddress((void**)&biP, g_biP);
    cudaGetSymbolAddress((void**)&ah,  g_Ah);
    cudaGetSymbolAddress((void**)&bt,  g_Bt);
    cudaGetSymbolAddress((void**)&ut,  g_Ut);
    cudaGetSymbolAddress((void**)&hsh, g_HSh);
    cudaGetSymbolAddress((void**)&hcfb, g_HCfb);

    cudaFuncSetAttribute(tcgemm, cudaFuncAttributeMaxDynamicSharedMemorySize, GEMM_SMEM);
    cudaFuncSetAttribute(tcgemm_h, cudaFuncAttributeMaxDynamicSharedMemorySize, GEMM_SMEM);
    cudaFuncSetAttribute(tcgemm_gates, cudaFuncAttributeMaxDynamicSharedMemorySize, GATES_SMEM);
    cudaFuncSetAttribute(recurrence2, cudaFuncAttributeMaxDynamicSharedMemorySize, RSMEM);

    const int n4A = MROWS * 512 / 4;

    // ---- all weight/bias prep in ONE launch ----
    prep_all<<<dim3(64, 16, 9), dim3(32, 8)>>>(Wf, Wb, Uf, Ub, Wfc1, Wfc2, Wi, Ui,
                                               bf, bb, bi, bt, ut, bfc, biP);

    // ---- combined intra input projection: ZX(fp16) = x @ [Wf|Wb] + [bf|bb] ----
    cvt_kernel<<<n4A / 256, 256>>>(x, ah, n4A);
    tcgemm_h<<<dim3(16, 256), 256, GEMM_SMEM>>>(ah, bt, zx, bfc, MROWS, 2048, 512);

    // ---- recurrence ----
    recurrence2<<<128, 256, RSMEM>>>(ut);

    // ---- fc1 (A = HS) ----
    tcgemm<<<dim3(4, 256), 256, GEMM_SMEM>>>(hsh, bt + OFF_FC1, fc, bfc1, MROWS, 512, 512);

    // ---- LN1 + residual -> out, fused convert (concat A cols 0..511) ----
    ln_kernel<<<256, 256>>>(fc, x, g1, b1, out, ah, 0);

    // ---- inter: single K=1024 GEMM with fused gates ----
    cvt_off_kernel<<<16384, 256>>>(h0, ah);
    float* hptr = full_out ? h_out : hcfb;
    float* cptr = full_out ? c_out : (hcfb + (size_t)MROWS * 512);
    tcgemm_gates<<<dim3(16, 256), 256, GATES_SMEM>>>(ah, bt + OFF_INTER, biP, c0,
                                                     hptr, cptr, hsh, 1024);

    // ---- fc2 (A = h in g_HSh) ----
    tcgemm<<<dim3(4, 256), 256, GEMM_SMEM>>>(hsh, bt + OFF_FC2, fc, bfc2, MROWS, 512, 512);

    // ---- LN2 accumulate into out ----
    ln_kernel<<<256, 256>>>(fc, nullptr, g2, b2, out, nullptr, 1);
}

// round 13
// speedup vs baseline: 1.2324x; 1.0423x over previous
#include <cuda_runtime.h>
#include <cuda_fp16.h>
#include <cstdint>
#include <math.h>

// Problem constants
#define NSAMP 256            // B*L
#define W_    128
#define C_    512
#define HD_   256
#define MROWS 32768          // B*W
#define OUT0  ((size_t)16777216)   // B*L*W*C

// B-region offsets inside g_Bt (in halfs)
#define OFF_INTER 1048576          // 2048 rows x 1024 K
#define OFF_FC1   3145728          // 512 x 512
#define OFF_FC2   3407872          // 512 x 512

// ---------------- scratch (static device globals; no allocations) ----------------
__device__ __half g_ZX [(size_t)MROWS * 2048];  // combined intra projections, fp16
__device__ float g_FC [(size_t)MROWS * 512];
__device__ float g_bfc[2048];
__device__ float g_biP[2048];
__device__ unsigned long long g_barG[8 * 16];   // per-group monotonic tickets

// fp16 operand buffers
__device__ __half g_Ah [(size_t)MROWS * 1024];
__device__ __half g_Bt [(size_t)3670016];       // proj | inter | fc1 | fc2 regions
// recurrence state / weights / outputs (fp16)
__device__ __half g_Hh[2][512 * 256];
__device__ __half g_Ut[(size_t)2048 * 256];
__device__ __half g_HSh[(size_t)MROWS * 512];
// fallback h/c buffers when out buffer is small
__device__ float g_HCfb[2][(size_t)MROWS * 512];

__device__ __forceinline__ float hsig(float x) {
    return fminf(fmaxf(fmaf(0.2f, x, 0.5f), 0.0f), 1.0f);
}
// fast tanh: 1 - 2/(e^{2x}+1); rel err ~1e-6 (MUFU ex2 + rcp), saturates correctly
__device__ __forceinline__ float fast_tanh(float x) {
    const float e = __expf(2.0f * x);
    return 1.0f - __fdividef(2.0f, e + 1.0f);
}

// ================= low-level helpers (sm_80-baseline ISA only) =================
__device__ __forceinline__ uint32_t smem_u32(const void* p) {
    uint32_t a;
    asm("{ .reg .u64 t; cvta.to.shared.u64 t, %1; cvt.u32.u64 %0, t; }" : "=r"(a) : "l"(p));
    return a;
}
#define CP_ASYNC16(dst, src) \
    asm volatile("cp.async.cg.shared.global [%0], [%1], 16;" :: "r"(dst), "l"(src) : "memory")
#define CP_COMMIT() asm volatile("cp.async.commit_group;" ::: "memory")
#define CP_WAIT2()  asm volatile("cp.async.wait_group 2;" ::: "memory")
#define CP_WAIT1()  asm volatile("cp.async.wait_group 1;" ::: "memory")
#define CP_WAIT0()  asm volatile("cp.async.wait_group 0;" ::: "memory")

__device__ __forceinline__ void ldmx4(uint32_t* r, uint32_t addr) {
    asm volatile("ldmatrix.sync.aligned.m8n8.x4.shared.b16 {%0,%1,%2,%3}, [%4];"
        : "=r"(r[0]), "=r"(r[1]), "=r"(r[2]), "=r"(r[3]) : "r"(addr));
}
__device__ __forceinline__ void mma_f16(float* d, const uint32_t* a, const uint32_t* b) {
    asm volatile("mma.sync.aligned.m16n8k16.row.col.f32.f16.f16.f32 "
        "{%0,%1,%2,%3}, {%4,%5,%6,%7}, {%8,%9}, {%0,%1,%2,%3};"
        : "+f"(d[0]), "+f"(d[1]), "+f"(d[2]), "+f"(d[3])
        : "r"(a[0]), "r"(a[1]), "r"(a[2]), "r"(a[3]), "r"(b[0]), "r"(b[1]));
}
__device__ __forceinline__ unsigned long long ld_acquire(const unsigned long long* p) {
    unsigned long long v;
    asm volatile("ld.acquire.gpu.u64 %0, [%1];" : "=l"(v) : "l"(p) : "memory");
    return v;
}

// ================= 128x128 fp16 GEMM (2 CTAs/SM, 3-stage pipeline) =================
#define TILE_B   10240           // 128*80
#define STG_B    20480
#define GEMM_SMEM  61440         // 3 stages
#define GATES_SMEM 67584         // epilogue stg 128*132*4

__device__ __forceinline__ void load_chunk(uint32_t stage_base,
    const __half* __restrict__ Ah, const __half* __restrict__ Bh,
    int m0, int n0, int kk, int K, int tid)
{
#pragma unroll
    for (int i = 0; i < 2; i++) {
        const int c = tid + i * 256;
        const int row = c >> 2;
        const int seg = c & 3;
        const uint32_t doff = (uint32_t)(row * 80 + seg * 16);
        const size_t akoff = (size_t)kk + seg * 8;
        CP_ASYNC16(stage_base + 0 * TILE_B + doff, Ah + (size_t)(m0 + row) * K + akoff);
        CP_ASYNC16(stage_base + 1 * TILE_B + doff, Bh + (size_t)(n0 + row) * K + akoff);
    }
}

#define GEMM_MAINLOOP(Ah, Bh, m0, n0, K, acc)                                     \
    {                                                                             \
        const int NC = (K) >> 5;                                                  \
        load_chunk(sb + 0 * STG_B, Ah, Bh, m0, n0, 0, K, tid);                    \
        CP_COMMIT();                                                              \
        load_chunk(sb + 1 * STG_B, Ah, Bh, m0, n0, 32, K, tid);                   \
        CP_COMMIT();                                                              \
        load_chunk(sb + 2 * STG_B, Ah, Bh, m0, n0, 64, K, tid);                   \
        CP_COMMIT();                                                              \
        int stage = 0;                                                            \
        for (int c = 0; c < NC; c++) {                                            \
            CP_WAIT2();                                                           \
            __syncthreads();                                                      \
            const uint32_t st = sb + stage * STG_B;                               \
            _Pragma("unroll")                                                     \
            for (int ks = 0; ks < 2; ks++) {                                      \
                const uint32_t kb = st + ks * 32;                                 \
                uint32_t af[4][4], bhf[4][2], t4[4];                              \
                _Pragma("unroll")                                                 \
                for (int nh = 0; nh < 2; nh++) {                                  \
                    ldmx4(t4, kb + 1 * TILE_B + b_off + nh * 1280);               \
                    bhf[2*nh][0] = t4[0]; bhf[2*nh][1] = t4[1];                   \
                    bhf[2*nh+1][0] = t4[2]; bhf[2*nh+1][1] = t4[3];               \
                }                                                                 \
                _Pragma("unroll")                                                 \
                for (int mf = 0; mf < 4; mf++) ldmx4(af[mf], kb + a_off + mf * 1280); \
                _Pragma("unroll")                                                 \
                for (int mf = 0; mf < 4; mf++)                                    \
                    _Pragma("unroll")                                             \
                    for (int nf = 0; nf < 4; nf++)                                \
                        mma_f16(acc[mf][nf], af[mf], bhf[nf]);                    \
            }                                                                     \
            __syncthreads();                                                      \
            if (c + 3 < NC)                                                       \
                load_chunk(st, Ah, Bh, m0, n0, (c + 3) << 5, K, tid);             \
            CP_COMMIT();                                                          \
            stage = (stage == 2) ? 0 : stage + 1;                                 \
        }                                                                         \
    }

// fp32-output GEMM (fc1/fc2)
__global__ __launch_bounds__(256, 2) void tcgemm(
    const __half* __restrict__ Ah, const __half* __restrict__ Bh,
    float* __restrict__ Cmat, const float* __restrict__ bias,
    int M, int N, int K)
{
    extern __shared__ __align__(128) char smem_raw[];
    const uint32_t sb = smem_u32(smem_raw);

    const int tid = threadIdx.x;
    const int lane = tid & 31;
    const int wid = tid >> 5;
    const int wm = wid >> 2;
    const int wn = wid & 3;
    const int m0 = blockIdx.y << 7;
    const int n0 = blockIdx.x << 7;

    const uint32_t a_off = (uint32_t)((wm * 64 + (lane & 15)) * 80 + (lane >> 4) * 16);
    const int bsub = lane >> 3;
    const uint32_t b_off = (uint32_t)((wn * 32 + ((bsub >> 1) << 3) + (lane & 7)) * 80 + (bsub & 1) * 16);

    float acc[4][4][4];
#pragma unroll
    for (int mf = 0; mf < 4; mf++)
#pragma unroll
        for (int nf = 0; nf < 4; nf++)
#pragma unroll
            for (int r = 0; r < 4; r++) acc[mf][nf][r] = 0.0f;

    GEMM_MAINLOOP(Ah, Bh, m0, n0, K, acc);

    const int qr = lane >> 2;
    const int qc = (lane & 3) << 1;
#pragma unroll
    for (int mf = 0; mf < 4; mf++) {
        const int row = m0 + wm * 64 + mf * 16 + qr;
#pragma unroll
        for (int nf = 0; nf < 4; nf++) {
            const int col = n0 + wn * 32 + nf * 8 + qc;
            const float2 bv = *(const float2*)(bias + col);
            float2 v0 = make_float2(acc[mf][nf][0] + bv.x, acc[mf][nf][1] + bv.y);
            float2 v1 = make_float2(acc[mf][nf][2] + bv.x, acc[mf][nf][3] + bv.y);
            *(float2*)(Cmat + (size_t)row * N + col) = v0;
            *(float2*)(Cmat + (size_t)(row + 8) * N + col) = v1;
        }
    }
}

// fp16-output GEMM (intra projection -> ZX)
__global__ __launch_bounds__(256, 2) void tcgemm_h(
    const __half* __restrict__ Ah, const __half* __restrict__ Bh,
    __half* __restrict__ Cmat, const float* __restrict__ bias,
    int M, int N, int K)
{
    extern __shared__ __align__(128) char smem_raw[];
    const uint32_t sb = smem_u32(smem_raw);

    const int tid = threadIdx.x;
    const int lane = tid & 31;
    const int wid = tid >> 5;
    const int wm = wid >> 2;
    const int wn = wid & 3;
    const int m0 = blockIdx.y << 7;
    const int n0 = blockIdx.x << 7;

    const uint32_t a_off = (uint32_t)((wm * 64 + (lane & 15)) * 80 + (lane >> 4) * 16);
    const int bsub = lane >> 3;
    const uint32_t b_off = (uint32_t)((wn * 32 + ((bsub >> 1) << 3) + (lane & 7)) * 80 + (bsub & 1) * 16);

    float acc[4][4][4];
#pragma unroll
    for (int mf = 0; mf < 4; mf++)
#pragma unroll
        for (int nf = 0; nf < 4; nf++)
#pragma unroll
            for (int r = 0; r < 4; r++) acc[mf][nf][r] = 0.0f;

    GEMM_MAINLOOP(Ah, Bh, m0, n0, K, acc);

    const int qr = lane >> 2;
    const int qc = (lane & 3) << 1;
#pragma unroll
    for (int mf = 0; mf < 4; mf++) {
        const int row = m0 + wm * 64 + mf * 16 + qr;
#pragma unroll
        for (int nf = 0; nf < 4; nf++) {
            const int col = n0 + wn * 32 + nf * 8 + qc;
            const float2 bv = *(const float2*)(bias + col);
            *(__half2*)(Cmat + (size_t)row * N + col) =
                __half2(__float2half_rn(acc[mf][nf][0] + bv.x),
                        __float2half_rn(acc[mf][nf][1] + bv.y));
            *(__half2*)(Cmat + (size_t)(row + 8) * N + col) =
                __half2(__float2half_rn(acc[mf][nf][2] + bv.x),
                        __float2half_rn(acc[mf][nf][3] + bv.y));
        }
    }
}

// ---- inter GEMM with fused LSTM gate epilogue (gate-interleaved B layout) ----
__global__ __launch_bounds__(256, 2) void tcgemm_gates(
    const __half* __restrict__ Ah, const __half* __restrict__ Bh,
    const float* __restrict__ biasP, const float* __restrict__ c0,
    float* __restrict__ h_out, float* __restrict__ c_out,
    __half* __restrict__ hh_out, int K)
{
    extern __shared__ __align__(128) char smem_raw[];
    const uint32_t sb = smem_u32(smem_raw);

    const int tid = threadIdx.x;
    const int lane = tid & 31;
    const int wid = tid >> 5;
    const int wm = wid >> 2;
    const int wn = wid & 3;
    const int m0 = blockIdx.y << 7;
    const int n0 = blockIdx.x << 7;
    const int hid0 = blockIdx.x << 5;

    const uint32_t a_off = (uint32_t)((wm * 64 + (lane & 15)) * 80 + (lane >> 4) * 16);
    const int bsub = lane >> 3;
    const uint32_t b_off = (uint32_t)((wn * 32 + ((bsub >> 1) << 3) + (lane & 7)) * 80 + (bsub & 1) * 16);

    float acc[4][4][4];
#pragma unroll
    for (int mf = 0; mf < 4; mf++)
#pragma unroll
        for (int nf = 0; nf < 4; nf++)
#pragma unroll
            for (int r = 0; r < 4; r++) acc[mf][nf][r] = 0.0f;

    GEMM_MAINLOOP(Ah, Bh, m0, n0, K, acc);

    __syncthreads();
    float* stg = (float*)smem_raw;    // 128 x 132
    const int qr = lane >> 2;
    const int qc = (lane & 3) << 1;
#pragma unroll
    for (int mf = 0; mf < 4; mf++) {
        const int rl = wm * 64 + mf * 16 + qr;
#pragma unroll
        for (int nf = 0; nf < 4; nf++) {
            const int col = wn * 32 + nf * 8 + qc;
            const float2 bv = *(const float2*)(biasP + n0 + col);
            stg[rl * 132 + col]           = acc[mf][nf][0] + bv.x;
            stg[rl * 132 + col + 1]       = acc[mf][nf][1] + bv.y;
            stg[(rl + 8) * 132 + col]     = acc[mf][nf][2] + bv.x;
            stg[(rl + 8) * 132 + col + 1] = acc[mf][nf][3] + bv.y;
        }
    }
    __syncthreads();

    {
        const int c = lane;
#pragma unroll
        for (int i = 0; i < 16; i++) {
            const int r = wid * 16 + i;
            const float zi = stg[r * 132 + c];
            const float zf = stg[r * 132 + 32 + c];
            const float zg = stg[r * 132 + 64 + c];
            const float zo = stg[r * 132 + 96 + c];
            const size_t go = (size_t)(m0 + r) * 512 + hid0 + c;
            const float cn = hsig(zf) * c0[go] + hsig(zi) * fast_tanh(zg);
            const float hv = hsig(zo) * fast_tanh(cn);
            c_out[go] = cn;
            h_out[go] = hv;
            hh_out[go] = __float2half_rn(hv);
        }
    }
}

// ================= convert kernels =================
__global__ __launch_bounds__(256) void cvt_kernel(
    const float* __restrict__ in, __half* __restrict__ out, int n4)
{
    const int i = blockIdx.x * blockDim.x + threadIdx.x;
    if (i >= n4) return;
    const float4 v = ((const float4*)in)[i];
    ((__half2*)out)[2 * i]     = __half2(__float2half_rn(v.x), __float2half_rn(v.y));
    ((__half2*)out)[2 * i + 1] = __half2(__float2half_rn(v.z), __float2half_rn(v.w));
}

// h0 [32768,512] -> g_Ah at row*1024 + 512 + col
__global__ __launch_bounds__(256) void cvt_off_kernel(
    const float* __restrict__ in, __half* __restrict__ out)
{
    const int q = blockIdx.x * blockDim.x + threadIdx.x;
    const int row = q >> 7;
    const int col = (q & 127) << 2;
    const float4 v = ((const float4*)in)[q];
    const size_t o = (size_t)row * 1024 + 512 + col;
    *(__half2*)(out + o)     = __half2(__float2half_rn(v.x), __float2half_rn(v.y));
    *(__half2*)(out + o + 2) = __half2(__float2half_rn(v.z), __float2half_rn(v.w));
}

// ---- unified weight/bias prep: blockIdx.z selects job ----
__device__ __forceinline__ void cvtT_tile(const float* __restrict__ Wm,
                                          __half* __restrict__ dst,
                                          int K, int N, int bx, int by,
                                          int tx, int ty)
{
    __shared__ float t[32][33];
    const int kb = by * 32, nb = bx * 32;
    for (int r = ty; r < 32; r += 8)
        t[r][tx] = Wm[(size_t)(kb + r) * N + nb + tx];
    __syncthreads();
    for (int r = ty; r < 32; r += 8)
        dst[(size_t)(nb + r) * K + kb + tx] = __float2half_rn(t[tx][r]);
}

__device__ __forceinline__ void cvtT_perm_tile(const float* __restrict__ Wm,
                                               __half* __restrict__ dst,
                                               int N, int Kout, int koff,
                                               int bx, int by, int tx, int ty)
{
    __shared__ float t[32][33];
    const int kb = by * 32, nb = bx * 32;
    for (int r = ty; r < 32; r += 8)
        t[r][tx] = Wm[(size_t)(kb + r) * N + nb + tx];
    __syncthreads();
    for (int r = ty; r < 32; r += 8) {
        const int n = nb + r;
        const int g = n >> 9, s = n & 511;
        const int nr = ((s >> 5) << 7) + (g << 5) + (s & 31);
        dst[(size_t)nr * Kout + koff + kb + tx] = __float2half_rn(t[tx][r]);
    }
}

__global__ void prep_all(
    const float* __restrict__ Wf, const float* __restrict__ Wb,
    const float* __restrict__ Uf, const float* __restrict__ Ub,
    const float* __restrict__ Wfc1, const float* __restrict__ Wfc2,
    const float* __restrict__ Wi, const float* __restrict__ Ui,
    const float* __restrict__ bf, const float* __restrict__ bb,
    const float* __restrict__ bi,
    __half* __restrict__ bt, __half* __restrict__ ut,
    float* __restrict__ bfc, float* __restrict__ biP)
{
    const int bx = blockIdx.x, by = blockIdx.y, job = blockIdx.z;
    const int tx = threadIdx.x, ty = threadIdx.y;
    switch (job) {
        case 0: if (bx < 32 && by < 16) cvtT_tile(Wf, bt, 512, 1024, bx, by, tx, ty); break;
        case 1: if (bx < 32 && by < 16) cvtT_tile(Wb, bt + (size_t)1024 * 512, 512, 1024, bx, by, tx, ty); break;
        case 2: if (bx < 32 && by < 8)  cvtT_tile(Uf, ut, 256, 1024, bx, by, tx, ty); break;
        case 3: if (bx < 32 && by < 8)  cvtT_tile(Ub, ut + 1024 * 256, 256, 1024, bx, by, tx, ty); break;
        case 4: if (bx < 16 && by < 16) cvtT_tile(Wfc1, bt + OFF_FC1, 512, 512, bx, by, tx, ty); break;
        case 5: if (bx < 16 && by < 16) cvtT_tile(Wfc2, bt + OFF_FC2, 512, 512, bx, by, tx, ty); break;
        case 6: if (bx < 64 && by < 16) cvtT_perm_tile(Wi, bt + OFF_INTER, 2048, 1024, 0, bx, by, tx, ty); break;
        case 7: if (bx < 64 && by < 16) cvtT_perm_tile(Ui, bt + OFF_INTER, 2048, 1024, 512, bx, by, tx, ty); break;
        case 8: {
            if (by == 0 && bx < 16) {
                const int i = bx * 256 + ty * 32 + tx;
                if (i < 1024) bfc[i] = bf[i];
                else if (i < 2048) bfc[i] = bb[i - 1024];
                else {
                    const int n = i - 2048;
                    const int g = n >> 9, s = n & 511;
                    const int nr = ((s >> 5) << 7) + (g << 5) + (s & 31);
                    biP[nr] = bi[n];
                }
            }
            break;
        }
    }
}

// ---------------- group barrier (16 CTAs per group; used pre-loop only) ----------------
__device__ __forceinline__ void group_barrier(int grp) {
    __threadfence();
    __syncthreads();
    if (threadIdx.x == 0) {
        unsigned long long* ctr = &g_barG[grp * 16];
        unsigned long long t = atomicAdd(ctr, 1ULL) + 1ULL;
        unsigned long long target = ((t + 15ULL) >> 4) << 4;
        while (ld_acquire(ctr) < target) { }
    }
    __syncthreads();
}

// ---------------- persistent bidirectional LSTM recurrence ----------------
// fp16, B(U) register-resident, register-resident gate update (no SMEM staging).
// CTA z-column order: col = hslice*32 + gate*8 + c8  (each warp owns all 4 gates
// of one 8-wide hidden slice -> update entirely in registers).
#define RA_STR   528
#define ROFF_BHI 33792
#define ROFF_ZX  67584           // 2 x 8KB fp16 zx buffers
#define RSMEM    83968

__global__ __launch_bounds__(256) void recurrence2(const __half* __restrict__ Ut)
{
    extern __shared__ __align__(128) char rsm[];
    const uint32_t sb = smem_u32(rsm);
    const int tid = threadIdx.x, lane = tid & 31, wid = tid >> 5;
    const int blk = blockIdx.x;
    const int tile_m = blk >> 4;
    const int tile_n = blk & 15;
    const int row0 = tile_m << 6;
    const int dir = (tile_m >= 4) ? 1 : 0;
    const int j0 = tile_n << 4;
    const int wm = wid & 3, wn = wid >> 2;   // wn = hidden slice (8 wide)
    unsigned long long* const ctr = &g_barG[tile_m * 16];

    // B resident: tile row q = hs*32 + g*8 + c8  <->  U^T row dir*1024 + g*256 + j0 + hs*8 + c8
    for (int i = tid; i < 2048; i += 256) {
        const int r = i >> 5, seg = i & 31;
        const int hs = r >> 5, w32 = r & 31;
        const int g = w32 >> 3, c = (hs << 3) + (w32 & 7);
        const size_t gr = ((size_t)(dir * 1024 + g * 256 + j0 + c)) * 256 + seg * 8;
        *(uint4*)(rsm + ROFF_BHI + r * RA_STR + seg * 16) = *(const uint4*)(Ut + gr);
    }

    if (tile_n == 0) {
        uint32_t* h0 = (uint32_t*)&g_Hh[0][row0 * 256];
        for (int i = tid; i < 8192; i += 256) h0[i] = 0u;
    }

    const uint32_t a_off = (uint32_t)((wm * 16 + (lane & 15)) * RA_STR + (lane >> 4) * 16);
    const int bsub = lane >> 3;
    const uint32_t b_off = (uint32_t)((wn * 32 + ((bsub >> 1) << 3) + (lane & 7)) * RA_STR + (bsub & 1) * 16);

    const int qr = lane >> 2;            // 0..7
    const int qc2 = (lane & 3) << 1;     // 0,2,4,6
    float creg[4] = {0.0f, 0.0f, 0.0f, 0.0f};

    // ---- prefetch zx(0) into buffer 0 (SMEM layout = z-column order) ----
    {
        const int w0 = dir ? 127 : 0;
#pragma unroll
        for (int ii = 0; ii < 2; ii++) {
            const int q = tid + ii * 256;
            const int r = q >> 3;
            const int m = q & 7;
            const int g = m & 3, hs = m >> 2;
            const __half* src = g_ZX + ((size_t)((row0 + r) & 255) * 128 + w0) * 2048
                               + dir * 1024 + g * 256 + j0 + hs * 8;
            CP_ASYNC16(sb + ROFF_ZX + (uint32_t)(r * 128 + hs * 64 + g * 16), src);
        }
    }
    CP_COMMIT();

    group_barrier(tile_m);

    // ---- cache ALL B (U) fragments in registers ----
    uint32_t breg[16][4][2];
#pragma unroll
    for (int ks = 0; ks < 16; ks++) {
        uint32_t t4[4];
        ldmx4(t4, sb + ROFF_BHI + b_off + ks * 32);
        breg[ks][0][0] = t4[0]; breg[ks][0][1] = t4[1];
        breg[ks][1][0] = t4[2]; breg[ks][1][1] = t4[3];
        ldmx4(t4, sb + ROFF_BHI + b_off + ks * 32 + 16 * RA_STR);
        breg[ks][2][0] = t4[0]; breg[ks][2][1] = t4[1];
        breg[ks][3][0] = t4[2]; breg[ks][3][1] = t4[3];
    }

    unsigned long long spin_target = 0;

    for (int t = 0; t < 128; t++) {
        const int pb = t & 1;
        const int w = dir ? (127 - t) : t;
        const __half* hh = g_Hh[pb];
        const __half* zxs = (const __half*)(rsm + ROFF_ZX + (t & 1) * 8192);

        // ---- commit group: H k 0..127 ----
#pragma unroll
        for (int ii = 0; ii < 4; ii++) {
            const int i = tid + ii * 256;
            const int r = i >> 4, seg = i & 15;
            CP_ASYNC16(sb + r * RA_STR + seg * 16, hh + (size_t)(row0 + r) * 256 + seg * 8);
        }
        CP_COMMIT();
        // ---- commit group: H k 128..255 ----
#pragma unroll
        for (int ii = 0; ii < 4; ii++) {
            const int i = tid + ii * 256;
            const int r = i >> 4, seg = 16 + (i & 15);
            CP_ASYNC16(sb + r * RA_STR + seg * 16, hh + (size_t)(row0 + r) * 256 + seg * 8);
        }
        CP_COMMIT();

        float acc[4][4];
#pragma unroll
        for (int nf = 0; nf < 4; nf++)
#pragma unroll
            for (int r = 0; r < 4; r++) acc[nf][r] = 0.0f;

        // wait: zx(t) + H first half done; H second half in flight
        CP_WAIT1();
        __syncthreads();
#pragma unroll
        for (int ks = 0; ks < 8; ks++) {
            uint32_t ah[4];
            ldmx4(ah, sb + a_off + ks * 32);
#pragma unroll
            for (int nf = 0; nf < 4; nf++)
                mma_f16(acc[nf], ah, breg[ks][nf]);
        }
        CP_WAIT0();
        __syncthreads();
#pragma unroll
        for (int ks = 8; ks < 16; ks++) {
            uint32_t ah[4];
            ldmx4(ah, sb + a_off + ks * 32);
#pragma unroll
            for (int nf = 0; nf < 4; nf++)
                mma_f16(acc[nf], ah, breg[ks][nf]);
        }

        // ---- register-resident gate update: acc[g][e] holds all 4 gates of this
        // thread's cells (rows qr,+8; cols qc2,+1 of hidden slice wn*8) ----
        __half2 hsv[2];
#pragma unroll
        for (int r = 0; r < 2; r++) {
            const int rloc = wm * 16 + qr + r * 8;
            const __half* zb = zxs + rloc * 64 + wn * 32 + qc2;
            const __half2 xi = *(const __half2*)(zb);
            const __half2 xf = *(const __half2*)(zb + 8);
            const __half2 xg = *(const __half2*)(zb + 16);
            const __half2 xo = *(const __half2*)(zb + 24);
            float hv0, hv1;
            {
                const int e = r * 2;
                const float zi = acc[0][e] + __half2float(xi.x);
                const float zf = acc[1][e] + __half2float(xf.x);
                const float zg = acc[2][e] + __half2float(xg.x);
                const float zo = acc[3][e] + __half2float(xo.x);
                const float cn = hsig(zf) * creg[e] + hsig(zi) * fast_tanh(zg);
                creg[e] = cn;
                hv0 = hsig(zo) * fast_tanh(cn);
            }
            {
                const int e = r * 2 + 1;
                const float zi = acc[0][e] + __half2float(xi.y);
                const float zf = acc[1][e] + __half2float(xf.y);
                const float zg = acc[2][e] + __half2float(xg.y);
                const float zo = acc[3][e] + __half2float(xo.y);
                const float cn = hsig(zf) * creg[e] + hsig(zi) * fast_tanh(zg);
                creg[e] = cn;
                hv1 = hsig(zo) * fast_tanh(cn);
            }
            hsv[r] = __half2(__float2half_rn(hv0), __float2half_rn(hv1));
            const int Rg = row0 + rloc;
            *(__half2*)(&g_Hh[pb ^ 1][(size_t)Rg * 256 + j0 + wn * 8 + qc2]) = hsv[r];
        }

        if (t < 127) {
            // arrive EARLY: H written; HS stores + zx prefetch ride under peer skew
            __threadfence();
            __syncthreads();
            if (tid == 0) {
                unsigned long long my = atomicAdd(ctr, 1ULL) + 1ULL;
                spin_target = ((my + 15ULL) >> 4) << 4;
            }
        }

        // HS output stores (off the cross-CTA critical path)
#pragma unroll
        for (int r = 0; r < 2; r++) {
            const int rloc = wm * 16 + qr + r * 8;
            const int Rg = row0 + rloc;
            const size_t hsoff = ((size_t)(Rg & 255) * 128 + w) * 512 + dir * 256
                               + j0 + wn * 8 + qc2;
            *(__half2*)(g_HSh + hsoff) = hsv[r];
        }

        if (t < 127) {
            // zx(t+1) prefetch into the other buffer
            const int wn1 = dir ? (127 - (t + 1)) : (t + 1);
            const uint32_t zdst = sb + ROFF_ZX + (uint32_t)(((t + 1) & 1) * 8192);
#pragma unroll
            for (int ii = 0; ii < 2; ii++) {
                const int q = tid + ii * 256;
                const int r = q >> 3;
                const int m = q & 7;
                const int g = m & 3, hs = m >> 2;
                const __half* src = g_ZX + ((size_t)((row0 + r) & 255) * 128 + wn1) * 2048
                                   + dir * 1024 + g * 256 + j0 + hs * 8;
                CP_ASYNC16(zdst + (uint32_t)(r * 128 + hs * 64 + g * 16), src);
            }
            CP_COMMIT();
            if (tid == 0) {
                while (ld_acquire(ctr) < spin_target) { }
            }
            __syncthreads();
        }
    }
}

// ---------------- LayerNorm over (W,C)=65536 (1024 threads), optional fused fp16 convert ----------------
__global__ __launch_bounds__(1024) void ln_kernel(
    const float* __restrict__ pre, const float* __restrict__ xres,
    const float* __restrict__ gamma, const float* __restrict__ beta,
    float* __restrict__ out, __half* __restrict__ sh, int mode)
{
    __shared__ float red[1024];
    const int tid = threadIdx.x;
    const size_t base = (size_t)blockIdx.x * 65536;

    float s = 0.0f, ss = 0.0f;
    for (int i = tid * 4; i < 65536; i += 4096) {
        float4 v = *(const float4*)(pre + base + i);
        s  += v.x + v.y + v.z + v.w;
        ss += v.x * v.x + v.y * v.y + v.z * v.z + v.w * v.w;
    }
    red[tid] = s; __syncthreads();
    for (int off = 512; off; off >>= 1) { if (tid < off) red[tid] += red[tid + off]; __syncthreads(); }
    const float mean = red[0] * (1.0f / 65536.0f);
    __syncthreads();
    red[tid] = ss; __syncthreads();
    for (int off = 512; off; off >>= 1) { if (tid < off) red[tid] += red[tid + off]; __syncthreads(); }
    const float var = red[0] * (1.0f / 65536.0f) - mean * mean;
    const float rstd = rsqrtf(var + 1e-3f);

    for (int i = tid * 4; i < 65536; i += 4096) {
        float4 v = *(const float4*)(pre + base + i);
        float4 g = *(const float4*)(gamma + i);
        float4 bb = *(const float4*)(beta + i);
        float4 r;
        r.x = (v.x - mean) * rstd * g.x + bb.x;
        r.y = (v.y - mean) * rstd * g.y + bb.y;
        r.z = (v.z - mean) * rstd * g.z + bb.z;
        r.w = (v.w - mean) * rstd * g.w + bb.w;
        if (mode == 0) {
            float4 xr = *(const float4*)(xres + base + i);
            r.x += xr.x; r.y += xr.y; r.z += xr.z; r.w += xr.w;
        } else {
            float4 o = *(const float4*)(out + base + i);
            r.x += o.x; r.y += o.y; r.z += o.z; r.w += o.w;
        }
        *(float4*)(out + base + i) = r;
        if (sh) {
            const size_t f = base + i;
            const size_t so = (f >> 9) * 1024 + (f & 511);
            *(__half2*)(sh + so)     = __half2(__float2half_rn(r.x), __float2half_rn(r.y));
            *(__half2*)(sh + so + 2) = __half2(__float2half_rn(r.z), __float2half_rn(r.w));
        }
    }
}

// ---------------- launch ----------------
extern "C" void kernel_launch(void* const* d_in, const int* in_sizes, int n_in,
                              void* d_out, int out_size)
{
    const float* x    = (const float*)d_in[0];
    const float* h0   = (const float*)d_in[1];
    const float* c0   = (const float*)d_in[2];
    const float* Wf   = (const float*)d_in[3];
    const float* Uf   = (const float*)d_in[4];
    const float* bf   = (const float*)d_in[5];
    const float* Wb   = (const float*)d_in[6];
    const float* Ub   = (const float*)d_in[7];
    const float* bb   = (const float*)d_in[8];
    const float* Wfc1 = (const float*)d_in[9];
    const float* bfc1 = (const float*)d_in[10];
    const float* g1   = (const float*)d_in[11];
    const float* b1   = (const float*)d_in[12];
    const float* Wi   = (const float*)d_in[13];
    const float* Ui   = (const float*)d_in[14];
    const float* bi   = (const float*)d_in[15];
    const float* Wfc2 = (const float*)d_in[16];
    const float* bfc2 = (const float*)d_in[17];
    const float* g2   = (const float*)d_in[18];
    const float* b2   = (const float*)d_in[19];

    float* out = (float*)d_out;
    float* h_out = out + OUT0;
    float* c_out = out + 2 * OUT0;
    const int full_out = (out_size >= (int)(3 * OUT0)) || out_size <= 0;

    float *fc, *bfc, *biP, *hcfb;
    __half *zx, *ah, *bt, *ut, *hsh;
    cudaGetSymbolAddress((void**)&zx,  g_ZX);
    cudaGetSymbolAddress((void**)&fc,  g_FC);
    cudaGetSymbolAddress((void**)&bfc, g_bfc);
    cudaGetSymbolAddress((void**)&biP, g_biP);
    cudaGetSymbolAddress((void**)&ah,  g_Ah);
    cudaGetSymbolAddress((void**)&bt,  g_Bt);
    cudaGetSymbolAddress((void**)&ut,  g_Ut);
    cudaGetSymbolAddress((void**)&hsh, g_HSh);
    cudaGetSymbolAddress((void**)&hcfb, g_HCfb);

    cudaFuncSetAttribute(tcgemm, cudaFuncAttributeMaxDynamicSharedMemorySize, GEMM_SMEM);
    cudaFuncSetAttribute(tcgemm_h, cudaFuncAttributeMaxDynamicSharedMemorySize, GEMM_SMEM);
    cudaFuncSetAttribute(tcgemm_gates, cudaFuncAttributeMaxDynamicSharedMemorySize, GATES_SMEM);
    cudaFuncSetAttribute(recurrence2, cudaFuncAttributeMaxDynamicSharedMemorySize, RSMEM);

    const int n4A = MROWS * 512 / 4;

    // ---- all weight/bias prep in ONE launch ----
    prep_all<<<dim3(64, 16, 9), dim3(32, 8)>>>(Wf, Wb, Uf, Ub, Wfc1, Wfc2, Wi, Ui,
                                               bf, bb, bi, bt, ut, bfc, biP);

    // ---- combined intra input projection: ZX(fp16) = x @ [Wf|Wb] + [bf|bb] ----
    cvt_kernel<<<n4A / 256, 256>>>(x, ah, n4A);
    tcgemm_h<<<dim3(16, 256), 256, GEMM_SMEM>>>(ah, bt, zx, bfc, MROWS, 2048, 512);

    // ---- recurrence ----
    recurrence2<<<128, 256, RSMEM>>>(ut);

    // ---- fc1 (A = HS) ----
    tcgemm<<<dim3(4, 256), 256, GEMM_SMEM>>>(hsh, bt + OFF_FC1, fc, bfc1, MROWS, 512, 512);

    // ---- LN1 + residual -> out, fused convert (concat A cols 0..511) ----
    ln_kernel<<<256, 1024>>>(fc, x, g1, b1, out, ah, 0);

    // ---- inter: single K=1024 GEMM with fused gates ----
    cvt_off_kernel<<<16384, 256>>>(h0, ah);
    float* hptr = full_out ? h_out : hcfb;
    float* cptr = full_out ? c_out : (hcfb + (size_t)MROWS * 512);
    tcgemm_gates<<<dim3(16, 256), 256, GATES_SMEM>>>(ah, bt + OFF_INTER, biP, c0,
                                                     hptr, cptr, hsh, 1024);

    // ---- fc2 (A = h in g_HSh) ----
    tcgemm<<<dim3(4, 256), 256, GEMM_SMEM>>>(hsh, bt + OFF_FC2, fc, bfc2, MROWS, 512, 512);

    // ---- LN2 accumulate into out ----
    ln_kernel<<<256, 1024>>>(fc, nullptr, g2, b2, out, nullptr, 1);
}

// round 14
// speedup vs baseline: 1.2815x; 1.0398x over previous
#include <cuda_runtime.h>
#include <cuda_fp16.h>
#include <cstdint>
#include <math.h>

// Problem constants
#define NSAMP 256            // B*L
#define W_    128
#define C_    512
#define HD_   256
#define MROWS 32768          // B*W
#define OUT0  ((size_t)16777216)   // B*L*W*C

// B-region offsets inside g_Bt (in halfs)
#define OFF_INTER 1048576          // 2048 rows x 1024 K
#define OFF_FC1   3145728          // 512 x 512
#define OFF_FC2   3407872          // 512 x 512

// ---------------- scratch (static device globals; no allocations) ----------------
__device__ __half g_ZX [(size_t)MROWS * 2048];  // combined intra projections, fp16
__device__ float g_FC [(size_t)MROWS * 512];
__device__ float g_bfc[2048];
__device__ float g_biP[2048];
__device__ unsigned long long g_barG[8 * 16];   // per-group monotonic tickets

// fp16 operand buffers
__device__ __half g_Ah [(size_t)MROWS * 1024];  // cols 0-511: x / intra_out; 512-1023: h0
__device__ __half g_Bt [(size_t)3670016];       // proj | inter | fc1 | fc2 regions
// recurrence state / weights / outputs (fp16)
__device__ __half g_Hh[2][512 * 256];
__device__ __half g_Ut[(size_t)2048 * 256];
__device__ __half g_HSh[(size_t)MROWS * 512];
// fallback h/c buffers when out buffer is small
__device__ float g_HCfb[2][(size_t)MROWS * 512];

__device__ __forceinline__ float hsig(float x) {
    return fminf(fmaxf(fmaf(0.2f, x, 0.5f), 0.0f), 1.0f);
}
__device__ __forceinline__ float fast_tanh(float x) {
    const float e = __expf(2.0f * x);
    return 1.0f - __fdividef(2.0f, e + 1.0f);
}

// ================= low-level helpers (sm_80-baseline ISA only) =================
__device__ __forceinline__ uint32_t smem_u32(const void* p) {
    uint32_t a;
    asm("{ .reg .u64 t; cvta.to.shared.u64 t, %1; cvt.u32.u64 %0, t; }" : "=r"(a) : "l"(p));
    return a;
}
#define CP_ASYNC16(dst, src) \
    asm volatile("cp.async.cg.shared.global [%0], [%1], 16;" :: "r"(dst), "l"(src) : "memory")
#define CP_COMMIT() asm volatile("cp.async.commit_group;" ::: "memory")
#define CP_WAIT2()  asm volatile("cp.async.wait_group 2;" ::: "memory")
#define CP_WAIT1()  asm volatile("cp.async.wait_group 1;" ::: "memory")
#define CP_WAIT0()  asm volatile("cp.async.wait_group 0;" ::: "memory")

__device__ __forceinline__ void ldmx4(uint32_t* r, uint32_t addr) {
    asm volatile("ldmatrix.sync.aligned.m8n8.x4.shared.b16 {%0,%1,%2,%3}, [%4];"
        : "=r"(r[0]), "=r"(r[1]), "=r"(r[2]), "=r"(r[3]) : "r"(addr));
}
__device__ __forceinline__ void mma_f16(float* d, const uint32_t* a, const uint32_t* b) {
    asm volatile("mma.sync.aligned.m16n8k16.row.col.f32.f16.f16.f32 "
        "{%0,%1,%2,%3}, {%4,%5,%6,%7}, {%8,%9}, {%0,%1,%2,%3};"
        : "+f"(d[0]), "+f"(d[1]), "+f"(d[2]), "+f"(d[3])
        : "r"(a[0]), "r"(a[1]), "r"(a[2]), "r"(a[3]), "r"(b[0]), "r"(b[1]));
}
__device__ __forceinline__ unsigned long long ld_acquire(const unsigned long long* p) {
    unsigned long long v;
    asm volatile("ld.acquire.gpu.u64 %0, [%1];" : "=l"(v) : "l"(p) : "memory");
    return v;
}

// ================= 128x128 fp16 GEMM: k64 chunks, 3-stage, 2 CTAs/SM =================
#define TILE_B   18432           // 128 rows * 144B (64 halfs + 16B pad)
#define STG_B    36864
#define GEMM_SMEM 110592         // 3 stages

__device__ __forceinline__ void load_chunk(uint32_t stage_base,
    const __half* __restrict__ Ah, const __half* __restrict__ Bh,
    int m0, int n0, int kk, int lda, int K, int tid)
{
#pragma unroll
    for (int i = 0; i < 4; i++) {
        const int c = tid + i * 256;
        const int row = c >> 3;
        const int seg = c & 7;
        const uint32_t doff = (uint32_t)(row * 144 + seg * 16);
        CP_ASYNC16(stage_base + doff, Ah + (size_t)(m0 + row) * lda + kk + seg * 8);
        CP_ASYNC16(stage_base + TILE_B + doff, Bh + (size_t)(n0 + row) * K + kk + seg * 8);
    }
}

#define GEMM_MAINLOOP(Ah, Bh, m0, n0, lda, K, acc)                                \
    {                                                                             \
        const int NC = (K) >> 6;                                                  \
        load_chunk(sb + 0 * STG_B, Ah, Bh, m0, n0, 0, lda, K, tid);               \
        CP_COMMIT();                                                              \
        load_chunk(sb + 1 * STG_B, Ah, Bh, m0, n0, 64, lda, K, tid);              \
        CP_COMMIT();                                                              \
        load_chunk(sb + 2 * STG_B, Ah, Bh, m0, n0, 128, lda, K, tid);             \
        CP_COMMIT();                                                              \
        int stage = 0;                                                            \
        for (int c = 0; c < NC; c++) {                                            \
            CP_WAIT2();                                                           \
            __syncthreads();                                                      \
            const uint32_t st = sb + stage * STG_B;                               \
            _Pragma("unroll")                                                     \
            for (int ks = 0; ks < 4; ks++) {                                      \
                const uint32_t kb = st + ks * 32;                                 \
                uint32_t af[4][4], bhf[4][2], t4[4];                              \
                _Pragma("unroll")                                                 \
                for (int nh = 0; nh < 2; nh++) {                                  \
                    ldmx4(t4, kb + TILE_B + b_off + nh * 16 * 144);               \
                    bhf[2*nh][0] = t4[0]; bhf[2*nh][1] = t4[1];                   \
                    bhf[2*nh+1][0] = t4[2]; bhf[2*nh+1][1] = t4[3];               \
                }                                                                 \
                _Pragma("unroll")                                                 \
                for (int mf = 0; mf < 4; mf++) ldmx4(af[mf], kb + a_off + mf * 16 * 144); \
                _Pragma("unroll")                                                 \
                for (int mf = 0; mf < 4; mf++)                                    \
                    _Pragma("unroll")                                             \
                    for (int nf = 0; nf < 4; nf++)                                \
                        mma_f16(acc[mf][nf], af[mf], bhf[nf]);                    \
            }                                                                     \
            __syncthreads();                                                      \
            if (c + 3 < NC)                                                       \
                load_chunk(st, Ah, Bh, m0, n0, (c + 3) << 6, lda, K, tid);        \
            CP_COMMIT();                                                          \
            stage = (stage == 2) ? 0 : stage + 1;                                 \
        }                                                                         \
    }

// fp32-output GEMM (fc1/fc2)
__global__ __launch_bounds__(256, 2) void tcgemm(
    const __half* __restrict__ Ah, const __half* __restrict__ Bh,
    float* __restrict__ Cmat, const float* __restrict__ bias,
    int M, int N, int K, int lda)
{
    extern __shared__ __align__(128) char smem_raw[];
    const uint32_t sb = smem_u32(smem_raw);

    const int tid = threadIdx.x;
    const int lane = tid & 31;
    const int wid = tid >> 5;
    const int wm = wid >> 2;
    const int wn = wid & 3;
    const int m0 = blockIdx.y << 7;
    const int n0 = blockIdx.x << 7;

    const uint32_t a_off = (uint32_t)((wm * 64 + (lane & 15)) * 144 + (lane >> 4) * 16);
    const int bsub = lane >> 3;
    const uint32_t b_off = (uint32_t)((wn * 32 + ((bsub >> 1) << 3) + (lane & 7)) * 144 + (bsub & 1) * 16);

    float acc[4][4][4];
#pragma unroll
    for (int mf = 0; mf < 4; mf++)
#pragma unroll
        for (int nf = 0; nf < 4; nf++)
#pragma unroll
            for (int r = 0; r < 4; r++) acc[mf][nf][r] = 0.0f;

    GEMM_MAINLOOP(Ah, Bh, m0, n0, lda, K, acc);

    const int qr = lane >> 2;
    const int qc = (lane & 3) << 1;
#pragma unroll
    for (int mf = 0; mf < 4; mf++) {
        const int row = m0 + wm * 64 + mf * 16 + qr;
#pragma unroll
        for (int nf = 0; nf < 4; nf++) {
            const int col = n0 + wn * 32 + nf * 8 + qc;
            const float2 bv = *(const float2*)(bias + col);
            float2 v0 = make_float2(acc[mf][nf][0] + bv.x, acc[mf][nf][1] + bv.y);
            float2 v1 = make_float2(acc[mf][nf][2] + bv.x, acc[mf][nf][3] + bv.y);
            *(float2*)(Cmat + (size_t)row * N + col) = v0;
            *(float2*)(Cmat + (size_t)(row + 8) * N + col) = v1;
        }
    }
}

// fp16-output GEMM (intra projection -> ZX)
__global__ __launch_bounds__(256, 2) void tcgemm_h(
    const __half* __restrict__ Ah, const __half* __restrict__ Bh,
    __half* __restrict__ Cmat, const float* __restrict__ bias,
    int M, int N, int K, int lda)
{
    extern __shared__ __align__(128) char smem_raw[];
    const uint32_t sb = smem_u32(smem_raw);

    const int tid = threadIdx.x;
    const int lane = tid & 31;
    const int wid = tid >> 5;
    const int wm = wid >> 2;
    const int wn = wid & 3;
    const int m0 = blockIdx.y << 7;
    const int n0 = blockIdx.x << 7;

    const uint32_t a_off = (uint32_t)((wm * 64 + (lane & 15)) * 144 + (lane >> 4) * 16);
    const int bsub = lane >> 3;
    const uint32_t b_off = (uint32_t)((wn * 32 + ((bsub >> 1) << 3) + (lane & 7)) * 144 + (bsub & 1) * 16);

    float acc[4][4][4];
#pragma unroll
    for (int mf = 0; mf < 4; mf++)
#pragma unroll
        for (int nf = 0; nf < 4; nf++)
#pragma unroll
            for (int r = 0; r < 4; r++) acc[mf][nf][r] = 0.0f;

    GEMM_MAINLOOP(Ah, Bh, m0, n0, lda, K, acc);

    const int qr = lane >> 2;
    const int qc = (lane & 3) << 1;
#pragma unroll
    for (int mf = 0; mf < 4; mf++) {
        const int row = m0 + wm * 64 + mf * 16 + qr;
#pragma unroll
        for (int nf = 0; nf < 4; nf++) {
            const int col = n0 + wn * 32 + nf * 8 + qc;
            const float2 bv = *(const float2*)(bias + col);
            *(__half2*)(Cmat + (size_t)row * N + col) =
                __half2(__float2half_rn(acc[mf][nf][0] + bv.x),
                        __float2half_rn(acc[mf][nf][1] + bv.y));
            *(__half2*)(Cmat + (size_t)(row + 8) * N + col) =
                __half2(__float2half_rn(acc[mf][nf][2] + bv.x),
                        __float2half_rn(acc[mf][nf][3] + bv.y));
        }
    }
}

// ---- inter GEMM with fused LSTM gate epilogue (gate-interleaved B layout) ----
__global__ __launch_bounds__(256, 2) void tcgemm_gates(
    const __half* __restrict__ Ah, const __half* __restrict__ Bh,
    const float* __restrict__ biasP, const float* __restrict__ c0,
    float* __restrict__ h_out, float* __restrict__ c_out,
    __half* __restrict__ hh_out, int K, int lda)
{
    extern __shared__ __align__(128) char smem_raw[];
    const uint32_t sb = smem_u32(smem_raw);

    const int tid = threadIdx.x;
    const int lane = tid & 31;
    const int wid = tid >> 5;
    const int wm = wid >> 2;
    const int wn = wid & 3;
    const int m0 = blockIdx.y << 7;
    const int n0 = blockIdx.x << 7;
    const int hid0 = blockIdx.x << 5;

    const uint32_t a_off = (uint32_t)((wm * 64 + (lane & 15)) * 144 + (lane >> 4) * 16);
    const int bsub = lane >> 3;
    const uint32_t b_off = (uint32_t)((wn * 32 + ((bsub >> 1) << 3) + (lane & 7)) * 144 + (bsub & 1) * 16);

    float acc[4][4][4];
#pragma unroll
    for (int mf = 0; mf < 4; mf++)
#pragma unroll
        for (int nf = 0; nf < 4; nf++)
#pragma unroll
            for (int r = 0; r < 4; r++) acc[mf][nf][r] = 0.0f;

    GEMM_MAINLOOP(Ah, Bh, m0, n0, lda, K, acc);

    __syncthreads();
    float* stg = (float*)smem_raw;    // 128 x 132
    const int qr = lane >> 2;
    const int qc = (lane & 3) << 1;
#pragma unroll
    for (int mf = 0; mf < 4; mf++) {
        const int rl = wm * 64 + mf * 16 + qr;
#pragma unroll
        for (int nf = 0; nf < 4; nf++) {
            const int col = wn * 32 + nf * 8 + qc;
            const float2 bv = *(const float2*)(biasP + n0 + col);
            stg[rl * 132 + col]           = acc[mf][nf][0] + bv.x;
            stg[rl * 132 + col + 1]       = acc[mf][nf][1] + bv.y;
            stg[(rl + 8) * 132 + col]     = acc[mf][nf][2] + bv.x;
            stg[(rl + 8) * 132 + col + 1] = acc[mf][nf][3] + bv.y;
        }
    }
    __syncthreads();

    {
        const int c = lane;
#pragma unroll
        for (int i = 0; i < 16; i++) {
            const int r = wid * 16 + i;
            const float zi = stg[r * 132 + c];
            const float zf = stg[r * 132 + 32 + c];
            const float zg = stg[r * 132 + 64 + c];
            const float zo = stg[r * 132 + 96 + c];
            const size_t go = (size_t)(m0 + r) * 512 + hid0 + c;
            const float cn = hsig(zf) * c0[go] + hsig(zi) * fast_tanh(zg);
            const float hv = hsig(zo) * fast_tanh(cn);
            c_out[go] = cn;
            h_out[go] = hv;
            hh_out[go] = __float2half_rn(hv);
        }
    }
}

// ---- unified prep: weight transposes + bias + x/h0 fp16 converts ----
__device__ __forceinline__ void cvtT_tile(const float* __restrict__ Wm,
                                          __half* __restrict__ dst,
                                          int K, int N, int bx, int by,
                                          int tx, int ty)
{
    __shared__ float t[32][33];
    const int kb = by * 32, nb = bx * 32;
    for (int r = ty; r < 32; r += 8)
        t[r][tx] = Wm[(size_t)(kb + r) * N + nb + tx];
    __syncthreads();
    for (int r = ty; r < 32; r += 8)
        dst[(size_t)(nb + r) * K + kb + tx] = __float2half_rn(t[tx][r]);
}

__device__ __forceinline__ void cvtT_perm_tile(const float* __restrict__ Wm,
                                               __half* __restrict__ dst,
                                               int N, int Kout, int koff,
                                               int bx, int by, int tx, int ty)
{
    __shared__ float t[32][33];
    const int kb = by * 32, nb = bx * 32;
    for (int r = ty; r < 32; r += 8)
        t[r][tx] = Wm[(size_t)(kb + r) * N + nb + tx];
    __syncthreads();
    for (int r = ty; r < 32; r += 8) {
        const int n = nb + r;
        const int g = n >> 9, s = n & 511;
        const int nr = ((s >> 5) << 7) + (g << 5) + (s & 31);
        dst[(size_t)nr * Kout + koff + kb + tx] = __float2half_rn(t[tx][r]);
    }
}

__global__ void prep_all(
    const float* __restrict__ Wf, const float* __restrict__ Wb,
    const float* __restrict__ Uf, const float* __restrict__ Ub,
    const float* __restrict__ Wfc1, const float* __restrict__ Wfc2,
    const float* __restrict__ Wi, const float* __restrict__ Ui,
    const float* __restrict__ bf, const float* __restrict__ bb,
    const float* __restrict__ bi,
    const float* __restrict__ x, const float* __restrict__ h0,
    __half* __restrict__ bt, __half* __restrict__ ut, __half* __restrict__ ah,
    float* __restrict__ bfc, float* __restrict__ biP)
{
    const int bx = blockIdx.x, by = blockIdx.y, job = blockIdx.z;
    const int tx = threadIdx.x, ty = threadIdx.y;
    const int tid8 = ty * 32 + tx;
    switch (job) {
        case 0: if (bx < 32 && by < 16) cvtT_tile(Wf, bt, 512, 1024, bx, by, tx, ty); break;
        case 1: if (bx < 32 && by < 16) cvtT_tile(Wb, bt + (size_t)1024 * 512, 512, 1024, bx, by, tx, ty); break;
        case 2: if (bx < 32 && by < 8)  cvtT_tile(Uf, ut, 256, 1024, bx, by, tx, ty); break;
        case 3: if (bx < 32 && by < 8)  cvtT_tile(Ub, ut + 1024 * 256, 256, 1024, bx, by, tx, ty); break;
        case 4: if (bx < 16 && by < 16) cvtT_tile(Wfc1, bt + OFF_FC1, 512, 512, bx, by, tx, ty); break;
        case 5: if (bx < 16 && by < 16) cvtT_tile(Wfc2, bt + OFF_FC2, 512, 512, bx, by, tx, ty); break;
        case 6: if (bx < 64 && by < 16) cvtT_perm_tile(Wi, bt + OFF_INTER, 2048, 1024, 0, bx, by, tx, ty); break;
        case 7: if (bx < 64 && by < 16) cvtT_perm_tile(Ui, bt + OFF_INTER, 2048, 1024, 512, bx, by, tx, ty); break;
        case 8: {
            if (by == 0 && bx < 16) {
                const int i = bx * 256 + tid8;
                if (i < 1024) bfc[i] = bf[i];
                else if (i < 2048) bfc[i] = bb[i - 1024];
                else {
                    const int n = i - 2048;
                    const int g = n >> 9, s = n & 511;
                    const int nr = ((s >> 5) << 7) + (g << 5) + (s & 31);
                    biP[nr] = bi[n];
                }
            }
            break;
        }
        case 9: {   // x -> Ah cols 0..511 (stride 1024)
            const int base_i = (by * 64 + bx) * 256 + tid8;
#pragma unroll
            for (int it = 0; it < 16; it++) {
                const int q = base_i + it * 262144;
                const float4 v = ((const float4*)x)[q];
                const int row = q >> 7;
                const int col = (q & 127) << 2;
                const size_t o = (size_t)row * 1024 + col;
                *(__half2*)(ah + o)     = __half2(__float2half_rn(v.x), __float2half_rn(v.y));
                *(__half2*)(ah + o + 2) = __half2(__float2half_rn(v.z), __float2half_rn(v.w));
            }
            break;
        }
        case 10: {  // h0 -> Ah cols 512..1023 (stride 1024)
            const int base_i = (by * 64 + bx) * 256 + tid8;
#pragma unroll
            for (int it = 0; it < 16; it++) {
                const int q = base_i + it * 262144;
                const float4 v = ((const float4*)h0)[q];
                const int row = q >> 7;
                const int col = (q & 127) << 2;
                const size_t o = (size_t)row * 1024 + 512 + col;
                *(__half2*)(ah + o)     = __half2(__float2half_rn(v.x), __float2half_rn(v.y));
                *(__half2*)(ah + o + 2) = __half2(__float2half_rn(v.z), __float2half_rn(v.w));
            }
            break;
        }
    }
}

// ---------------- group barrier (16 CTAs per group; used pre-loop only) ----------------
__device__ __forceinline__ void group_barrier(int grp) {
    __threadfence();
    __syncthreads();
    if (threadIdx.x == 0) {
        unsigned long long* ctr = &g_barG[grp * 16];
        unsigned long long t = atomicAdd(ctr, 1ULL) + 1ULL;
        unsigned long long target = ((t + 15ULL) >> 4) << 4;
        while (ld_acquire(ctr) < target) { }
    }
    __syncthreads();
}

// ---------------- persistent bidirectional LSTM recurrence ----------------
#define RA_STR   528
#define ROFF_BHI 33792
#define ROFF_ZX  67584           // 2 x 8KB fp16 zx buffers
#define RSMEM    83968

__global__ __launch_bounds__(256) void recurrence2(const __half* __restrict__ Ut)
{
    extern __shared__ __align__(128) char rsm[];
    const uint32_t sb = smem_u32(rsm);
    const int tid = threadIdx.x, lane = tid & 31, wid = tid >> 5;
    const int blk = blockIdx.x;
    const int tile_m = blk >> 4;
    const int tile_n = blk & 15;
    const int row0 = tile_m << 6;
    const int dir = (tile_m >= 4) ? 1 : 0;
    const int j0 = tile_n << 4;
    const int wm = wid & 3, wn = wid >> 2;
    unsigned long long* const ctr = &g_barG[tile_m * 16];

    for (int i = tid; i < 2048; i += 256) {
        const int r = i >> 5, seg = i & 31;
        const int hs = r >> 5, w32 = r & 31;
        const int g = w32 >> 3, c = (hs << 3) + (w32 & 7);
        const size_t gr = ((size_t)(dir * 1024 + g * 256 + j0 + c)) * 256 + seg * 8;
        *(uint4*)(rsm + ROFF_BHI + r * RA_STR + seg * 16) = *(const uint4*)(Ut + gr);
    }

    if (tile_n == 0) {
        uint32_t* h0p = (uint32_t*)&g_Hh[0][row0 * 256];
        for (int i = tid; i < 8192; i += 256) h0p[i] = 0u;
    }

    const uint32_t a_off = (uint32_t)((wm * 16 + (lane & 15)) * RA_STR + (lane >> 4) * 16);
    const int bsub = lane >> 3;
    const uint32_t b_off = (uint32_t)((wn * 32 + ((bsub >> 1) << 3) + (lane & 7)) * RA_STR + (bsub & 1) * 16);

    const int qr = lane >> 2;
    const int qc2 = (lane & 3) << 1;
    float creg[4] = {0.0f, 0.0f, 0.0f, 0.0f};

    {
        const int w0 = dir ? 127 : 0;
#pragma unroll
        for (int ii = 0; ii < 2; ii++) {
            const int q = tid + ii * 256;
            const int r = q >> 3;
            const int m = q & 7;
            const int g = m & 3, hs = m >> 2;
            const __half* src = g_ZX + ((size_t)((row0 + r) & 255) * 128 + w0) * 2048
                               + dir * 1024 + g * 256 + j0 + hs * 8;
            CP_ASYNC16(sb + ROFF_ZX + (uint32_t)(r * 128 + hs * 64 + g * 16), src);
        }
    }
    CP_COMMIT();

    group_barrier(tile_m);

    uint32_t breg[16][4][2];
#pragma unroll
    for (int ks = 0; ks < 16; ks++) {
        uint32_t t4[4];
        ldmx4(t4, sb + ROFF_BHI + b_off + ks * 32);
        breg[ks][0][0] = t4[0]; breg[ks][0][1] = t4[1];
        breg[ks][1][0] = t4[2]; breg[ks][1][1] = t4[3];
        ldmx4(t4, sb + ROFF_BHI + b_off + ks * 32 + 16 * RA_STR);
        breg[ks][2][0] = t4[0]; breg[ks][2][1] = t4[1];
        breg[ks][3][0] = t4[2]; breg[ks][3][1] = t4[3];
    }

    unsigned long long spin_target = 0;

    for (int t = 0; t < 128; t++) {
        const int pb = t & 1;
        const int w = dir ? (127 - t) : t;
        const __half* hh = g_Hh[pb];
        const __half* zxs = (const __half*)(rsm + ROFF_ZX + (t & 1) * 8192);

#pragma unroll
        for (int ii = 0; ii < 4; ii++) {
            const int i = tid + ii * 256;
            const int r = i >> 4, seg = i & 15;
            CP_ASYNC16(sb + r * RA_STR + seg * 16, hh + (size_t)(row0 + r) * 256 + seg * 8);
        }
        CP_COMMIT();
#pragma unroll
        for (int ii = 0; ii < 4; ii++) {
            const int i = tid + ii * 256;
            const int r = i >> 4, seg = 16 + (i & 15);
            CP_ASYNC16(sb + r * RA_STR + seg * 16, hh + (size_t)(row0 + r) * 256 + seg * 8);
        }
        CP_COMMIT();

        float acc[4][4];
#pragma unroll
        for (int nf = 0; nf < 4; nf++)
#pragma unroll
            for (int r = 0; r < 4; r++) acc[nf][r] = 0.0f;

        CP_WAIT1();
        __syncthreads();
#pragma unroll
        for (int ks = 0; ks < 8; ks++) {
            uint32_t ah4[4];
            ldmx4(ah4, sb + a_off + ks * 32);
#pragma unroll
            for (int nf = 0; nf < 4; nf++)
                mma_f16(acc[nf], ah4, breg[ks][nf]);
        }
        CP_WAIT0();
        __syncthreads();
#pragma unroll
        for (int ks = 8; ks < 16; ks++) {
            uint32_t ah4[4];
            ldmx4(ah4, sb + a_off + ks * 32);
#pragma unroll
            for (int nf = 0; nf < 4; nf++)
                mma_f16(acc[nf], ah4, breg[ks][nf]);
        }

        __half2 hsv[2];
#pragma unroll
        for (int r = 0; r < 2; r++) {
            const int rloc = wm * 16 + qr + r * 8;
            const __half* zb = zxs + rloc * 64 + wn * 32 + qc2;
            const __half2 xi = *(const __half2*)(zb);
            const __half2 xf = *(const __half2*)(zb + 8);
            const __half2 xg = *(const __half2*)(zb + 16);
            const __half2 xo = *(const __half2*)(zb + 24);
            float hv0, hv1;
            {
                const int e = r * 2;
                const float zi = acc[0][e] + __half2float(xi.x);
                const float zf = acc[1][e] + __half2float(xf.x);
                const float zg = acc[2][e] + __half2float(xg.x);
                const float zo = acc[3][e] + __half2float(xo.x);
                const float cn = hsig(zf) * creg[e] + hsig(zi) * fast_tanh(zg);
                creg[e] = cn;
                hv0 = hsig(zo) * fast_tanh(cn);
            }
            {
                const int e = r * 2 + 1;
                const float zi = acc[0][e] + __half2float(xi.y);
                const float zf = acc[1][e] + __half2float(xf.y);
                const float zg = acc[2][e] + __half2float(xg.y);
                const float zo = acc[3][e] + __half2float(xo.y);
                const float cn = hsig(zf) * creg[e] + hsig(zi) * fast_tanh(zg);
                creg[e] = cn;
                hv1 = hsig(zo) * fast_tanh(cn);
            }
            hsv[r] = __half2(__float2half_rn(hv0), __float2half_rn(hv1));
            const int Rg = row0 + rloc;
            *(__half2*)(&g_Hh[pb ^ 1][(size_t)Rg * 256 + j0 + wn * 8 + qc2]) = hsv[r];
        }

        if (t < 127) {
            __threadfence();
            __syncthreads();
            if (tid == 0) {
                unsigned long long my = atomicAdd(ctr, 1ULL) + 1ULL;
                spin_target = ((my + 15ULL) >> 4) << 4;
            }
        }

#pragma unroll
        for (int r = 0; r < 2; r++) {
            const int rloc = wm * 16 + qr + r * 8;
            const int Rg = row0 + rloc;
            const size_t hsoff = ((size_t)(Rg & 255) * 128 + w) * 512 + dir * 256
                               + j0 + wn * 8 + qc2;
            *(__half2*)(g_HSh + hsoff) = hsv[r];
        }

        if (t < 127) {
            const int wn1 = dir ? (127 - (t + 1)) : (t + 1);
            const uint32_t zdst = sb + ROFF_ZX + (uint32_t)(((t + 1) & 1) * 8192);
#pragma unroll
            for (int ii = 0; ii < 2; ii++) {
                const int q = tid + ii * 256;
                const int r = q >> 3;
                const int m = q & 7;
                const int g = m & 3, hs = m >> 2;
                const __half* src = g_ZX + ((size_t)((row0 + r) & 255) * 128 + wn1) * 2048
                                   + dir * 1024 + g * 256 + j0 + hs * 8;
                CP_ASYNC16(zdst + (uint32_t)(r * 128 + hs * 64 + g * 16), src);
            }
            CP_COMMIT();
            if (tid == 0) {
                while (ld_acquire(ctr) < spin_target) { }
            }
            __syncthreads();
        }
    }
}

// ---------------- LayerNorm over (W,C)=65536 (1024 threads), optional fused fp16 convert ----------------
__global__ __launch_bounds__(1024) void ln_kernel(
    const float* __restrict__ pre, const float* __restrict__ xres,
    const float* __restrict__ gamma, const float* __restrict__ beta,
    float* __restrict__ out, __half* __restrict__ sh, int mode)
{
    __shared__ float red[1024];
    const int tid = threadIdx.x;
    const size_t base = (size_t)blockIdx.x * 65536;

    float s = 0.0f, ss = 0.0f;
    for (int i = tid * 4; i < 65536; i += 4096) {
        float4 v = *(const float4*)(pre + base + i);
        s  += v.x + v.y + v.z + v.w;
        ss += v.x * v.x + v.y * v.y + v.z * v.z + v.w * v.w;
    }
    red[tid] = s; __syncthreads();
    for (int off = 512; off; off >>= 1) { if (tid < off) red[tid] += red[tid + off]; __syncthreads(); }
    const float mean = red[0] * (1.0f / 65536.0f);
    __syncthreads();
    red[tid] = ss; __syncthreads();
    for (int off = 512; off; off >>= 1) { if (tid < off) red[tid] += red[tid + off]; __syncthreads(); }
    const float var = red[0] * (1.0f / 65536.0f) - mean * mean;
    const float rstd = rsqrtf(var + 1e-3f);

    for (int i = tid * 4; i < 65536; i += 4096) {
        float4 v = *(const float4*)(pre + base + i);
        float4 g = *(const float4*)(gamma + i);
        float4 bb = *(const float4*)(beta + i);
        float4 r;
        r.x = (v.x - mean) * rstd * g.x + bb.x;
        r.y = (v.y - mean) * rstd * g.y + bb.y;
        r.z = (v.z - mean) * rstd * g.z + bb.z;
        r.w = (v.w - mean) * rstd * g.w + bb.w;
        if (mode == 0) {
            float4 xr = *(const float4*)(xres + base + i);
            r.x += xr.x; r.y += xr.y; r.z += xr.z; r.w += xr.w;
        } else {
            float4 o = *(const float4*)(out + base + i);
            r.x += o.x; r.y += o.y; r.z += o.z; r.w += o.w;
        }
        *(float4*)(out + base + i) = r;
        if (sh) {
            const size_t f = base + i;
            const size_t so = (f >> 9) * 1024 + (f & 511);
            *(__half2*)(sh + so)     = __half2(__float2half_rn(r.x), __float2half_rn(r.y));
            *(__half2*)(sh + so + 2) = __half2(__float2half_rn(r.z), __float2half_rn(r.w));
        }
    }
}

// ---------------- launch ----------------
extern "C" void kernel_launch(void* const* d_in, const int* in_sizes, int n_in,
                              void* d_out, int out_size)
{
    const float* x    = (const float*)d_in[0];
    const float* h0   = (const float*)d_in[1];
    const float* c0   = (const float*)d_in[2];
    const float* Wf   = (const float*)d_in[3];
    const float* Uf   = (const float*)d_in[4];
    const float* bf   = (const float*)d_in[5];
    const float* Wb   = (const float*)d_in[6];
    const float* Ub   = (const float*)d_in[7];
    const float* bb   = (const float*)d_in[8];
    const float* Wfc1 = (const float*)d_in[9];
    const float* bfc1 = (const float*)d_in[10];
    const float* g1   = (const float*)d_in[11];
    const float* b1   = (const float*)d_in[12];
    const float* Wi   = (const float*)d_in[13];
    const float* Ui   = (const float*)d_in[14];
    const float* bi   = (const float*)d_in[15];
    const float* Wfc2 = (const float*)d_in[16];
    const float* bfc2 = (const float*)d_in[17];
    const float* g2   = (const float*)d_in[18];
    const float* b2   = (const float*)d_in[19];

    float* out = (float*)d_out;
    float* h_out = out + OUT0;
    float* c_out = out + 2 * OUT0;
    const int full_out = (out_size >= (int)(3 * OUT0)) || out_size <= 0;

    float *fc, *bfc, *biP, *hcfb;
    __half *zx, *ah, *bt, *ut, *hsh;
    cudaGetSymbolAddress((void**)&zx,  g_ZX);
    cudaGetSymbolAddress((void**)&fc,  g_FC);
    cudaGetSymbolAddress((void**)&bfc, g_bfc);
    cudaGetSymbolAddress((void**)&biP, g_biP);
    cudaGetSymbolAddress((void**)&ah,  g_Ah);
    cudaGetSymbolAddress((void**)&bt,  g_Bt);
    cudaGetSymbolAddress((void**)&ut,  g_Ut);
    cudaGetSymbolAddress((void**)&hsh, g_HSh);
    cudaGetSymbolAddress((void**)&hcfb, g_HCfb);

    cudaFuncSetAttribute(tcgemm, cudaFuncAttributeMaxDynamicSharedMemorySize, GEMM_SMEM);
    cudaFuncSetAttribute(tcgemm_h, cudaFuncAttributeMaxDynamicSharedMemorySize, GEMM_SMEM);
    cudaFuncSetAttribute(tcgemm_gates, cudaFuncAttributeMaxDynamicSharedMemorySize, GEMM_SMEM);
    cudaFuncSetAttribute(recurrence2, cudaFuncAttributeMaxDynamicSharedMemorySize, RSMEM);

    // ---- all prep (weights, biases, x/h0 converts) in ONE launch ----
    prep_all<<<dim3(64, 16, 11), dim3(32, 8)>>>(Wf, Wb, Uf, Ub, Wfc1, Wfc2, Wi, Ui,
                                                bf, bb, bi, x, h0, bt, ut, ah, bfc, biP);

    // ---- combined intra input projection: ZX(fp16) = x @ [Wf|Wb] + [bf|bb] ----
    tcgemm_h<<<dim3(16, 256), 256, GEMM_SMEM>>>(ah, bt, zx, bfc, MROWS, 2048, 512, 1024);

    // ---- recurrence ----
    recurrence2<<<128, 256, RSMEM>>>(ut);

    // ---- fc1 (A = HS) ----
    tcgemm<<<dim3(4, 256), 256, GEMM_SMEM>>>(hsh, bt + OFF_FC1, fc, bfc1, MROWS, 512, 512, 512);

    // ---- LN1 + residual -> out, fused convert (Ah cols 0..511) ----
    ln_kernel<<<256, 1024>>>(fc, x, g1, b1, out, ah, 0);

    // ---- inter: single K=1024 GEMM with fused gates ----
    float* hptr = full_out ? h_out : hcfb;
    float* cptr = full_out ? c_out : (hcfb + (size_t)MROWS * 512);
    tcgemm_gates<<<dim3(16, 256), 256, GEMM_SMEM>>>(ah, bt + OFF_INTER, biP, c0,
                                                    hptr, cptr, hsh, 1024, 1024);

    // ---- fc2 (A = h in g_HSh) ----
    tcgemm<<<dim3(4, 256), 256, GEMM_SMEM>>>(hsh, bt + OFF_FC2, fc, bfc2, MROWS, 512, 512, 512);

    // ---- LN2 accumulate into out ----
    ln_kernel<<<256, 1024>>>(fc, nullptr, g2, b2, out, nullptr, 1);
}

// round 15
// speedup vs baseline: 1.3105x; 1.0226x over previous
#include <cuda_runtime.h>
#include <cuda_fp16.h>
#include <cstdint>
#include <math.h>

// Problem constants
#define NSAMP 256            // B*L
#define W_    128
#define C_    512
#define HD_   256
#define MROWS 32768          // B*W
#define OUT0  ((size_t)16777216)   // B*L*W*C

// B-region offsets inside g_Bt (in halfs)
#define OFF_INTER 1048576          // 2048 rows x 1024 K
#define OFF_FC1   3145728          // 512 x 512
#define OFF_FC2   3407872          // 512 x 512

// ---------------- scratch (static device globals; no allocations) ----------------
__device__ __half g_ZX [(size_t)MROWS * 2048];  // combined intra projections, fp16
__device__ float g_FC [(size_t)MROWS * 512];
__device__ float g_bfc[2048];
__device__ float g_biP[2048];
__device__ unsigned long long g_barG[8 * 16];   // per-group monotonic tickets

// fp16 operand buffers
__device__ __half g_Ah [(size_t)MROWS * 1024];  // cols 0-511: x / intra_out; 512-1023: h0
__device__ __half g_Bt [(size_t)3670016];       // proj | inter | fc1 | fc2 regions
// recurrence state / weights / outputs (fp16)
__device__ __half g_Hh[2][512 * 256];
__device__ __half g_Ut[(size_t)2048 * 256];
__device__ __half g_HSh[(size_t)MROWS * 512];
// fallback h/c buffers when out buffer is small
__device__ float g_HCfb[2][(size_t)MROWS * 512];

__device__ __forceinline__ float hsig(float x) {
    return fminf(fmaxf(fmaf(0.2f, x, 0.5f), 0.0f), 1.0f);
}
__device__ __forceinline__ float fast_tanh(float x) {
    const float e = __expf(2.0f * x);
    return 1.0f - __fdividef(2.0f, e + 1.0f);
}

// ================= low-level helpers (sm_80-baseline ISA only) =================
__device__ __forceinline__ uint32_t smem_u32(const void* p) {
    uint32_t a;
    asm("{ .reg .u64 t; cvta.to.shared.u64 t, %1; cvt.u32.u64 %0, t; }" : "=r"(a) : "l"(p));
    return a;
}
#define CP_ASYNC16(dst, src) \
    asm volatile("cp.async.cg.shared.global [%0], [%1], 16;" :: "r"(dst), "l"(src) : "memory")
#define CP_COMMIT() asm volatile("cp.async.commit_group;" ::: "memory")
#define CP_WAIT2()  asm volatile("cp.async.wait_group 2;" ::: "memory")
#define CP_WAIT1()  asm volatile("cp.async.wait_group 1;" ::: "memory")
#define CP_WAIT0()  asm volatile("cp.async.wait_group 0;" ::: "memory")

__device__ __forceinline__ void ldmx4(uint32_t* r, uint32_t addr) {
    asm volatile("ldmatrix.sync.aligned.m8n8.x4.shared.b16 {%0,%1,%2,%3}, [%4];"
        : "=r"(r[0]), "=r"(r[1]), "=r"(r[2]), "=r"(r[3]) : "r"(addr));
}
__device__ __forceinline__ void mma_f16(float* d, const uint32_t* a, const uint32_t* b) {
    asm volatile("mma.sync.aligned.m16n8k16.row.col.f32.f16.f16.f32 "
        "{%0,%1,%2,%3}, {%4,%5,%6,%7}, {%8,%9}, {%0,%1,%2,%3};"
        : "+f"(d[0]), "+f"(d[1]), "+f"(d[2]), "+f"(d[3])
        : "r"(a[0]), "r"(a[1]), "r"(a[2]), "r"(a[3]), "r"(b[0]), "r"(b[1]));
}
__device__ __forceinline__ unsigned long long ld_acquire(const unsigned long long* p) {
    unsigned long long v;
    asm volatile("ld.acquire.gpu.u64 %0, [%1];" : "=l"(v) : "l"(p) : "memory");
    return v;
}

// ================= 128x128 fp16 GEMM: k64 chunks, 3-stage, 2 CTAs/SM =================
#define TILE_B   18432           // 128 rows * 144B (64 halfs + 16B pad)
#define STG_B    36864
#define GEMM_SMEM 110592         // 3 stages

__device__ __forceinline__ void load_chunk(uint32_t stage_base,
    const __half* __restrict__ Ah, const __half* __restrict__ Bh,
    int m0, int n0, int kk, int lda, int K, int tid)
{
#pragma unroll
    for (int i = 0; i < 4; i++) {
        const int c = tid + i * 256;
        const int row = c >> 3;
        const int seg = c & 7;
        const uint32_t doff = (uint32_t)(row * 144 + seg * 16);
        CP_ASYNC16(stage_base + doff, Ah + (size_t)(m0 + row) * lda + kk + seg * 8);
        CP_ASYNC16(stage_base + TILE_B + doff, Bh + (size_t)(n0 + row) * K + kk + seg * 8);
    }
}

#define GEMM_MAINLOOP(Ah, Bh, m0, n0, lda, K, acc)                                \
    {                                                                             \
        const int NC = (K) >> 6;                                                  \
        load_chunk(sb + 0 * STG_B, Ah, Bh, m0, n0, 0, lda, K, tid);               \
        CP_COMMIT();                                                              \
        load_chunk(sb + 1 * STG_B, Ah, Bh, m0, n0, 64, lda, K, tid);              \
        CP_COMMIT();                                                              \
        load_chunk(sb + 2 * STG_B, Ah, Bh, m0, n0, 128, lda, K, tid);             \
        CP_COMMIT();                                                              \
        int stage = 0;                                                            \
        for (int c = 0; c < NC; c++) {                                            \
            CP_WAIT2();                                                           \
            __syncthreads();                                                      \
            const uint32_t st = sb + stage * STG_B;                               \
            _Pragma("unroll")                                                     \
            for (int ks = 0; ks < 4; ks++) {                                      \
                const uint32_t kb = st + ks * 32;                                 \
                uint32_t af[4][4], bhf[4][2], t4[4];                              \
                _Pragma("unroll")                                                 \
                for (int nh = 0; nh < 2; nh++) {                                  \
                    ldmx4(t4, kb + TILE_B + b_off + nh * 16 * 144);               \
                    bhf[2*nh][0] = t4[0]; bhf[2*nh][1] = t4[1];                   \
                    bhf[2*nh+1][0] = t4[2]; bhf[2*nh+1][1] = t4[3];               \
                }                                                                 \
                _Pragma("unroll")                                                 \
                for (int mf = 0; mf < 4; mf++) ldmx4(af[mf], kb + a_off + mf * 16 * 144); \
                _Pragma("unroll")                                                 \
                for (int mf = 0; mf < 4; mf++)                                    \
                    _Pragma("unroll")                                             \
                    for (int nf = 0; nf < 4; nf++)                                \
                        mma_f16(acc[mf][nf], af[mf], bhf[nf]);                    \
            }                                                                     \
            __syncthreads();                                                      \
            if (c + 3 < NC)                                                       \
                load_chunk(st, Ah, Bh, m0, n0, (c + 3) << 6, lda, K, tid);        \
            CP_COMMIT();                                                          \
            stage = (stage == 2) ? 0 : stage + 1;                                 \
        }                                                                         \
    }

// fp32-output GEMM (fc1/fc2)
__global__ __launch_bounds__(256, 2) void tcgemm(
    const __half* __restrict__ Ah, const __half* __restrict__ Bh,
    float* __restrict__ Cmat, const float* __restrict__ bias,
    int M, int N, int K, int lda)
{
    extern __shared__ __align__(128) char smem_raw[];
    const uint32_t sb = smem_u32(smem_raw);

    const int tid = threadIdx.x;
    const int lane = tid & 31;
    const int wid = tid >> 5;
    const int wm = wid >> 2;
    const int wn = wid & 3;
    const int m0 = blockIdx.y << 7;
    const int n0 = blockIdx.x << 7;

    const uint32_t a_off = (uint32_t)((wm * 64 + (lane & 15)) * 144 + (lane >> 4) * 16);
    const int bsub = lane >> 3;
    const uint32_t b_off = (uint32_t)((wn * 32 + ((bsub >> 1) << 3) + (lane & 7)) * 144 + (bsub & 1) * 16);

    float acc[4][4][4];
#pragma unroll
    for (int mf = 0; mf < 4; mf++)
#pragma unroll
        for (int nf = 0; nf < 4; nf++)
#pragma unroll
            for (int r = 0; r < 4; r++) acc[mf][nf][r] = 0.0f;

    GEMM_MAINLOOP(Ah, Bh, m0, n0, lda, K, acc);

    const int qr = lane >> 2;
    const int qc = (lane & 3) << 1;
#pragma unroll
    for (int mf = 0; mf < 4; mf++) {
        const int row = m0 + wm * 64 + mf * 16 + qr;
#pragma unroll
        for (int nf = 0; nf < 4; nf++) {
            const int col = n0 + wn * 32 + nf * 8 + qc;
            const float2 bv = *(const float2*)(bias + col);
            float2 v0 = make_float2(acc[mf][nf][0] + bv.x, acc[mf][nf][1] + bv.y);
            float2 v1 = make_float2(acc[mf][nf][2] + bv.x, acc[mf][nf][3] + bv.y);
            *(float2*)(Cmat + (size_t)row * N + col) = v0;
            *(float2*)(Cmat + (size_t)(row + 8) * N + col) = v1;
        }
    }
}

// fp16-output GEMM (intra projection -> ZX)
__global__ __launch_bounds__(256, 2) void tcgemm_h(
    const __half* __restrict__ Ah, const __half* __restrict__ Bh,
    __half* __restrict__ Cmat, const float* __restrict__ bias,
    int M, int N, int K, int lda)
{
    extern __shared__ __align__(128) char smem_raw[];
    const uint32_t sb = smem_u32(smem_raw);

    const int tid = threadIdx.x;
    const int lane = tid & 31;
    const int wid = tid >> 5;
    const int wm = wid >> 2;
    const int wn = wid & 3;
    const int m0 = blockIdx.y << 7;
    const int n0 = blockIdx.x << 7;

    const uint32_t a_off = (uint32_t)((wm * 64 + (lane & 15)) * 144 + (lane >> 4) * 16);
    const int bsub = lane >> 3;
    const uint32_t b_off = (uint32_t)((wn * 32 + ((bsub >> 1) << 3) + (lane & 7)) * 144 + (bsub & 1) * 16);

    float acc[4][4][4];
#pragma unroll
    for (int mf = 0; mf < 4; mf++)
#pragma unroll
        for (int nf = 0; nf < 4; nf++)
#pragma unroll
            for (int r = 0; r < 4; r++) acc[mf][nf][r] = 0.0f;

    GEMM_MAINLOOP(Ah, Bh, m0, n0, lda, K, acc);

    const int qr = lane >> 2;
    const int qc = (lane & 3) << 1;
#pragma unroll
    for (int mf = 0; mf < 4; mf++) {
        const int row = m0 + wm * 64 + mf * 16 + qr;
#pragma unroll
        for (int nf = 0; nf < 4; nf++) {
            const int col = n0 + wn * 32 + nf * 8 + qc;
            const float2 bv = *(const float2*)(bias + col);
            *(__half2*)(Cmat + (size_t)row * N + col) =
                __half2(__float2half_rn(acc[mf][nf][0] + bv.x),
                        __float2half_rn(acc[mf][nf][1] + bv.y));
            *(__half2*)(Cmat + (size_t)(row + 8) * N + col) =
                __half2(__float2half_rn(acc[mf][nf][2] + bv.x),
                        __float2half_rn(acc[mf][nf][3] + bv.y));
        }
    }
}

// ---- inter GEMM with fused LSTM gate epilogue (gate-interleaved B layout) ----
__global__ __launch_bounds__(256, 2) void tcgemm_gates(
    const __half* __restrict__ Ah, const __half* __restrict__ Bh,
    const float* __restrict__ biasP, const float* __restrict__ c0,
    float* __restrict__ h_out, float* __restrict__ c_out,
    __half* __restrict__ hh_out, int K, int lda)
{
    extern __shared__ __align__(128) char smem_raw[];
    const uint32_t sb = smem_u32(smem_raw);

    const int tid = threadIdx.x;
    const int lane = tid & 31;
    const int wid = tid >> 5;
    const int wm = wid >> 2;
    const int wn = wid & 3;
    const int m0 = blockIdx.y << 7;
    const int n0 = blockIdx.x << 7;
    const int hid0 = blockIdx.x << 5;

    const uint32_t a_off = (uint32_t)((wm * 64 + (lane & 15)) * 144 + (lane >> 4) * 16);
    const int bsub = lane >> 3;
    const uint32_t b_off = (uint32_t)((wn * 32 + ((bsub >> 1) << 3) + (lane & 7)) * 144 + (bsub & 1) * 16);

    float acc[4][4][4];
#pragma unroll
    for (int mf = 0; mf < 4; mf++)
#pragma unroll
        for (int nf = 0; nf < 4; nf++)
#pragma unroll
            for (int r = 0; r < 4; r++) acc[mf][nf][r] = 0.0f;

    GEMM_MAINLOOP(Ah, Bh, m0, n0, lda, K, acc);

    __syncthreads();
    float* stg = (float*)smem_raw;    // 128 x 132
    const int qr = lane >> 2;
    const int qc = (lane & 3) << 1;
#pragma unroll
    for (int mf = 0; mf < 4; mf++) {
        const int rl = wm * 64 + mf * 16 + qr;
#pragma unroll
        for (int nf = 0; nf < 4; nf++) {
            const int col = wn * 32 + nf * 8 + qc;
            const float2 bv = *(const float2*)(biasP + n0 + col);
            stg[rl * 132 + col]           = acc[mf][nf][0] + bv.x;
            stg[rl * 132 + col + 1]       = acc[mf][nf][1] + bv.y;
            stg[(rl + 8) * 132 + col]     = acc[mf][nf][2] + bv.x;
            stg[(rl + 8) * 132 + col + 1] = acc[mf][nf][3] + bv.y;
        }
    }
    __syncthreads();

    {
        const int c = lane;
#pragma unroll
        for (int i = 0; i < 16; i++) {
            const int r = wid * 16 + i;
            const float zi = stg[r * 132 + c];
            const float zf = stg[r * 132 + 32 + c];
            const float zg = stg[r * 132 + 64 + c];
            const float zo = stg[r * 132 + 96 + c];
            const size_t go = (size_t)(m0 + r) * 512 + hid0 + c;
            const float cn = hsig(zf) * c0[go] + hsig(zi) * fast_tanh(zg);
            const float hv = hsig(zo) * fast_tanh(cn);
            c_out[go] = cn;
            h_out[go] = hv;
            hh_out[go] = __float2half_rn(hv);
        }
    }
}

// ---- unified prep: weight transposes + bias + x/h0 fp16 converts ----
__device__ __forceinline__ void cvtT_tile(const float* __restrict__ Wm,
                                          __half* __restrict__ dst,
                                          int K, int N, int bx, int by,
                                          int tx, int ty)
{
    __shared__ float t[32][33];
    const int kb = by * 32, nb = bx * 32;
    for (int r = ty; r < 32; r += 8)
        t[r][tx] = Wm[(size_t)(kb + r) * N + nb + tx];
    __syncthreads();
    for (int r = ty; r < 32; r += 8)
        dst[(size_t)(nb + r) * K + kb + tx] = __float2half_rn(t[tx][r]);
}

__device__ __forceinline__ void cvtT_perm_tile(const float* __restrict__ Wm,
                                               __half* __restrict__ dst,
                                               int N, int Kout, int koff,
                                               int bx, int by, int tx, int ty)
{
    __shared__ float t[32][33];
    const int kb = by * 32, nb = bx * 32;
    for (int r = ty; r < 32; r += 8)
        t[r][tx] = Wm[(size_t)(kb + r) * N + nb + tx];
    __syncthreads();
    for (int r = ty; r < 32; r += 8) {
        const int n = nb + r;
        const int g = n >> 9, s = n & 511;
        const int nr = ((s >> 5) << 7) + (g << 5) + (s & 31);
        dst[(size_t)nr * Kout + koff + kb + tx] = __float2half_rn(t[tx][r]);
    }
}

__global__ void prep_all(
    const float* __restrict__ Wf, const float* __restrict__ Wb,
    const float* __restrict__ Uf, const float* __restrict__ Ub,
    const float* __restrict__ Wfc1, const float* __restrict__ Wfc2,
    const float* __restrict__ Wi, const float* __restrict__ Ui,
    const float* __restrict__ bf, const float* __restrict__ bb,
    const float* __restrict__ bi,
    const float* __restrict__ x, const float* __restrict__ h0,
    __half* __restrict__ bt, __half* __restrict__ ut, __half* __restrict__ ah,
    float* __restrict__ bfc, float* __restrict__ biP)
{
    const int bx = blockIdx.x, by = blockIdx.y, job = blockIdx.z;
    const int tx = threadIdx.x, ty = threadIdx.y;
    const int tid8 = ty * 32 + tx;
    switch (job) {
        case 0: if (bx < 32 && by < 16) cvtT_tile(Wf, bt, 512, 1024, bx, by, tx, ty); break;
        case 1: if (bx < 32 && by < 16) cvtT_tile(Wb, bt + (size_t)1024 * 512, 512, 1024, bx, by, tx, ty); break;
        case 2: if (bx < 32 && by < 8)  cvtT_tile(Uf, ut, 256, 1024, bx, by, tx, ty); break;
        case 3: if (bx < 32 && by < 8)  cvtT_tile(Ub, ut + 1024 * 256, 256, 1024, bx, by, tx, ty); break;
        case 4: if (bx < 16 && by < 16) cvtT_tile(Wfc1, bt + OFF_FC1, 512, 512, bx, by, tx, ty); break;
        case 5: if (bx < 16 && by < 16) cvtT_tile(Wfc2, bt + OFF_FC2, 512, 512, bx, by, tx, ty); break;
        case 6: if (bx < 64 && by < 16) cvtT_perm_tile(Wi, bt + OFF_INTER, 2048, 1024, 0, bx, by, tx, ty); break;
        case 7: if (bx < 64 && by < 16) cvtT_perm_tile(Ui, bt + OFF_INTER, 2048, 1024, 512, bx, by, tx, ty); break;
        case 8: {
            if (by == 0 && bx < 16) {
                const int i = bx * 256 + tid8;
                if (i < 1024) bfc[i] = bf[i];
                else if (i < 2048) bfc[i] = bb[i - 1024];
                else {
                    const int n = i - 2048;
                    const int g = n >> 9, s = n & 511;
                    const int nr = ((s >> 5) << 7) + (g << 5) + (s & 31);
                    biP[nr] = bi[n];
                }
            }
            break;
        }
        case 9: {   // x -> Ah cols 0..511 (stride 1024)
            const int base_i = (by * 64 + bx) * 256 + tid8;
#pragma unroll
            for (int it = 0; it < 16; it++) {
                const int q = base_i + it * 262144;
                const float4 v = ((const float4*)x)[q];
                const int row = q >> 7;
                const int col = (q & 127) << 2;
                const size_t o = (size_t)row * 1024 + col;
                *(__half2*)(ah + o)     = __half2(__float2half_rn(v.x), __float2half_rn(v.y));
                *(__half2*)(ah + o + 2) = __half2(__float2half_rn(v.z), __float2half_rn(v.w));
            }
            break;
        }
        case 10: {  // h0 -> Ah cols 512..1023 (stride 1024)
            const int base_i = (by * 64 + bx) * 256 + tid8;
#pragma unroll
            for (int it = 0; it < 16; it++) {
                const int q = base_i + it * 262144;
                const float4 v = ((const float4*)h0)[q];
                const int row = q >> 7;
                const int col = (q & 127) << 2;
                const size_t o = (size_t)row * 1024 + 512 + col;
                *(__half2*)(ah + o)     = __half2(__float2half_rn(v.x), __float2half_rn(v.y));
                *(__half2*)(ah + o + 2) = __half2(__float2half_rn(v.z), __float2half_rn(v.w));
            }
            break;
        }
    }
}

// ---------------- persistent bidirectional LSTM recurrence ----------------
// fp16, B(U) register-resident, register gate update, static-target barrier:
// arrive = fire-and-forget atomicAdd (no return use); all threads poll
// base + 16*(t+1) where base comes from the pre-loop barrier ticket.
#define RA_STR   528
#define ROFF_BHI 33792
#define ROFF_ZX  67584           // 2 x 8KB fp16 zx buffers
#define RSMEM    83968

__global__ __launch_bounds__(256) void recurrence2(const __half* __restrict__ Ut)
{
    extern __shared__ __align__(128) char rsm[];
    __shared__ unsigned long long s_base;
    const uint32_t sb = smem_u32(rsm);
    const int tid = threadIdx.x, lane = tid & 31, wid = tid >> 5;
    const int blk = blockIdx.x;
    const int tile_m = blk >> 4;
    const int tile_n = blk & 15;
    const int row0 = tile_m << 6;
    const int dir = (tile_m >= 4) ? 1 : 0;
    const int j0 = tile_n << 4;
    const int wm = wid & 3, wn = wid >> 2;
    unsigned long long* const ctr = &g_barG[tile_m * 16];

    // B resident: tile row q = hs*32 + g*8 + c8 <-> U^T row dir*1024 + g*256 + j0 + hs*8 + c8
    for (int i = tid; i < 2048; i += 256) {
        const int r = i >> 5, seg = i & 31;
        const int hs = r >> 5, w32 = r & 31;
        const int g = w32 >> 3, c = (hs << 3) + (w32 & 7);
        const size_t gr = ((size_t)(dir * 1024 + g * 256 + j0 + c)) * 256 + seg * 8;
        *(uint4*)(rsm + ROFF_BHI + r * RA_STR + seg * 16) = *(const uint4*)(Ut + gr);
    }

    if (tile_n == 0) {
        uint32_t* h0p = (uint32_t*)&g_Hh[0][row0 * 256];
        for (int i = tid; i < 8192; i += 256) h0p[i] = 0u;
    }

    const uint32_t a_off = (uint32_t)((wm * 16 + (lane & 15)) * RA_STR + (lane >> 4) * 16);
    const int bsub = lane >> 3;
    const uint32_t b_off = (uint32_t)((wn * 32 + ((bsub >> 1) << 3) + (lane & 7)) * RA_STR + (bsub & 1) * 16);

    const int qr = lane >> 2;
    const int qc2 = (lane & 3) << 1;
    float creg[4] = {0.0f, 0.0f, 0.0f, 0.0f};

    // ---- zx(0) prefetch (independent of peers) ----
    {
        const int w0 = dir ? 127 : 0;
#pragma unroll
        for (int ii = 0; ii < 2; ii++) {
            const int q = tid + ii * 256;
            const int r = q >> 3;
            const int m = q & 7;
            const int g = m & 3, hs = m >> 2;
            const __half* src = g_ZX + ((size_t)((row0 + r) & 255) * 128 + w0) * 2048
                               + dir * 1024 + g * 256 + j0 + hs * 8;
            CP_ASYNC16(sb + ROFF_ZX + (uint32_t)(r * 128 + hs * 64 + g * 16), src);
        }
    }
    CP_COMMIT();

    // B smem filled by own CTA -> local sync, then cache fragments in registers
    __syncthreads();
    uint32_t breg[16][4][2];
#pragma unroll
    for (int ks = 0; ks < 16; ks++) {
        uint32_t t4[4];
        ldmx4(t4, sb + ROFF_BHI + b_off + ks * 32);
        breg[ks][0][0] = t4[0]; breg[ks][0][1] = t4[1];
        breg[ks][1][0] = t4[2]; breg[ks][1][1] = t4[3];
        ldmx4(t4, sb + ROFF_BHI + b_off + ks * 32 + 16 * RA_STR);
        breg[ks][2][0] = t4[0]; breg[ks][2][1] = t4[1];
        breg[ks][3][0] = t4[2]; breg[ks][3][1] = t4[3];
    }

    // ---- pre-loop group barrier; its rounded ticket IS the step-target base ----
    __threadfence();
    __syncthreads();
    if (tid == 0) {
        unsigned long long t0 = atomicAdd(ctr, 1ULL) + 1ULL;
        unsigned long long target = ((t0 + 15ULL) >> 4) << 4;
        while (ld_acquire(ctr) < target) { }
        s_base = target;
    }
    __syncthreads();
    const unsigned long long base = s_base;

    for (int t = 0; t < 128; t++) {
        const int pb = t & 1;
        const int w = dir ? (127 - t) : t;
        const __half* hh = g_Hh[pb];
        const __half* zxs = (const __half*)(rsm + ROFF_ZX + (t & 1) * 8192);

#pragma unroll
        for (int ii = 0; ii < 4; ii++) {
            const int i = tid + ii * 256;
            const int r = i >> 4, seg = i & 15;
            CP_ASYNC16(sb + r * RA_STR + seg * 16, hh + (size_t)(row0 + r) * 256 + seg * 8);
        }
        CP_COMMIT();
#pragma unroll
        for (int ii = 0; ii < 4; ii++) {
            const int i = tid + ii * 256;
            const int r = i >> 4, seg = 16 + (i & 15);
            CP_ASYNC16(sb + r * RA_STR + seg * 16, hh + (size_t)(row0 + r) * 256 + seg * 8);
        }
        CP_COMMIT();

        float acc[4][4];
#pragma unroll
        for (int nf = 0; nf < 4; nf++)
#pragma unroll
            for (int r = 0; r < 4; r++) acc[nf][r] = 0.0f;

        CP_WAIT1();
        __syncthreads();
#pragma unroll
        for (int ks = 0; ks < 8; ks++) {
            uint32_t ah4[4];
            ldmx4(ah4, sb + a_off + ks * 32);
#pragma unroll
            for (int nf = 0; nf < 4; nf++)
                mma_f16(acc[nf], ah4, breg[ks][nf]);
        }
        CP_WAIT0();
        __syncthreads();
#pragma unroll
        for (int ks = 8; ks < 16; ks++) {
            uint32_t ah4[4];
            ldmx4(ah4, sb + a_off + ks * 32);
#pragma unroll
            for (int nf = 0; nf < 4; nf++)
                mma_f16(acc[nf], ah4, breg[ks][nf]);
        }

        // ---- register-resident gate update; store next-H first ----
        __half2 hsv[2];
#pragma unroll
        for (int r = 0; r < 2; r++) {
            const int rloc = wm * 16 + qr + r * 8;
            const __half* zb = zxs + rloc * 64 + wn * 32 + qc2;
            const __half2 xi = *(const __half2*)(zb);
            const __half2 xf = *(const __half2*)(zb + 8);
            const __half2 xg = *(const __half2*)(zb + 16);
            const __half2 xo = *(const __half2*)(zb + 24);
            float hv0, hv1;
            {
                const int e = r * 2;
                const float zi = acc[0][e] + __half2float(xi.x);
                const float zf = acc[1][e] + __half2float(xf.x);
                const float zg = acc[2][e] + __half2float(xg.x);
                const float zo = acc[3][e] + __half2float(xo.x);
                const float cn = hsig(zf) * creg[e] + hsig(zi) * fast_tanh(zg);
                creg[e] = cn;
                hv0 = hsig(zo) * fast_tanh(cn);
            }
            {
                const int e = r * 2 + 1;
                const float zi = acc[0][e] + __half2float(xi.y);
                const float zf = acc[1][e] + __half2float(xf.y);
                const float zg = acc[2][e] + __half2float(xg.y);
                const float zo = acc[3][e] + __half2float(xo.y);
                const float cn = hsig(zf) * creg[e] + hsig(zi) * fast_tanh(zg);
                creg[e] = cn;
                hv1 = hsig(zo) * fast_tanh(cn);
            }
            hsv[r] = __half2(__float2half_rn(hv0), __float2half_rn(hv1));
            const int Rg = row0 + rloc;
            *(__half2*)(&g_Hh[pb ^ 1][(size_t)Rg * 256 + j0 + wn * 8 + qc2]) = hsv[r];
        }

        if (t < 127) {
            // arrive: fence all H stores, then fire-and-forget increment
            __threadfence();
            __syncthreads();
            if (tid == 0) atomicAdd(ctr, 1ULL);   // return unused -> REDG
        }

        // HS output stores (off the cross-CTA critical path)
#pragma unroll
        for (int r = 0; r < 2; r++) {
            const int rloc = wm * 16 + qr + r * 8;
            const int Rg = row0 + rloc;
            const size_t hsoff = ((size_t)(Rg & 255) * 128 + w) * 512 + dir * 256
                               + j0 + wn * 8 + qc2;
            *(__half2*)(g_HSh + hsoff) = hsv[r];
        }

        if (t < 127) {
            // zx(t+1) prefetch into the other buffer
            const int wn1 = dir ? (127 - (t + 1)) : (t + 1);
            const uint32_t zdst = sb + ROFF_ZX + (uint32_t)(((t + 1) & 1) * 8192);
#pragma unroll
            for (int ii = 0; ii < 2; ii++) {
                const int q = tid + ii * 256;
                const int r = q >> 3;
                const int m = q & 7;
                const int g = m & 3, hs = m >> 2;
                const __half* src = g_ZX + ((size_t)((row0 + r) & 255) * 128 + wn1) * 2048
                                   + dir * 1024 + g * 256 + j0 + hs * 8;
                CP_ASYNC16(zdst + (uint32_t)(r * 128 + hs * 64 + g * 16), src);
            }
            CP_COMMIT();
            // static-target poll: every warp proceeds as soon as all 16 arrive
            const unsigned long long tgt = base + 16ULL * (unsigned long long)(t + 1);
            while (ld_acquire(ctr) < tgt) { }
        }
    }
}

// ---------------- LayerNorm over (W,C)=65536 (1024 threads), optional fused fp16 convert ----------------
__global__ __launch_bounds__(1024) void ln_kernel(
    const float* __restrict__ pre, const float* __restrict__ xres,
    const float* __restrict__ gamma, const float* __restrict__ beta,
    float* __restrict__ out, __half* __restrict__ sh, int mode)
{
    __shared__ float red[1024];
    const int tid = threadIdx.x;
    const size_t base = (size_t)blockIdx.x * 65536;

    float s = 0.0f, ss = 0.0f;
    for (int i = tid * 4; i < 65536; i += 4096) {
        float4 v = *(const float4*)(pre + base + i);
        s  += v.x + v.y + v.z + v.w;
        ss += v.x * v.x + v.y * v.y + v.z * v.z + v.w * v.w;
    }
    red[tid] = s; __syncthreads();
    for (int off = 512; off; off >>= 1) { if (tid < off) red[tid] += red[tid + off]; __syncthreads(); }
    const float mean = red[0] * (1.0f / 65536.0f);
    __syncthreads();
    red[tid] = ss; __syncthreads();
    for (int off = 512; off; off >>= 1) { if (tid < off) red[tid] += red[tid + off]; __syncthreads(); }
    const float var = red[0] * (1.0f / 65536.0f) - mean * mean;
    const float rstd = rsqrtf(var + 1e-3f);

    for (int i = tid * 4; i < 65536; i += 4096) {
        float4 v = *(const float4*)(pre + base + i);
        float4 g = *(const float4*)(gamma + i);
        float4 bb = *(const float4*)(beta + i);
        float4 r;
        r.x = (v.x - mean) * rstd * g.x + bb.x;
        r.y = (v.y - mean) * rstd * g.y + bb.y;
        r.z = (v.z - mean) * rstd * g.z + bb.z;
        r.w = (v.w - mean) * rstd * g.w + bb.w;
        if (mode == 0) {
            float4 xr = *(const float4*)(xres + base + i);
            r.x += xr.x; r.y += xr.y; r.z += xr.z; r.w += xr.w;
        } else {
            float4 o = *(const float4*)(out + base + i);
            r.x += o.x; r.y += o.y; r.z += o.z; r.w += o.w;
        }
        *(float4*)(out + base + i) = r;
        if (sh) {
            const size_t f = base + i;
            const size_t so = (f >> 9) * 1024 + (f & 511);
            *(__half2*)(sh + so)     = __half2(__float2half_rn(r.x), __float2half_rn(r.y));
            *(__half2*)(sh + so + 2) = __half2(__float2half_rn(r.z), __float2half_rn(r.w));
        }
    }
}

// ---------------- launch ----------------
extern "C" void kernel_launch(void* const* d_in, const int* in_sizes, int n_in,
                              void* d_out, int out_size)
{
    const float* x    = (const float*)d_in[0];
    const float* h0   = (const float*)d_in[1];
    const float* c0   = (const float*)d_in[2];
    const float* Wf   = (const float*)d_in[3];
    const float* Uf   = (const float*)d_in[4];
    const float* bf   = (const float*)d_in[5];
    const float* Wb   = (const float*)d_in[6];
    const float* Ub   = (const float*)d_in[7];
    const float* bb   = (const float*)d_in[8];
    const float* Wfc1 = (const float*)d_in[9];
    const float* bfc1 = (const float*)d_in[10];
    const float* g1   = (const float*)d_in[11];
    const float* b1   = (const float*)d_in[12];
    const float* Wi   = (const float*)d_in[13];
    const float* Ui   = (const float*)d_in[14];
    const float* bi   = (const float*)d_in[15];
    const float* Wfc2 = (const float*)d_in[16];
    const float* bfc2 = (const float*)d_in[17];
    const float* g2   = (const float*)d_in[18];
    const float* b2   = (const float*)d_in[19];

    float* out = (float*)d_out;
    float* h_out = out + OUT0;
    float* c_out = out + 2 * OUT0;
    const int full_out = (out_size >= (int)(3 * OUT0)) || out_size <= 0;

    float *fc, *bfc, *biP, *hcfb;
    __half *zx, *ah, *bt, *ut, *hsh;
    cudaGetSymbolAddress((void**)&zx,  g_ZX);
    cudaGetSymbolAddress((void**)&fc,  g_FC);
    cudaGetSymbolAddress((void**)&bfc, g_bfc);
    cudaGetSymbolAddress((void**)&biP, g_biP);
    cudaGetSymbolAddress((void**)&ah,  g_Ah);
    cudaGetSymbolAddress((void**)&bt,  g_Bt);
    cudaGetSymbolAddress((void**)&ut,  g_Ut);
    cudaGetSymbolAddress((void**)&hsh, g_HSh);
    cudaGetSymbolAddress((void**)&hcfb, g_HCfb);

    cudaFuncSetAttribute(tcgemm, cudaFuncAttributeMaxDynamicSharedMemorySize, GEMM_SMEM);
    cudaFuncSetAttribute(tcgemm_h, cudaFuncAttributeMaxDynamicSharedMemorySize, GEMM_SMEM);
    cudaFuncSetAttribute(tcgemm_gates, cudaFuncAttributeMaxDynamicSharedMemorySize, GEMM_SMEM);
    cudaFuncSetAttribute(recurrence2, cudaFuncAttributeMaxDynamicSharedMemorySize, RSMEM);

    // ---- all prep (weights, biases, x/h0 converts) in ONE launch ----
    prep_all<<<dim3(64, 16, 11), dim3(32, 8)>>>(Wf, Wb, Uf, Ub, Wfc1, Wfc2, Wi, Ui,
                                                bf, bb, bi, x, h0, bt, ut, ah, bfc, biP);

    // ---- combined intra input projection: ZX(fp16) = x @ [Wf|Wb] + [bf|bb] ----
    tcgemm_h<<<dim3(16, 256), 256, GEMM_SMEM>>>(ah, bt, zx, bfc, MROWS, 2048, 512, 1024);

    // ---- recurrence ----
    recurrence2<<<128, 256, RSMEM>>>(ut);

    // ---- fc1 (A = HS) ----
    tcgemm<<<dim3(4, 256), 256, GEMM_SMEM>>>(hsh, bt + OFF_FC1, fc, bfc1, MROWS, 512, 512, 512);

    // ---- LN1 + residual -> out, fused convert (Ah cols 0..511) ----
    ln_kernel<<<256, 1024>>>(fc, x, g1, b1, out, ah, 0);

    // ---- inter: single K=1024 GEMM with fused gates ----
    float* hptr = full_out ? h_out : hcfb;
    float* cptr = full_out ? c_out : (hcfb + (size_t)MROWS * 512);
    tcgemm_gates<<<dim3(16, 256), 256, GEMM_SMEM>>>(ah, bt + OFF_INTER, biP, c0,
                                                    hptr, cptr, hsh, 1024, 1024);

    // ---- fc2 (A = h in g_HSh) ----
    tcgemm<<<dim3(4, 256), 256, GEMM_SMEM>>>(hsh, bt + OFF_FC2, fc, bfc2, MROWS, 512, 512, 512);

    // ---- LN2 accumulate into out ----
    ln_kernel<<<256, 1024>>>(fc, nullptr, g2, b2, out, nullptr, 1);
}

// round 16
// speedup vs baseline: 1.3617x; 1.0391x over previous
#include <cuda_runtime.h>
#include <cuda_fp16.h>
#include <cstdint>
#include <math.h>

// Problem constants
#define NSAMP 256            // B*L
#define W_    128
#define C_    512
#define HD_   256
#define MROWS 32768          // B*W
#define OUT0  ((size_t)16777216)   // B*L*W*C

// B-region offsets inside g_Bt (in halfs)
#define OFF_INTER 1048576          // 2048 rows x 1024 K
#define OFF_FC1   3145728          // 512 x 512
#define OFF_FC2   3407872          // 512 x 512

// ---------------- scratch (static device globals; no allocations) ----------------
__device__ __half g_ZX [(size_t)MROWS * 2048];  // combined intra projections, fp16
__device__ float g_FC [(size_t)MROWS * 512];
__device__ float g_bfc[2048];
__device__ float g_biP[2048];
__device__ unsigned long long g_barG[8 * 16];   // per-group monotonic tickets (A at +0, B at +8)

// fp16 operand buffers
__device__ __half g_Ah [(size_t)MROWS * 1024];  // cols 0-511: x / intra_out; 512-1023: h0
__device__ __half g_Bt [(size_t)3670016];       // proj | inter | fc1 | fc2 regions
// recurrence state / weights / outputs (fp16)
__device__ __half g_Hh[2][512 * 256];
__device__ __half g_Ut[(size_t)2048 * 256];
__device__ __half g_HSh[(size_t)MROWS * 512];
// fallback h/c buffers when out buffer is small
__device__ float g_HCfb[2][(size_t)MROWS * 512];

__device__ __forceinline__ float hsig(float x) {
    return fminf(fmaxf(fmaf(0.2f, x, 0.5f), 0.0f), 1.0f);
}
__device__ __forceinline__ float fast_tanh(float x) {
    const float e = __expf(2.0f * x);
    return 1.0f - __fdividef(2.0f, e + 1.0f);
}

// ================= low-level helpers (sm_80-baseline ISA only) =================
__device__ __forceinline__ uint32_t smem_u32(const void* p) {
    uint32_t a;
    asm("{ .reg .u64 t; cvta.to.shared.u64 t, %1; cvt.u32.u64 %0, t; }" : "=r"(a) : "l"(p));
    return a;
}
#define CP_ASYNC16(dst, src) \
    asm volatile("cp.async.cg.shared.global [%0], [%1], 16;" :: "r"(dst), "l"(src) : "memory")
#define CP_COMMIT() asm volatile("cp.async.commit_group;" ::: "memory")
#define CP_WAIT2()  asm volatile("cp.async.wait_group 2;" ::: "memory")
#define CP_WAIT1()  asm volatile("cp.async.wait_group 1;" ::: "memory")
#define CP_WAIT0()  asm volatile("cp.async.wait_group 0;" ::: "memory")

__device__ __forceinline__ void ldmx4(uint32_t* r, uint32_t addr) {
    asm volatile("ldmatrix.sync.aligned.m8n8.x4.shared.b16 {%0,%1,%2,%3}, [%4];"
        : "=r"(r[0]), "=r"(r[1]), "=r"(r[2]), "=r"(r[3]) : "r"(addr));
}
__device__ __forceinline__ void mma_f16(float* d, const uint32_t* a, const uint32_t* b) {
    asm volatile("mma.sync.aligned.m16n8k16.row.col.f32.f16.f16.f32 "
        "{%0,%1,%2,%3}, {%4,%5,%6,%7}, {%8,%9}, {%0,%1,%2,%3};"
        : "+f"(d[0]), "+f"(d[1]), "+f"(d[2]), "+f"(d[3])
        : "r"(a[0]), "r"(a[1]), "r"(a[2]), "r"(a[3]), "r"(b[0]), "r"(b[1]));
}
__device__ __forceinline__ unsigned long long ld_acquire(const unsigned long long* p) {
    unsigned long long v;
    asm volatile("ld.acquire.gpu.u64 %0, [%1];" : "=l"(v) : "l"(p) : "memory");
    return v;
}
__device__ __forceinline__ unsigned long long atom_release_add(unsigned long long* p) {
    unsigned long long v;
    asm volatile("atom.release.gpu.global.add.u64 %0, [%1], %2;"
        : "=l"(v) : "l"(p), "l"(1ULL) : "memory");
    return v;
}
__device__ __forceinline__ void red_release_add(unsigned long long* p) {
    asm volatile("red.release.gpu.global.add.u64 [%0], %1;" :: "l"(p), "l"(1ULL) : "memory");
}

// ================= 128x128 fp16 GEMM: k64 chunks, 3-stage, 2 CTAs/SM =================
#define TILE_B   18432           // 128 rows * 144B (64 halfs + 16B pad)
#define STG_B    36864
#define GEMM_SMEM 110592         // 3 stages

__device__ __forceinline__ void load_chunk(uint32_t stage_base,
    const __half* __restrict__ Ah, const __half* __restrict__ Bh,
    int m0, int n0, int kk, int lda, int K, int tid)
{
#pragma unroll
    for (int i = 0; i < 4; i++) {
        const int c = tid + i * 256;
        const int row = c >> 3;
        const int seg = c & 7;
        const uint32_t doff = (uint32_t)(row * 144 + seg * 16);
        CP_ASYNC16(stage_base + doff, Ah + (size_t)(m0 + row) * lda + kk + seg * 8);
        CP_ASYNC16(stage_base + TILE_B + doff, Bh + (size_t)(n0 + row) * K + kk + seg * 8);
    }
}

#define GEMM_MAINLOOP(Ah, Bh, m0, n0, lda, K, acc)                                \
    {                                                                             \
        const int NC = (K) >> 6;                                                  \
        load_chunk(sb + 0 * STG_B, Ah, Bh, m0, n0, 0, lda, K, tid);               \
        CP_COMMIT();                                                              \
        load_chunk(sb + 1 * STG_B, Ah, Bh, m0, n0, 64, lda, K, tid);              \
        CP_COMMIT();                                                              \
        load_chunk(sb + 2 * STG_B, Ah, Bh, m0, n0, 128, lda, K, tid);             \
        CP_COMMIT();                                                              \
        int stage = 0;                                                            \
        for (int c = 0; c < NC; c++) {                                            \
            CP_WAIT2();                                                           \
            __syncthreads();                                                      \
            const uint32_t st = sb + stage * STG_B;                               \
            _Pragma("unroll")                                                     \
            for (int ks = 0; ks < 4; ks++) {                                      \
                const uint32_t kb = st + ks * 32;                                 \
                uint32_t af[4][4], bhf[4][2], t4[4];                              \
                _Pragma("unroll")                                                 \
                for (int nh = 0; nh < 2; nh++) {                                  \
                    ldmx4(t4, kb + TILE_B + b_off + nh * 16 * 144);               \
                    bhf[2*nh][0] = t4[0]; bhf[2*nh][1] = t4[1];                   \
                    bhf[2*nh+1][0] = t4[2]; bhf[2*nh+1][1] = t4[3];               \
                }                                                                 \
                _Pragma("unroll")                                                 \
                for (int mf = 0; mf < 4; mf++) ldmx4(af[mf], kb + a_off + mf * 16 * 144); \
                _Pragma("unroll")                                                 \
                for (int mf = 0; mf < 4; mf++)                                    \
                    _Pragma("unroll")                                             \
                    for (int nf = 0; nf < 4; nf++)                                \
                        mma_f16(acc[mf][nf], af[mf], bhf[nf]);                    \
            }                                                                     \
            __syncthreads();                                                      \
            if (c + 3 < NC)                                                       \
                load_chunk(st, Ah, Bh, m0, n0, (c + 3) << 6, lda, K, tid);        \
            CP_COMMIT();                                                          \
            stage = (stage == 2) ? 0 : stage + 1;                                 \
        }                                                                         \
    }

// fp32-output GEMM (fc1/fc2)
__global__ __launch_bounds__(256, 2) void tcgemm(
    const __half* __restrict__ Ah, const __half* __restrict__ Bh,
    float* __restrict__ Cmat, const float* __restrict__ bias,
    int M, int N, int K, int lda)
{
    extern __shared__ __align__(128) char smem_raw[];
    const uint32_t sb = smem_u32(smem_raw);

    const int tid = threadIdx.x;
    const int lane = tid & 31;
    const int wid = tid >> 5;
    const int wm = wid >> 2;
    const int wn = wid & 3;
    const int m0 = blockIdx.y << 7;
    const int n0 = blockIdx.x << 7;

    const uint32_t a_off = (uint32_t)((wm * 64 + (lane & 15)) * 144 + (lane >> 4) * 16);
    const int bsub = lane >> 3;
    const uint32_t b_off = (uint32_t)((wn * 32 + ((bsub >> 1) << 3) + (lane & 7)) * 144 + (bsub & 1) * 16);

    float acc[4][4][4];
#pragma unroll
    for (int mf = 0; mf < 4; mf++)
#pragma unroll
        for (int nf = 0; nf < 4; nf++)
#pragma unroll
            for (int r = 0; r < 4; r++) acc[mf][nf][r] = 0.0f;

    GEMM_MAINLOOP(Ah, Bh, m0, n0, lda, K, acc);

    const int qr = lane >> 2;
    const int qc = (lane & 3) << 1;
#pragma unroll
    for (int mf = 0; mf < 4; mf++) {
        const int row = m0 + wm * 64 + mf * 16 + qr;
#pragma unroll
        for (int nf = 0; nf < 4; nf++) {
            const int col = n0 + wn * 32 + nf * 8 + qc;
            const float2 bv = *(const float2*)(bias + col);
            float2 v0 = make_float2(acc[mf][nf][0] + bv.x, acc[mf][nf][1] + bv.y);
            float2 v1 = make_float2(acc[mf][nf][2] + bv.x, acc[mf][nf][3] + bv.y);
            *(float2*)(Cmat + (size_t)row * N + col) = v0;
            *(float2*)(Cmat + (size_t)(row + 8) * N + col) = v1;
        }
    }
}

// fp16-output GEMM (intra projection -> ZX)
__global__ __launch_bounds__(256, 2) void tcgemm_h(
    const __half* __restrict__ Ah, const __half* __restrict__ Bh,
    __half* __restrict__ Cmat, const float* __restrict__ bias,
    int M, int N, int K, int lda)
{
    extern __shared__ __align__(128) char smem_raw[];
    const uint32_t sb = smem_u32(smem_raw);

    const int tid = threadIdx.x;
    const int lane = tid & 31;
    const int wid = tid >> 5;
    const int wm = wid >> 2;
    const int wn = wid & 3;
    const int m0 = blockIdx.y << 7;
    const int n0 = blockIdx.x << 7;

    const uint32_t a_off = (uint32_t)((wm * 64 + (lane & 15)) * 144 + (lane >> 4) * 16);
    const int bsub = lane >> 3;
    const uint32_t b_off = (uint32_t)((wn * 32 + ((bsub >> 1) << 3) + (lane & 7)) * 144 + (bsub & 1) * 16);

    float acc[4][4][4];
#pragma unroll
    for (int mf = 0; mf < 4; mf++)
#pragma unroll
        for (int nf = 0; nf < 4; nf++)
#pragma unroll
            for (int r = 0; r < 4; r++) acc[mf][nf][r] = 0.0f;

    GEMM_MAINLOOP(Ah, Bh, m0, n0, lda, K, acc);

    const int qr = lane >> 2;
    const int qc = (lane & 3) << 1;
#pragma unroll
    for (int mf = 0; mf < 4; mf++) {
        const int row = m0 + wm * 64 + mf * 16 + qr;
#pragma unroll
        for (int nf = 0; nf < 4; nf++) {
            const int col = n0 + wn * 32 + nf * 8 + qc;
            const float2 bv = *(const float2*)(bias + col);
            *(__half2*)(Cmat + (size_t)row * N + col) =
                __half2(__float2half_rn(acc[mf][nf][0] + bv.x),
                        __float2half_rn(acc[mf][nf][1] + bv.y));
            *(__half2*)(Cmat + (size_t)(row + 8) * N + col) =
                __half2(__float2half_rn(acc[mf][nf][2] + bv.x),
                        __float2half_rn(acc[mf][nf][3] + bv.y));
        }
    }
}

// ---- inter GEMM with register-resident LSTM gate epilogue ----
// B permuted so tile col = hs8*32 + gate*8 + c8: each warp owns all 4 gates of
// one 8-wide hidden slice -> update entirely in registers (no SMEM staging).
__global__ __launch_bounds__(256, 2) void tcgemm_gates(
    const __half* __restrict__ Ah, const __half* __restrict__ Bh,
    const float* __restrict__ biasP, const float* __restrict__ c0,
    float* __restrict__ h_out, float* __restrict__ c_out,
    __half* __restrict__ hh_out, int K, int lda)
{
    extern __shared__ __align__(128) char smem_raw[];
    const uint32_t sb = smem_u32(smem_raw);

    const int tid = threadIdx.x;
    const int lane = tid & 31;
    const int wid = tid >> 5;
    const int wm = wid >> 2;
    const int wn = wid & 3;
    const int m0 = blockIdx.y << 7;
    const int n0 = blockIdx.x << 7;
    const int hid0 = blockIdx.x << 5;

    const uint32_t a_off = (uint32_t)((wm * 64 + (lane & 15)) * 144 + (lane >> 4) * 16);
    const int bsub = lane >> 3;
    const uint32_t b_off = (uint32_t)((wn * 32 + ((bsub >> 1) << 3) + (lane & 7)) * 144 + (bsub & 1) * 16);

    float acc[4][4][4];
#pragma unroll
    for (int mf = 0; mf < 4; mf++)
#pragma unroll
        for (int nf = 0; nf < 4; nf++)
#pragma unroll
            for (int r = 0; r < 4; r++) acc[mf][nf][r] = 0.0f;

    GEMM_MAINLOOP(Ah, Bh, m0, n0, lda, K, acc);

    // register gate update: gate = nf, hidden local = wn*8 + qc + e01
    const int qr = lane >> 2;
    const int qc = (lane & 3) << 1;
    float2 bv[4];
#pragma unroll
    for (int g = 0; g < 4; g++)
        bv[g] = *(const float2*)(biasP + n0 + wn * 32 + g * 8 + qc);

#pragma unroll
    for (int mf = 0; mf < 4; mf++) {
#pragma unroll
        for (int rh = 0; rh < 2; rh++) {
            const int row = m0 + wm * 64 + mf * 16 + qr + rh * 8;
            const size_t go = (size_t)row * 512 + hid0 + wn * 8 + qc;
            const float2 c0v = *(const float2*)(c0 + go);
            float cn[2], hv[2];
#pragma unroll
            for (int e01 = 0; e01 < 2; e01++) {
                const int e = rh * 2 + e01;
                const float zi = acc[mf][0][e] + (e01 ? bv[0].y : bv[0].x);
                const float zf = acc[mf][1][e] + (e01 ? bv[1].y : bv[1].x);
                const float zg = acc[mf][2][e] + (e01 ? bv[2].y : bv[2].x);
                const float zo = acc[mf][3][e] + (e01 ? bv[3].y : bv[3].x);
                const float c0e = e01 ? c0v.y : c0v.x;
                cn[e01] = hsig(zf) * c0e + hsig(zi) * fast_tanh(zg);
                hv[e01] = hsig(zo) * fast_tanh(cn[e01]);
            }
            *(float2*)(c_out + go) = make_float2(cn[0], cn[1]);
            *(float2*)(h_out + go) = make_float2(hv[0], hv[1]);
            *(__half2*)(hh_out + go) = __half2(__float2half_rn(hv[0]), __float2half_rn(hv[1]));
        }
    }
}

// ---- unified prep: weight transposes + bias + x/h0 fp16 converts ----
__device__ __forceinline__ void cvtT_tile(const float* __restrict__ Wm,
                                          __half* __restrict__ dst,
                                          int K, int N, int bx, int by,
                                          int tx, int ty)
{
    __shared__ float t[32][33];
    const int kb = by * 32, nb = bx * 32;
    for (int r = ty; r < 32; r += 8)
        t[r][tx] = Wm[(size_t)(kb + r) * N + nb + tx];
    __syncthreads();
    for (int r = ty; r < 32; r += 8)
        dst[(size_t)(nb + r) * K + kb + tx] = __float2half_rn(t[tx][r]);
}

// gate-per-8 interleave: n = g*512+s -> nr = (s>>5)*128 + ((s>>3)&3)*32 + g*8 + (s&7)
__device__ __forceinline__ int gate_perm(int n) {
    const int g = n >> 9, s = n & 511;
    return ((s >> 5) << 7) + (((s >> 3) & 3) << 5) + (g << 3) + (s & 7);
}

__device__ __forceinline__ void cvtT_perm_tile(const float* __restrict__ Wm,
                                               __half* __restrict__ dst,
                                               int N, int Kout, int koff,
                                               int bx, int by, int tx, int ty)
{
    __shared__ float t[32][33];
    const int kb = by * 32, nb = bx * 32;
    for (int r = ty; r < 32; r += 8)
        t[r][tx] = Wm[(size_t)(kb + r) * N + nb + tx];
    __syncthreads();
    for (int r = ty; r < 32; r += 8) {
        const int nr = gate_perm(nb + r);
        dst[(size_t)nr * Kout + koff + kb + tx] = __float2half_rn(t[tx][r]);
    }
}

__global__ void prep_all(
    const float* __restrict__ Wf, const float* __restrict__ Wb,
    const float* __restrict__ Uf, const float* __restrict__ Ub,
    const float* __restrict__ Wfc1, const float* __restrict__ Wfc2,
    const float* __restrict__ Wi, const float* __restrict__ Ui,
    const float* __restrict__ bf, const float* __restrict__ bb,
    const float* __restrict__ bi,
    const float* __restrict__ x, const float* __restrict__ h0,
    __half* __restrict__ bt, __half* __restrict__ ut, __half* __restrict__ ah,
    float* __restrict__ bfc, float* __restrict__ biP)
{
    const int bx = blockIdx.x, by = blockIdx.y, job = blockIdx.z;
    const int tx = threadIdx.x, ty = threadIdx.y;
    const int tid8 = ty * 32 + tx;
    switch (job) {
        case 0: if (bx < 32 && by < 16) cvtT_tile(Wf, bt, 512, 1024, bx, by, tx, ty); break;
        case 1: if (bx < 32 && by < 16) cvtT_tile(Wb, bt + (size_t)1024 * 512, 512, 1024, bx, by, tx, ty); break;
        case 2: if (bx < 32 && by < 8)  cvtT_tile(Uf, ut, 256, 1024, bx, by, tx, ty); break;
        case 3: if (bx < 32 && by < 8)  cvtT_tile(Ub, ut + 1024 * 256, 256, 1024, bx, by, tx, ty); break;
        case 4: if (bx < 16 && by < 16) cvtT_tile(Wfc1, bt + OFF_FC1, 512, 512, bx, by, tx, ty); break;
        case 5: if (bx < 16 && by < 16) cvtT_tile(Wfc2, bt + OFF_FC2, 512, 512, bx, by, tx, ty); break;
        case 6: if (bx < 64 && by < 16) cvtT_perm_tile(Wi, bt + OFF_INTER, 2048, 1024, 0, bx, by, tx, ty); break;
        case 7: if (bx < 64 && by < 16) cvtT_perm_tile(Ui, bt + OFF_INTER, 2048, 1024, 512, bx, by, tx, ty); break;
        case 8: {
            if (by == 0 && bx < 16) {
                const int i = bx * 256 + tid8;
                if (i < 1024) bfc[i] = bf[i];
                else if (i < 2048) bfc[i] = bb[i - 1024];
                else biP[gate_perm(i - 2048)] = bi[i - 2048];
            }
            break;
        }
        case 9: {   // x -> Ah cols 0..511 (stride 1024)
            const int base_i = (by * 64 + bx) * 256 + tid8;
#pragma unroll
            for (int it = 0; it < 16; it++) {
                const int q = base_i + it * 262144;
                const float4 v = ((const float4*)x)[q];
                const int row = q >> 7;
                const int col = (q & 127) << 2;
                const size_t o = (size_t)row * 1024 + col;
                *(__half2*)(ah + o)     = __half2(__float2half_rn(v.x), __float2half_rn(v.y));
                *(__half2*)(ah + o + 2) = __half2(__float2half_rn(v.z), __float2half_rn(v.w));
            }
            break;
        }
        case 10: {  // h0 -> Ah cols 512..1023 (stride 1024)
            const int base_i = (by * 64 + bx) * 256 + tid8;
#pragma unroll
            for (int it = 0; it < 16; it++) {
                const int q = base_i + it * 262144;
                const float4 v = ((const float4*)h0)[q];
                const int row = q >> 7;
                const int col = (q & 127) << 2;
                const size_t o = (size_t)row * 1024 + 512 + col;
                *(__half2*)(ah + o)     = __half2(__float2half_rn(v.x), __float2half_rn(v.y));
                *(__half2*)(ah + o + 2) = __half2(__float2half_rn(v.z), __float2half_rn(v.w));
            }
            break;
        }
    }
}

// ---------------- persistent bidirectional LSTM recurrence ----------------
// Split-half barrier: ctrA tracks producers of hidden 0..127 (tile_n 0-7),
// ctrB hidden 128..255. Consumer polls A, loads H k0..127, polls B, loads rest.
// Arrive = red.release (no threadfence).
#define RA_STR   528
#define ROFF_BHI 33792
#define ROFF_ZX  67584           // 2 x 8KB fp16 zx buffers
#define RSMEM    83968

__global__ __launch_bounds__(256) void recurrence2(const __half* __restrict__ Ut)
{
    extern __shared__ __align__(128) char rsm[];
    __shared__ unsigned long long s_base;
    const uint32_t sb = smem_u32(rsm);
    const int tid = threadIdx.x, lane = tid & 31, wid = tid >> 5;
    const int blk = blockIdx.x;
    const int tile_m = blk >> 4;
    const int tile_n = blk & 15;
    const int row0 = tile_m << 6;
    const int dir = (tile_m >= 4) ? 1 : 0;
    const int j0 = tile_n << 4;
    const int wm = wid & 3, wn = wid >> 2;
    unsigned long long* const ctrA = &g_barG[tile_m * 16];
    unsigned long long* const ctrB = &g_barG[tile_m * 16 + 8];
    unsigned long long* const mine = (tile_n < 8) ? ctrA : ctrB;

    // B resident: tile row q = hs*32 + g*8 + c8 <-> U^T row dir*1024 + g*256 + j0 + hs*8 + c8
    for (int i = tid; i < 2048; i += 256) {
        const int r = i >> 5, seg = i & 31;
        const int hs = r >> 5, w32 = r & 31;
        const int g = w32 >> 3, c = (hs << 3) + (w32 & 7);
        const size_t gr = ((size_t)(dir * 1024 + g * 256 + j0 + c)) * 256 + seg * 8;
        *(uint4*)(rsm + ROFF_BHI + r * RA_STR + seg * 16) = *(const uint4*)(Ut + gr);
    }

    if (tile_n == 0) {
        uint32_t* h0p = (uint32_t*)&g_Hh[0][row0 * 256];
        for (int i = tid; i < 8192; i += 256) h0p[i] = 0u;
    }

    const uint32_t a_off = (uint32_t)((wm * 16 + (lane & 15)) * RA_STR + (lane >> 4) * 16);
    const int bsub = lane >> 3;
    const uint32_t b_off = (uint32_t)((wn * 32 + ((bsub >> 1) << 3) + (lane & 7)) * RA_STR + (bsub & 1) * 16);

    const int qr = lane >> 2;
    const int qc2 = (lane & 3) << 1;
    float creg[4] = {0.0f, 0.0f, 0.0f, 0.0f};

    // ---- zx(0) prefetch (independent of peers) ----
    {
        const int w0 = dir ? 127 : 0;
#pragma unroll
        for (int ii = 0; ii < 2; ii++) {
            const int q = tid + ii * 256;
            const int r = q >> 3;
            const int m = q & 7;
            const int g = m & 3, hs = m >> 2;
            const __half* src = g_ZX + ((size_t)((row0 + r) & 255) * 128 + w0) * 2048
                               + dir * 1024 + g * 256 + j0 + hs * 8;
            CP_ASYNC16(sb + ROFF_ZX + (uint32_t)(r * 128 + hs * 64 + g * 16), src);
        }
    }
    CP_COMMIT();

    // B smem filled by own CTA -> local sync, then cache fragments in registers
    __syncthreads();
    uint32_t breg[16][4][2];
#pragma unroll
    for (int ks = 0; ks < 16; ks++) {
        uint32_t t4[4];
        ldmx4(t4, sb + ROFF_BHI + b_off + ks * 32);
        breg[ks][0][0] = t4[0]; breg[ks][0][1] = t4[1];
        breg[ks][1][0] = t4[2]; breg[ks][1][1] = t4[3];
        ldmx4(t4, sb + ROFF_BHI + b_off + ks * 32 + 16 * RA_STR);
        breg[ks][2][0] = t4[0]; breg[ks][2][1] = t4[1];
        breg[ks][3][0] = t4[2]; breg[ks][3][1] = t4[3];
    }

    // ---- pre-loop barrier: arrive(release) own counter; wait both; base = rounded ticket
    __syncthreads();
    if (tid == 0) {
        unsigned long long t0 = atom_release_add(mine) + 1ULL;
        unsigned long long target = ((t0 + 7ULL) >> 3) << 3;
        while (ld_acquire(ctrA) < target) { }
        while (ld_acquire(ctrB) < target) { }
        s_base = target;
    }
    __syncthreads();
    const unsigned long long base = s_base;

    for (int t = 0; t < 128; t++) {
        const int pb = t & 1;
        const int w = dir ? (127 - t) : t;
        const __half* hh = g_Hh[pb];
        const __half* zxs = (const __half*)(rsm + ROFF_ZX + (t & 1) * 8192);
        const unsigned long long tgt = base + 8ULL * (unsigned long long)t;

        // ---- wait producers of hidden 0..127, load H k 0..127 ----
        if (t > 0) { while (ld_acquire(ctrA) < tgt) { } }
#pragma unroll
        for (int ii = 0; ii < 4; ii++) {
            const int i = tid + ii * 256;
            const int r = i >> 4, seg = i & 15;
            CP_ASYNC16(sb + r * RA_STR + seg * 16, hh + (size_t)(row0 + r) * 256 + seg * 8);
        }
        CP_COMMIT();
        // ---- wait producers of hidden 128..255, load H k 128..255 ----
        if (t > 0) { while (ld_acquire(ctrB) < tgt) { } }
#pragma unroll
        for (int ii = 0; ii < 4; ii++) {
            const int i = tid + ii * 256;
            const int r = i >> 4, seg = 16 + (i & 15);
            CP_ASYNC16(sb + r * RA_STR + seg * 16, hh + (size_t)(row0 + r) * 256 + seg * 8);
        }
        CP_COMMIT();

        float acc[4][4];
#pragma unroll
        for (int nf = 0; nf < 4; nf++)
#pragma unroll
            for (int r = 0; r < 4; r++) acc[nf][r] = 0.0f;

        CP_WAIT1();
        __syncthreads();
#pragma unroll
        for (int ks = 0; ks < 8; ks++) {
            uint32_t ah4[4];
            ldmx4(ah4, sb + a_off + ks * 32);
#pragma unroll
            for (int nf = 0; nf < 4; nf++)
                mma_f16(acc[nf], ah4, breg[ks][nf]);
        }
        CP_WAIT0();
        __syncthreads();
#pragma unroll
        for (int ks = 8; ks < 16; ks++) {
            uint32_t ah4[4];
            ldmx4(ah4, sb + a_off + ks * 32);
#pragma unroll
            for (int nf = 0; nf < 4; nf++)
                mma_f16(acc[nf], ah4, breg[ks][nf]);
        }

        // ---- register-resident gate update; store next-H first ----
        __half2 hsv[2];
#pragma unroll
        for (int r = 0; r < 2; r++) {
            const int rloc = wm * 16 + qr + r * 8;
            const __half* zb = zxs + rloc * 64 + wn * 32 + qc2;
            const __half2 xi = *(const __half2*)(zb);
            const __half2 xf = *(const __half2*)(zb + 8);
            const __half2 xg = *(const __half2*)(zb + 16);
            const __half2 xo = *(const __half2*)(zb + 24);
            float hv0, hv1;
            {
                const int e = r * 2;
                const float zi = acc[0][e] + __half2float(xi.x);
                const float zf = acc[1][e] + __half2float(xf.x);
                const float zg = acc[2][e] + __half2float(xg.x);
                const float zo = acc[3][e] + __half2float(xo.x);
                const float cn = hsig(zf) * creg[e] + hsig(zi) * fast_tanh(zg);
                creg[e] = cn;
                hv0 = hsig(zo) * fast_tanh(cn);
            }
            {
                const int e = r * 2 + 1;
                const float zi = acc[0][e] + __half2float(xi.y);
                const float zf = acc[1][e] + __half2float(xf.y);
                const float zg = acc[2][e] + __half2float(xg.y);
                const float zo = acc[3][e] + __half2float(xo.y);
                const float cn = hsig(zf) * creg[e] + hsig(zi) * fast_tanh(zg);
                creg[e] = cn;
                hv1 = hsig(zo) * fast_tanh(cn);
            }
            hsv[r] = __half2(__float2half_rn(hv0), __float2half_rn(hv1));
            const int Rg = row0 + rloc;
            *(__half2*)(&g_Hh[pb ^ 1][(size_t)Rg * 256 + j0 + wn * 8 + qc2]) = hsv[r];
        }

        if (t < 127) {
            // arrive: bar.sync orders all threads' H stores before tid0's release
            __syncthreads();
            if (tid == 0) red_release_add(mine);
        }

        // HS output stores (off the cross-CTA critical path)
#pragma unroll
        for (int r = 0; r < 2; r++) {
            const int rloc = wm * 16 + qr + r * 8;
            const int Rg = row0 + rloc;
            const size_t hsoff = ((size_t)(Rg & 255) * 128 + w) * 512 + dir * 256
                               + j0 + wn * 8 + qc2;
            *(__half2*)(g_HSh + hsoff) = hsv[r];
        }

        if (t < 127) {
            // zx(t+1) prefetch into the other buffer
            const int wn1 = dir ? (127 - (t + 1)) : (t + 1);
            const uint32_t zdst = sb + ROFF_ZX + (uint32_t)(((t + 1) & 1) * 8192);
#pragma unroll
            for (int ii = 0; ii < 2; ii++) {
                const int q = tid + ii * 256;
                const int r = q >> 3;
                const int m = q & 7;
                const int g = m & 3, hs = m >> 2;
                const __half* src = g_ZX + ((size_t)((row0 + r) & 255) * 128 + wn1) * 2048
                                   + dir * 1024 + g * 256 + j0 + hs * 8;
                CP_ASYNC16(zdst + (uint32_t)(r * 128 + hs * 64 + g * 16), src);
            }
            CP_COMMIT();
        }
    }
}

// ---------------- LayerNorm over (W,C)=65536 (1024 threads), optional fused fp16 convert ----------------
__global__ __launch_bounds__(1024) void ln_kernel(
    const float* __restrict__ pre, const float* __restrict__ xres,
    const float* __restrict__ gamma, const float* __restrict__ beta,
    float* __restrict__ out, __half* __restrict__ sh, int mode)
{
    __shared__ float red[1024];
    const int tid = threadIdx.x;
    const size_t base = (size_t)blockIdx.x * 65536;

    float s = 0.0f, ss = 0.0f;
    for (int i = tid * 4; i < 65536; i += 4096) {
        float4 v = *(const float4*)(pre + base + i);
        s  += v.x + v.y + v.z + v.w;
        ss += v.x * v.x + v.y * v.y + v.z * v.z + v.w * v.w;
    }
    red[tid] = s; __syncthreads();
    for (int off = 512; off; off >>= 1) { if (tid < off) red[tid] += red[tid + off]; __syncthreads(); }
    const float mean = red[0] * (1.0f / 65536.0f);
    __syncthreads();
    red[tid] = ss; __syncthreads();
    for (int off = 512; off; off >>= 1) { if (tid < off) red[tid] += red[tid + off]; __syncthreads(); }
    const float var = red[0] * (1.0f / 65536.0f) - mean * mean;
    const float rstd = rsqrtf(var + 1e-3f);

    for (int i = tid * 4; i < 65536; i += 4096) {
        float4 v = *(const float4*)(pre + base + i);
        float4 g = *(const float4*)(gamma + i);
        float4 bb = *(const float4*)(beta + i);
        float4 r;
        r.x = (v.x - mean) * rstd * g.x + bb.x;
        r.y = (v.y - mean) * rstd * g.y + bb.y;
        r.z = (v.z - mean) * rstd * g.z + bb.z;
        r.w = (v.w - mean) * rstd * g.w + bb.w;
        if (mode == 0) {
            float4 xr = *(const float4*)(xres + base + i);
            r.x += xr.x; r.y += xr.y; r.z += xr.z; r.w += xr.w;
        } else {
            float4 o = *(const float4*)(out + base + i);
            r.x += o.x; r.y += o.y; r.z += o.z; r.w += o.w;
        }
        *(float4*)(out + base + i) = r;
        if (sh) {
            const size_t f = base + i;
            const size_t so = (f >> 9) * 1024 + (f & 511);
            *(__half2*)(sh + so)     = __half2(__float2half_rn(r.x), __float2half_rn(r.y));
            *(__half2*)(sh + so + 2) = __half2(__float2half_rn(r.z), __float2half_rn(r.w));
        }
    }
}

// ---------------- launch ----------------
extern "C" void kernel_launch(void* const* d_in, const int* in_sizes, int n_in,
                              void* d_out, int out_size)
{
    const float* x    = (const float*)d_in[0];
    const float* h0   = (const float*)d_in[1];
    const float* c0   = (const float*)d_in[2];
    const float* Wf   = (const float*)d_in[3];
    const float* Uf   = (const float*)d_in[4];
    const float* bf   = (const float*)d_in[5];
    const float* Wb   = (const float*)d_in[6];
    const float* Ub   = (const float*)d_in[7];
    const float* bb   = (const float*)d_in[8];
    const float* Wfc1 = (const float*)d_in[9];
    const float* bfc1 = (const float*)d_in[10];
    const float* g1   = (const float*)d_in[11];
    const float* b1   = (const float*)d_in[12];
    const float* Wi   = (const float*)d_in[13];
    const float* Ui   = (const float*)d_in[14];
    const float* bi   = (const float*)d_in[15];
    const float* Wfc2 = (const float*)d_in[16];
    const float* bfc2 = (const float*)d_in[17];
    const float* g2   = (const float*)d_in[18];
    const float* b2   = (const float*)d_in[19];

    float* out = (float*)d_out;
    float* h_out = out + OUT0;
    float* c_out = out + 2 * OUT0;
    const int full_out = (out_size >= (int)(3 * OUT0)) || out_size <= 0;

    float *fc, *bfc, *biP, *hcfb;
    __half *zx, *ah, *bt, *ut, *hsh;
    cudaGetSymbolAddress((void**)&zx,  g_ZX);
    cudaGetSymbolAddress((void**)&fc,  g_FC);
    cudaGetSymbolAddress((void**)&bfc, g_bfc);
    cudaGetSymbolAddress((void**)&biP, g_biP);
    cudaGetSymbolAddress((void**)&ah,  g_Ah);
    cudaGetSymbolAddress((void**)&bt,  g_Bt);
    cudaGetSymbolAddress((void**)&ut,  g_Ut);
    cudaGetSymbolAddress((void**)&hsh, g_HSh);
    cudaGetSymbolAddress((void**)&hcfb, g_HCfb);

    cudaFuncSetAttribute(tcgemm, cudaFuncAttributeMaxDynamicSharedMemorySize, GEMM_SMEM);
    cudaFuncSetAttribute(tcgemm_h, cudaFuncAttributeMaxDynamicSharedMemorySize, GEMM_SMEM);
    cudaFuncSetAttribute(tcgemm_gates, cudaFuncAttributeMaxDynamicSharedMemorySize, GEMM_SMEM);
    cudaFuncSetAttribute(recurrence2, cudaFuncAttributeMaxDynamicSharedMemorySize, RSMEM);

    // ---- all prep (weights, biases, x/h0 converts) in ONE launch ----
    prep_all<<<dim3(64, 16, 11), dim3(32, 8)>>>(Wf, Wb, Uf, Ub, Wfc1, Wfc2, Wi, Ui,
                                                bf, bb, bi, x, h0, bt, ut, ah, bfc, biP);

    // ---- combined intra input projection: ZX(fp16) = x @ [Wf|Wb] + [bf|bb] ----
    tcgemm_h<<<dim3(16, 256), 256, GEMM_SMEM>>>(ah, bt, zx, bfc, MROWS, 2048, 512, 1024);

    // ---- recurrence ----
    recurrence2<<<128, 256, RSMEM>>>(ut);

    // ---- fc1 (A = HS) ----
    tcgemm<<<dim3(4, 256), 256, GEMM_SMEM>>>(hsh, bt + OFF_FC1, fc, bfc1, MROWS, 512, 512, 512);

    // ---- LN1 + residual -> out, fused convert (Ah cols 0..511) ----
    ln_kernel<<<256, 1024>>>(fc, x, g1, b1, out, ah, 0);

    // ---- inter: single K=1024 GEMM with register-gate epilogue ----
    float* hptr = full_out ? h_out : hcfb;
    float* cptr = full_out ? c_out : (hcfb + (size_t)MROWS * 512);
    tcgemm_gates<<<dim3(16, 256), 256, GEMM_SMEM>>>(ah, bt + OFF_INTER, biP, c0,
                                                    hptr, cptr, hsh, 1024, 1024);

    // ---- fc2 (A = h in g_HSh) ----
    tcgemm<<<dim3(4, 256), 256, GEMM_SMEM>>>(hsh, bt + OFF_FC2, fc, bfc2, MROWS, 512, 512, 512);

    // ---- LN2 accumulate into out ----
    ln_kernel<<<256, 1024>>>(fc, nullptr, g2, b2, out, nullptr, 1);
}

// round 17
// speedup vs baseline: 1.3935x; 1.0234x over previous
#include <cuda_runtime.h>
#include <cuda_fp16.h>
#include <cstdint>
#include <math.h>

// Problem constants
#define NSAMP 256            // B*L
#define W_    128
#define C_    512
#define HD_   256
#define MROWS 32768          // B*W
#define OUT0  ((size_t)16777216)   // B*L*W*C

// B-region offsets inside g_Bt (in halfs)
#define OFF_INTER 1048576          // 2048 rows x 1024 K
#define OFF_FC1   3145728          // 512 x 512
#define OFF_FC2   3407872          // 512 x 512

// ---------------- scratch (static device globals; no allocations) ----------------
__device__ __half g_ZX [(size_t)MROWS * 2048];  // combined intra projections, fp16
__device__ float g_FC [(size_t)MROWS * 512];
__device__ float g_bfc[2048];
__device__ float g_biP[2048];
__device__ unsigned long long g_barG[8 * 16];   // per-group monotonic tickets (A at +0, B at +8)

// fp16 operand buffers
__device__ __half g_Ah [(size_t)MROWS * 1024];  // cols 0-511: x / intra_out; 512-1023: h0
__device__ __half g_Bt [(size_t)3670016];       // proj | inter | fc1 | fc2 regions
// recurrence state / weights / outputs (fp16)
__device__ __half g_Hh[2][512 * 256];
__device__ __half g_Ut[(size_t)2048 * 256];
__device__ __half g_HSh[(size_t)MROWS * 512];
// fallback h/c buffers when out buffer is small
__device__ float g_HCfb[2][(size_t)MROWS * 512];

__device__ __forceinline__ float hsig(float x) {
    return fminf(fmaxf(fmaf(0.2f, x, 0.5f), 0.0f), 1.0f);
}
__device__ __forceinline__ float fast_tanh(float x) {
    const float e = __expf(2.0f * x);
    return 1.0f - __fdividef(2.0f, e + 1.0f);
}

// ================= low-level helpers (sm_80-baseline ISA only) =================
__device__ __forceinline__ uint32_t smem_u32(const void* p) {
    uint32_t a;
    asm("{ .reg .u64 t; cvta.to.shared.u64 t, %1; cvt.u32.u64 %0, t; }" : "=r"(a) : "l"(p));
    return a;
}
#define CP_ASYNC16(dst, src) \
    asm volatile("cp.async.cg.shared.global [%0], [%1], 16;" :: "r"(dst), "l"(src) : "memory")
#define CP_COMMIT() asm volatile("cp.async.commit_group;" ::: "memory")
#define CP_WAIT2()  asm volatile("cp.async.wait_group 2;" ::: "memory")
#define CP_WAIT1()  asm volatile("cp.async.wait_group 1;" ::: "memory")
#define CP_WAIT0()  asm volatile("cp.async.wait_group 0;" ::: "memory")

__device__ __forceinline__ void ldmx4(uint32_t* r, uint32_t addr) {
    asm volatile("ldmatrix.sync.aligned.m8n8.x4.shared.b16 {%0,%1,%2,%3}, [%4];"
        : "=r"(r[0]), "=r"(r[1]), "=r"(r[2]), "=r"(r[3]) : "r"(addr));
}
__device__ __forceinline__ void mma_f16(float* d, const uint32_t* a, const uint32_t* b) {
    asm volatile("mma.sync.aligned.m16n8k16.row.col.f32.f16.f16.f32 "
        "{%0,%1,%2,%3}, {%4,%5,%6,%7}, {%8,%9}, {%0,%1,%2,%3};"
        : "+f"(d[0]), "+f"(d[1]), "+f"(d[2]), "+f"(d[3])
        : "r"(a[0]), "r"(a[1]), "r"(a[2]), "r"(a[3]), "r"(b[0]), "r"(b[1]));
}
__device__ __forceinline__ unsigned long long ld_acquire(const unsigned long long* p) {
    unsigned long long v;
    asm volatile("ld.acquire.gpu.u64 %0, [%1];" : "=l"(v) : "l"(p) : "memory");
    return v;
}
__device__ __forceinline__ unsigned long long atom_release_add(unsigned long long* p) {
    unsigned long long v;
    asm volatile("atom.release.gpu.global.add.u64 %0, [%1], %2;"
        : "=l"(v) : "l"(p), "l"(1ULL) : "memory");
    return v;
}
__device__ __forceinline__ void red_release_add(unsigned long long* p) {
    asm volatile("red.release.gpu.global.add.u64 [%0], %1;" :: "l"(p), "l"(1ULL) : "memory");
}

// ================= 128x128 fp16 GEMM: k64 chunks, 3-stage, 2 CTAs/SM =================
#define TILE_B   18432           // 128 rows * 144B (64 halfs + 16B pad)
#define STG_B    36864
#define GEMM_SMEM 110592         // 3 stages

__device__ __forceinline__ void load_chunk(uint32_t stage_base,
    const __half* __restrict__ Ah, const __half* __restrict__ Bh,
    int m0, int n0, int kk, int lda, int K, int tid)
{
#pragma unroll
    for (int i = 0; i < 4; i++) {
        const int c = tid + i * 256;
        const int row = c >> 3;
        const int seg = c & 7;
        const uint32_t doff = (uint32_t)(row * 144 + seg * 16);
        CP_ASYNC16(stage_base + doff, Ah + (size_t)(m0 + row) * lda + kk + seg * 8);
        CP_ASYNC16(stage_base + TILE_B + doff, Bh + (size_t)(n0 + row) * K + kk + seg * 8);
    }
}

#define GEMM_MAINLOOP(Ah, Bh, m0, n0, lda, K, acc)                                \
    {                                                                             \
        const int NC = (K) >> 6;                                                  \
        load_chunk(sb + 0 * STG_B, Ah, Bh, m0, n0, 0, lda, K, tid);               \
        CP_COMMIT();                                                              \
        load_chunk(sb + 1 * STG_B, Ah, Bh, m0, n0, 64, lda, K, tid);              \
        CP_COMMIT();                                                              \
        load_chunk(sb + 2 * STG_B, Ah, Bh, m0, n0, 128, lda, K, tid);             \
        CP_COMMIT();                                                              \
        int stage = 0;                                                            \
        for (int c = 0; c < NC; c++) {                                            \
            CP_WAIT2();                                                           \
            __syncthreads();                                                      \
            const uint32_t st = sb + stage * STG_B;                               \
            _Pragma("unroll")                                                     \
            for (int ks = 0; ks < 4; ks++) {                                      \
                const uint32_t kb = st + ks * 32;                                 \
                uint32_t af[4][4], bhf[4][2], t4[4];                              \
                _Pragma("unroll")                                                 \
                for (int nh = 0; nh < 2; nh++) {                                  \
                    ldmx4(t4, kb + TILE_B + b_off + nh * 16 * 144);               \
                    bhf[2*nh][0] = t4[0]; bhf[2*nh][1] = t4[1];                   \
                    bhf[2*nh+1][0] = t4[2]; bhf[2*nh+1][1] = t4[3];               \
                }                                                                 \
                _Pragma("unroll")                                                 \
                for (int mf = 0; mf < 4; mf++) ldmx4(af[mf], kb + a_off + mf * 16 * 144); \
                _Pragma("unroll")                                                 \
                for (int mf = 0; mf < 4; mf++)                                    \
                    _Pragma("unroll")                                             \
                    for (int nf = 0; nf < 4; nf++)                                \
                        mma_f16(acc[mf][nf], af[mf], bhf[nf]);                    \
            }                                                                     \
            __syncthreads();                                                      \
            if (c + 3 < NC)                                                       \
                load_chunk(st, Ah, Bh, m0, n0, (c + 3) << 6, lda, K, tid);        \
            CP_COMMIT();                                                          \
            stage = (stage == 2) ? 0 : stage + 1;                                 \
        }                                                                         \
    }

// fp32-output GEMM (fc1/fc2)
__global__ __launch_bounds__(256, 2) void tcgemm(
    const __half* __restrict__ Ah, const __half* __restrict__ Bh,
    float* __restrict__ Cmat, const float* __restrict__ bias,
    int M, int N, int K, int lda)
{
    extern __shared__ __align__(128) char smem_raw[];
    const uint32_t sb = smem_u32(smem_raw);

    const int tid = threadIdx.x;
    const int lane = tid & 31;
    const int wid = tid >> 5;
    const int wm = wid >> 2;
    const int wn = wid & 3;
    const int m0 = blockIdx.y << 7;
    const int n0 = blockIdx.x << 7;

    const uint32_t a_off = (uint32_t)((wm * 64 + (lane & 15)) * 144 + (lane >> 4) * 16);
    const int bsub = lane >> 3;
    const uint32_t b_off = (uint32_t)((wn * 32 + ((bsub >> 1) << 3) + (lane & 7)) * 144 + (bsub & 1) * 16);

    float acc[4][4][4];
#pragma unroll
    for (int mf = 0; mf < 4; mf++)
#pragma unroll
        for (int nf = 0; nf < 4; nf++)
#pragma unroll
            for (int r = 0; r < 4; r++) acc[mf][nf][r] = 0.0f;

    GEMM_MAINLOOP(Ah, Bh, m0, n0, lda, K, acc);

    const int qr = lane >> 2;
    const int qc = (lane & 3) << 1;
#pragma unroll
    for (int mf = 0; mf < 4; mf++) {
        const int row = m0 + wm * 64 + mf * 16 + qr;
#pragma unroll
        for (int nf = 0; nf < 4; nf++) {
            const int col = n0 + wn * 32 + nf * 8 + qc;
            const float2 bv = *(const float2*)(bias + col);
            float2 v0 = make_float2(acc[mf][nf][0] + bv.x, acc[mf][nf][1] + bv.y);
            float2 v1 = make_float2(acc[mf][nf][2] + bv.x, acc[mf][nf][3] + bv.y);
            *(float2*)(Cmat + (size_t)row * N + col) = v0;
            *(float2*)(Cmat + (size_t)(row + 8) * N + col) = v1;
        }
    }
}

// fp16-output GEMM (intra projection -> ZX)
__global__ __launch_bounds__(256, 2) void tcgemm_h(
    const __half* __restrict__ Ah, const __half* __restrict__ Bh,
    __half* __restrict__ Cmat, const float* __restrict__ bias,
    int M, int N, int K, int lda)
{
    extern __shared__ __align__(128) char smem_raw[];
    const uint32_t sb = smem_u32(smem_raw);

    const int tid = threadIdx.x;
    const int lane = tid & 31;
    const int wid = tid >> 5;
    const int wm = wid >> 2;
    const int wn = wid & 3;
    const int m0 = blockIdx.y << 7;
    const int n0 = blockIdx.x << 7;

    const uint32_t a_off = (uint32_t)((wm * 64 + (lane & 15)) * 144 + (lane >> 4) * 16);
    const int bsub = lane >> 3;
    const uint32_t b_off = (uint32_t)((wn * 32 + ((bsub >> 1) << 3) + (lane & 7)) * 144 + (bsub & 1) * 16);

    float acc[4][4][4];
#pragma unroll
    for (int mf = 0; mf < 4; mf++)
#pragma unroll
        for (int nf = 0; nf < 4; nf++)
#pragma unroll
            for (int r = 0; r < 4; r++) acc[mf][nf][r] = 0.0f;

    GEMM_MAINLOOP(Ah, Bh, m0, n0, lda, K, acc);

    const int qr = lane >> 2;
    const int qc = (lane & 3) << 1;
#pragma unroll
    for (int mf = 0; mf < 4; mf++) {
        const int row = m0 + wm * 64 + mf * 16 + qr;
#pragma unroll
        for (int nf = 0; nf < 4; nf++) {
            const int col = n0 + wn * 32 + nf * 8 + qc;
            const float2 bv = *(const float2*)(bias + col);
            *(__half2*)(Cmat + (size_t)row * N + col) =
                __half2(__float2half_rn(acc[mf][nf][0] + bv.x),
                        __float2half_rn(acc[mf][nf][1] + bv.y));
            *(__half2*)(Cmat + (size_t)(row + 8) * N + col) =
                __half2(__float2half_rn(acc[mf][nf][2] + bv.x),
                        __float2half_rn(acc[mf][nf][3] + bv.y));
        }
    }
}

// ---- inter GEMM with register-resident LSTM gate epilogue ----
__global__ __launch_bounds__(256, 2) void tcgemm_gates(
    const __half* __restrict__ Ah, const __half* __restrict__ Bh,
    const float* __restrict__ biasP, const float* __restrict__ c0,
    float* __restrict__ h_out, float* __restrict__ c_out,
    __half* __restrict__ hh_out, int K, int lda)
{
    extern __shared__ __align__(128) char smem_raw[];
    const uint32_t sb = smem_u32(smem_raw);

    const int tid = threadIdx.x;
    const int lane = tid & 31;
    const int wid = tid >> 5;
    const int wm = wid >> 2;
    const int wn = wid & 3;
    const int m0 = blockIdx.y << 7;
    const int n0 = blockIdx.x << 7;
    const int hid0 = blockIdx.x << 5;

    const uint32_t a_off = (uint32_t)((wm * 64 + (lane & 15)) * 144 + (lane >> 4) * 16);
    const int bsub = lane >> 3;
    const uint32_t b_off = (uint32_t)((wn * 32 + ((bsub >> 1) << 3) + (lane & 7)) * 144 + (bsub & 1) * 16);

    float acc[4][4][4];
#pragma unroll
    for (int mf = 0; mf < 4; mf++)
#pragma unroll
        for (int nf = 0; nf < 4; nf++)
#pragma unroll
            for (int r = 0; r < 4; r++) acc[mf][nf][r] = 0.0f;

    GEMM_MAINLOOP(Ah, Bh, m0, n0, lda, K, acc);

    // register gate update: gate = nf, hidden local = wn*8 + qc + e01
    const int qr = lane >> 2;
    const int qc = (lane & 3) << 1;
    float2 bv[4];
#pragma unroll
    for (int g = 0; g < 4; g++)
        bv[g] = *(const float2*)(biasP + n0 + wn * 32 + g * 8 + qc);

#pragma unroll
    for (int mf = 0; mf < 4; mf++) {
#pragma unroll
        for (int rh = 0; rh < 2; rh++) {
            const int row = m0 + wm * 64 + mf * 16 + qr + rh * 8;
            const size_t go = (size_t)row * 512 + hid0 + wn * 8 + qc;
            const float2 c0v = *(const float2*)(c0 + go);
            float cn[2], hv[2];
#pragma unroll
            for (int e01 = 0; e01 < 2; e01++) {
                const int e = rh * 2 + e01;
                const float zi = acc[mf][0][e] + (e01 ? bv[0].y : bv[0].x);
                const float zf = acc[mf][1][e] + (e01 ? bv[1].y : bv[1].x);
                const float zg = acc[mf][2][e] + (e01 ? bv[2].y : bv[2].x);
                const float zo = acc[mf][3][e] + (e01 ? bv[3].y : bv[3].x);
                const float c0e = e01 ? c0v.y : c0v.x;
                cn[e01] = hsig(zf) * c0e + hsig(zi) * fast_tanh(zg);
                hv[e01] = hsig(zo) * fast_tanh(cn[e01]);
            }
            *(float2*)(c_out + go) = make_float2(cn[0], cn[1]);
            *(float2*)(h_out + go) = make_float2(hv[0], hv[1]);
            *(__half2*)(hh_out + go) = __half2(__float2half_rn(hv[0]), __float2half_rn(hv[1]));
        }
    }
}

// ---- unified prep: weight transposes + bias + x/h0 fp16 converts ----
__device__ __forceinline__ void cvtT_tile(const float* __restrict__ Wm,
                                          __half* __restrict__ dst,
                                          int K, int N, int bx, int by,
                                          int tx, int ty)
{
    __shared__ float t[32][33];
    const int kb = by * 32, nb = bx * 32;
    for (int r = ty; r < 32; r += 8)
        t[r][tx] = Wm[(size_t)(kb + r) * N + nb + tx];
    __syncthreads();
    for (int r = ty; r < 32; r += 8)
        dst[(size_t)(nb + r) * K + kb + tx] = __float2half_rn(t[tx][r]);
}

// gate-per-8 interleave: n = g*512+s -> nr = (s>>5)*128 + ((s>>3)&3)*32 + g*8 + (s&7)
__device__ __forceinline__ int gate_perm(int n) {
    const int g = n >> 9, s = n & 511;
    return ((s >> 5) << 7) + (((s >> 3) & 3) << 5) + (g << 3) + (s & 7);
}

__device__ __forceinline__ void cvtT_perm_tile(const float* __restrict__ Wm,
                                               __half* __restrict__ dst,
                                               int N, int Kout, int koff,
                                               int bx, int by, int tx, int ty)
{
    __shared__ float t[32][33];
    const int kb = by * 32, nb = bx * 32;
    for (int r = ty; r < 32; r += 8)
        t[r][tx] = Wm[(size_t)(kb + r) * N + nb + tx];
    __syncthreads();
    for (int r = ty; r < 32; r += 8) {
        const int nr = gate_perm(nb + r);
        dst[(size_t)nr * Kout + koff + kb + tx] = __float2half_rn(t[tx][r]);
    }
}

__global__ void prep_all(
    const float* __restrict__ Wf, const float* __restrict__ Wb,
    const float* __restrict__ Uf, const float* __restrict__ Ub,
    const float* __restrict__ Wfc1, const float* __restrict__ Wfc2,
    const float* __restrict__ Wi, const float* __restrict__ Ui,
    const float* __restrict__ bf, const float* __restrict__ bb,
    const float* __restrict__ bi,
    const float* __restrict__ x, const float* __restrict__ h0,
    __half* __restrict__ bt, __half* __restrict__ ut, __half* __restrict__ ah,
    float* __restrict__ bfc, float* __restrict__ biP)
{
    const int bx = blockIdx.x, by = blockIdx.y, job = blockIdx.z;
    const int tx = threadIdx.x, ty = threadIdx.y;
    const int tid8 = ty * 32 + tx;
    switch (job) {
        case 0: if (bx < 32 && by < 16) cvtT_tile(Wf, bt, 512, 1024, bx, by, tx, ty); break;
        case 1: if (bx < 32 && by < 16) cvtT_tile(Wb, bt + (size_t)1024 * 512, 512, 1024, bx, by, tx, ty); break;
        case 2: if (bx < 32 && by < 8)  cvtT_tile(Uf, ut, 256, 1024, bx, by, tx, ty); break;
        case 3: if (bx < 32 && by < 8)  cvtT_tile(Ub, ut + 1024 * 256, 256, 1024, bx, by, tx, ty); break;
        case 4: if (bx < 16 && by < 16) cvtT_tile(Wfc1, bt + OFF_FC1, 512, 512, bx, by, tx, ty); break;
        case 5: if (bx < 16 && by < 16) cvtT_tile(Wfc2, bt + OFF_FC2, 512, 512, bx, by, tx, ty); break;
        case 6: if (bx < 64 && by < 16) cvtT_perm_tile(Wi, bt + OFF_INTER, 2048, 1024, 0, bx, by, tx, ty); break;
        case 7: if (bx < 64 && by < 16) cvtT_perm_tile(Ui, bt + OFF_INTER, 2048, 1024, 512, bx, by, tx, ty); break;
        case 8: {
            if (by == 0 && bx < 16) {
                const int i = bx * 256 + tid8;
                if (i < 1024) bfc[i] = bf[i];
                else if (i < 2048) bfc[i] = bb[i - 1024];
                else biP[gate_perm(i - 2048)] = bi[i - 2048];
            }
            break;
        }
        case 9: {   // x -> Ah cols 0..511 (stride 1024)
            const int base_i = (by * 64 + bx) * 256 + tid8;
#pragma unroll
            for (int it = 0; it < 16; it++) {
                const int q = base_i + it * 262144;
                const float4 v = ((const float4*)x)[q];
                const int row = q >> 7;
                const int col = (q & 127) << 2;
                const size_t o = (size_t)row * 1024 + col;
                *(__half2*)(ah + o)     = __half2(__float2half_rn(v.x), __float2half_rn(v.y));
                *(__half2*)(ah + o + 2) = __half2(__float2half_rn(v.z), __float2half_rn(v.w));
            }
            break;
        }
        case 10: {  // h0 -> Ah cols 512..1023 (stride 1024)
            const int base_i = (by * 64 + bx) * 256 + tid8;
#pragma unroll
            for (int it = 0; it < 16; it++) {
                const int q = base_i + it * 262144;
                const float4 v = ((const float4*)h0)[q];
                const int row = q >> 7;
                const int col = (q & 127) << 2;
                const size_t o = (size_t)row * 1024 + 512 + col;
                *(__half2*)(ah + o)     = __half2(__float2half_rn(v.x), __float2half_rn(v.y));
                *(__half2*)(ah + o + 2) = __half2(__float2half_rn(v.z), __float2half_rn(v.w));
            }
            break;
        }
    }
}

// ---------------- persistent bidirectional LSTM recurrence ----------------
// Split-half barrier: ctrA tracks producers of hidden 0..127 (tile_n 0-7),
// ctrB hidden 128..255. Arrive = red.release; static targets from pre-loop base.
#define RA_STR   528
#define ROFF_BHI 33792
#define ROFF_ZX  67584           // 2 x 8KB fp16 zx buffers
#define RSMEM    83968

__global__ __launch_bounds__(256) void recurrence2(const __half* __restrict__ Ut)
{
    extern __shared__ __align__(128) char rsm[];
    __shared__ unsigned long long s_base;
    const uint32_t sb = smem_u32(rsm);
    const int tid = threadIdx.x, lane = tid & 31, wid = tid >> 5;
    const int blk = blockIdx.x;
    const int tile_m = blk >> 4;
    const int tile_n = blk & 15;
    const int row0 = tile_m << 6;
    const int dir = (tile_m >= 4) ? 1 : 0;
    const int j0 = tile_n << 4;
    const int wm = wid & 3, wn = wid >> 2;
    unsigned long long* const ctrA = &g_barG[tile_m * 16];
    unsigned long long* const ctrB = &g_barG[tile_m * 16 + 8];
    unsigned long long* const mine = (tile_n < 8) ? ctrA : ctrB;

    // B resident: tile row q = hs*32 + g*8 + c8 <-> U^T row dir*1024 + g*256 + j0 + hs*8 + c8
    for (int i = tid; i < 2048; i += 256) {
        const int r = i >> 5, seg = i & 31;
        const int hs = r >> 5, w32 = r & 31;
        const int g = w32 >> 3, c = (hs << 3) + (w32 & 7);
        const size_t gr = ((size_t)(dir * 1024 + g * 256 + j0 + c)) * 256 + seg * 8;
        *(uint4*)(rsm + ROFF_BHI + r * RA_STR + seg * 16) = *(const uint4*)(Ut + gr);
    }

    if (tile_n == 0) {
        uint32_t* h0p = (uint32_t*)&g_Hh[0][row0 * 256];
        for (int i = tid; i < 8192; i += 256) h0p[i] = 0u;
    }

    const uint32_t a_off = (uint32_t)((wm * 16 + (lane & 15)) * RA_STR + (lane >> 4) * 16);
    const int bsub = lane >> 3;
    const uint32_t b_off = (uint32_t)((wn * 32 + ((bsub >> 1) << 3) + (lane & 7)) * RA_STR + (bsub & 1) * 16);

    const int qr = lane >> 2;
    const int qc2 = (lane & 3) << 1;
    float creg[4] = {0.0f, 0.0f, 0.0f, 0.0f};

    // ---- zx(0) prefetch (independent of peers) ----
    {
        const int w0 = dir ? 127 : 0;
#pragma unroll
        for (int ii = 0; ii < 2; ii++) {
            const int q = tid + ii * 256;
            const int r = q >> 3;
            const int m = q & 7;
            const int g = m & 3, hs = m >> 2;
            const __half* src = g_ZX + ((size_t)((row0 + r) & 255) * 128 + w0) * 2048
                               + dir * 1024 + g * 256 + j0 + hs * 8;
            CP_ASYNC16(sb + ROFF_ZX + (uint32_t)(r * 128 + hs * 64 + g * 16), src);
        }
    }
    CP_COMMIT();

    // B smem filled by own CTA -> local sync, then cache fragments in registers
    __syncthreads();
    uint32_t breg[16][4][2];
#pragma unroll
    for (int ks = 0; ks < 16; ks++) {
        uint32_t t4[4];
        ldmx4(t4, sb + ROFF_BHI + b_off + ks * 32);
        breg[ks][0][0] = t4[0]; breg[ks][0][1] = t4[1];
        breg[ks][1][0] = t4[2]; breg[ks][1][1] = t4[3];
        ldmx4(t4, sb + ROFF_BHI + b_off + ks * 32 + 16 * RA_STR);
        breg[ks][2][0] = t4[0]; breg[ks][2][1] = t4[1];
        breg[ks][3][0] = t4[2]; breg[ks][3][1] = t4[3];
    }

    // ---- pre-loop barrier: arrive(release) own counter; wait both; base = rounded ticket
    __syncthreads();
    if (tid == 0) {
        unsigned long long t0 = atom_release_add(mine) + 1ULL;
        unsigned long long target = ((t0 + 7ULL) >> 3) << 3;
        while (ld_acquire(ctrA) < target) { }
        while (ld_acquire(ctrB) < target) { }
        s_base = target;
    }
    __syncthreads();
    const unsigned long long base = s_base;

    for (int t = 0; t < 128; t++) {
        const int pb = t & 1;
        const int w = dir ? (127 - t) : t;
        const __half* hh = g_Hh[pb];
        const __half* zxs = (const __half*)(rsm + ROFF_ZX + (t & 1) * 8192);
        const unsigned long long tgt = base + 8ULL * (unsigned long long)t;

        // ---- wait producers of hidden 0..127, load H k 0..127 ----
        if (t > 0) { while (ld_acquire(ctrA) < tgt) { } }
#pragma unroll
        for (int ii = 0; ii < 4; ii++) {
            const int i = tid + ii * 256;
            const int r = i >> 4, seg = i & 15;
            CP_ASYNC16(sb + r * RA_STR + seg * 16, hh + (size_t)(row0 + r) * 256 + seg * 8);
        }
        CP_COMMIT();
        // ---- wait producers of hidden 128..255, load H k 128..255 ----
        if (t > 0) { while (ld_acquire(ctrB) < tgt) { } }
#pragma unroll
        for (int ii = 0; ii < 4; ii++) {
            const int i = tid + ii * 256;
            const int r = i >> 4, seg = 16 + (i & 15);
            CP_ASYNC16(sb + r * RA_STR + seg * 16, hh + (size_t)(row0 + r) * 256 + seg * 8);
        }
        CP_COMMIT();

        float acc[4][4];
#pragma unroll
        for (int nf = 0; nf < 4; nf++)
#pragma unroll
            for (int r = 0; r < 4; r++) acc[nf][r] = 0.0f;

        CP_WAIT1();
        __syncthreads();
#pragma unroll
        for (int ks = 0; ks < 8; ks++) {
            uint32_t ah4[4];
            ldmx4(ah4, sb + a_off + ks * 32);
#pragma unroll
            for (int nf = 0; nf < 4; nf++)
                mma_f16(acc[nf], ah4, breg[ks][nf]);
        }
        CP_WAIT0();
        __syncthreads();
#pragma unroll
        for (int ks = 8; ks < 16; ks++) {
            uint32_t ah4[4];
            ldmx4(ah4, sb + a_off + ks * 32);
#pragma unroll
            for (int nf = 0; nf < 4; nf++)
                mma_f16(acc[nf], ah4, breg[ks][nf]);
        }

        // ---- register-resident gate update; store next-H first ----
        __half2 hsv[2];
#pragma unroll
        for (int r = 0; r < 2; r++) {
            const int rloc = wm * 16 + qr + r * 8;
            const __half* zb = zxs + rloc * 64 + wn * 32 + qc2;
            const __half2 xi = *(const __half2*)(zb);
            const __half2 xf = *(const __half2*)(zb + 8);
            const __half2 xg = *(const __half2*)(zb + 16);
            const __half2 xo = *(const __half2*)(zb + 24);
            float hv0, hv1;
            {
                const int e = r * 2;
                const float zi = acc[0][e] + __half2float(xi.x);
                const float zf = acc[1][e] + __half2float(xf.x);
                const float zg = acc[2][e] + __half2float(xg.x);
                const float zo = acc[3][e] + __half2float(xo.x);
                const float cn = hsig(zf) * creg[e] + hsig(zi) * fast_tanh(zg);
                creg[e] = cn;
                hv0 = hsig(zo) * fast_tanh(cn);
            }
            {
                const int e = r * 2 + 1;
                const float zi = acc[0][e] + __half2float(xi.y);
                const float zf = acc[1][e] + __half2float(xf.y);
                const float zg = acc[2][e] + __half2float(xg.y);
                const float zo = acc[3][e] + __half2float(xo.y);
                const float cn = hsig(zf) * creg[e] + hsig(zi) * fast_tanh(zg);
                creg[e] = cn;
                hv1 = hsig(zo) * fast_tanh(cn);
            }
            hsv[r] = __half2(__float2half_rn(hv0), __float2half_rn(hv1));
            const int Rg = row0 + rloc;
            *(__half2*)(&g_Hh[pb ^ 1][(size_t)Rg * 256 + j0 + wn * 8 + qc2]) = hsv[r];
        }

        if (t < 127) {
            // arrive: bar.sync orders all threads' H stores before tid0's release
            __syncthreads();
            if (tid == 0) red_release_add(mine);

            // zx(t+1) prefetch FIRST (gets loads on the wire under peer skew)
            const int wn1 = dir ? (127 - (t + 1)) : (t + 1);
            const uint32_t zdst = sb + ROFF_ZX + (uint32_t)(((t + 1) & 1) * 8192);
#pragma unroll
            for (int ii = 0; ii < 2; ii++) {
                const int q = tid + ii * 256;
                const int r = q >> 3;
                const int m = q & 7;
                const int g = m & 3, hs = m >> 2;
                const __half* src = g_ZX + ((size_t)((row0 + r) & 255) * 128 + wn1) * 2048
                                   + dir * 1024 + g * 256 + j0 + hs * 8;
                CP_ASYNC16(zdst + (uint32_t)(r * 128 + hs * 64 + g * 16), src);
            }
            CP_COMMIT();
        }

        // HS output stores (off the cross-CTA critical path)
#pragma unroll
        for (int r = 0; r < 2; r++) {
            const int rloc = wm * 16 + qr + r * 8;
            const int Rg = row0 + rloc;
            const size_t hsoff = ((size_t)(Rg & 255) * 128 + w) * 512 + dir * 256
                               + j0 + wn * 8 + qc2;
            *(__half2*)(g_HSh + hsoff) = hsv[r];
        }
    }
}

// ---------------- LayerNorm over (W,C)=65536 (512 threads, shuffle reduce) ----------------
__global__ __launch_bounds__(512) void ln_kernel(
    const float* __restrict__ pre, const float* __restrict__ xres,
    const float* __restrict__ gamma, const float* __restrict__ beta,
    float* __restrict__ out, __half* __restrict__ sh, int mode)
{
    __shared__ float warp_s[16], warp_ss[16];
    __shared__ float s_mean, s_rstd;
    const int tid = threadIdx.x;
    const size_t base = (size_t)blockIdx.x * 65536;

    float s = 0.0f, ss = 0.0f;
    for (int i = tid * 4; i < 65536; i += 2048) {
        float4 v = *(const float4*)(pre + base + i);
        s  += v.x + v.y + v.z + v.w;
        ss += v.x * v.x + v.y * v.y + v.z * v.z + v.w * v.w;
    }
#pragma unroll
    for (int o = 16; o; o >>= 1) {
        s  += __shfl_xor_sync(0xFFFFFFFFu, s, o);
        ss += __shfl_xor_sync(0xFFFFFFFFu, ss, o);
    }
    if ((tid & 31) == 0) { warp_s[tid >> 5] = s; warp_ss[tid >> 5] = ss; }
    __syncthreads();
    if (tid < 32) {
        float a = (tid < 16) ? warp_s[tid] : 0.0f;
        float b = (tid < 16) ? warp_ss[tid] : 0.0f;
#pragma unroll
        for (int o = 8; o; o >>= 1) {
            a += __shfl_xor_sync(0xFFFFFFFFu, a, o);
            b += __shfl_xor_sync(0xFFFFFFFFu, b, o);
        }
        if (tid == 0) {
            const float mean = a * (1.0f / 65536.0f);
            const float var = b * (1.0f / 65536.0f) - mean * mean;
            s_mean = mean;
            s_rstd = rsqrtf(var + 1e-3f);
        }
    }
    __syncthreads();
    const float mean = s_mean, rstd = s_rstd;

    for (int i = tid * 4; i < 65536; i += 2048) {
        float4 v = *(const float4*)(pre + base + i);
        float4 g = *(const float4*)(gamma + i);
        float4 bb = *(const float4*)(beta + i);
        float4 r;
        r.x = (v.x - mean) * rstd * g.x + bb.x;
        r.y = (v.y - mean) * rstd * g.y + bb.y;
        r.z = (v.z - mean) * rstd * g.z + bb.z;
        r.w = (v.w - mean) * rstd * g.w + bb.w;
        if (mode == 0) {
            float4 xr = *(const float4*)(xres + base + i);
            r.x += xr.x; r.y += xr.y; r.z += xr.z; r.w += xr.w;
        } else {
            float4 o = *(const float4*)(out + base + i);
            r.x += o.x; r.y += o.y; r.z += o.z; r.w += o.w;
        }
        *(float4*)(out + base + i) = r;
        if (sh) {
            const size_t f = base + i;
            const size_t so = (f >> 9) * 1024 + (f & 511);
            *(__half2*)(sh + so)     = __half2(__float2half_rn(r.x), __float2half_rn(r.y));
            *(__half2*)(sh + so + 2) = __half2(__float2half_rn(r.z), __float2half_rn(r.w));
        }
    }
}

// ---------------- launch ----------------
extern "C" void kernel_launch(void* const* d_in, const int* in_sizes, int n_in,
                              void* d_out, int out_size)
{
    const float* x    = (const float*)d_in[0];
    const float* h0   = (const float*)d_in[1];
    const float* c0   = (const float*)d_in[2];
    const float* Wf   = (const float*)d_in[3];
    const float* Uf   = (const float*)d_in[4];
    const float* bf   = (const float*)d_in[5];
    const float* Wb   = (const float*)d_in[6];
    const float* Ub   = (const float*)d_in[7];
    const float* bb   = (const float*)d_in[8];
    const float* Wfc1 = (const float*)d_in[9];
    const float* bfc1 = (const float*)d_in[10];
    const float* g1   = (const float*)d_in[11];
    const float* b1   = (const float*)d_in[12];
    const float* Wi   = (const float*)d_in[13];
    const float* Ui   = (const float*)d_in[14];
    const float* bi   = (const float*)d_in[15];
    const float* Wfc2 = (const float*)d_in[16];
    const float* bfc2 = (const float*)d_in[17];
    const float* g2   = (const float*)d_in[18];
    const float* b2   = (const float*)d_in[19];

    float* out = (float*)d_out;
    float* h_out = out + OUT0;
    float* c_out = out + 2 * OUT0;
    const int full_out = (out_size >= (int)(3 * OUT0)) || out_size <= 0;

    float *fc, *bfc, *biP, *hcfb;
    __half *zx, *ah, *bt, *ut, *hsh;
    cudaGetSymbolAddress((void**)&zx,  g_ZX);
    cudaGetSymbolAddress((void**)&fc,  g_FC);
    cudaGetSymbolAddress((void**)&bfc, g_bfc);
    cudaGetSymbolAddress((void**)&biP, g_biP);
    cudaGetSymbolAddress((void**)&ah,  g_Ah);
    cudaGetSymbolAddress((void**)&bt,  g_Bt);
    cudaGetSymbolAddress((void**)&ut,  g_Ut);
    cudaGetSymbolAddress((void**)&hsh, g_HSh);
    cudaGetSymbolAddress((void**)&hcfb, g_HCfb);

    cudaFuncSetAttribute(tcgemm, cudaFuncAttributeMaxDynamicSharedMemorySize, GEMM_SMEM);
    cudaFuncSetAttribute(tcgemm_h, cudaFuncAttributeMaxDynamicSharedMemorySize, GEMM_SMEM);
    cudaFuncSetAttribute(tcgemm_gates, cudaFuncAttributeMaxDynamicSharedMemorySize, GEMM_SMEM);
    cudaFuncSetAttribute(recurrence2, cudaFuncAttributeMaxDynamicSharedMemorySize, RSMEM);

    // ---- all prep (weights, biases, x/h0 converts) in ONE launch ----
    prep_all<<<dim3(64, 16, 11), dim3(32, 8)>>>(Wf, Wb, Uf, Ub, Wfc1, Wfc2, Wi, Ui,
                                                bf, bb, bi, x, h0, bt, ut, ah, bfc, biP);

    // ---- combined intra input projection: ZX(fp16) = x @ [Wf|Wb] + [bf|bb] ----
    tcgemm_h<<<dim3(16, 256), 256, GEMM_SMEM>>>(ah, bt, zx, bfc, MROWS, 2048, 512, 1024);

    // ---- recurrence ----
    recurrence2<<<128, 256, RSMEM>>>(ut);

    // ---- fc1 (A = HS) ----
    tcgemm<<<dim3(4, 256), 256, GEMM_SMEM>>>(hsh, bt + OFF_FC1, fc, bfc1, MROWS, 512, 512, 512);

    // ---- LN1 + residual -> out, fused convert (Ah cols 0..511) ----
    ln_kernel<<<256, 512>>>(fc, x, g1, b1, out, ah, 0);

    // ---- inter: single K=1024 GEMM with register-gate epilogue ----
    float* hptr = full_out ? h_out : hcfb;
    float* cptr = full_out ? c_out : (hcfb + (size_t)MROWS * 512);
    tcgemm_gates<<<dim3(16, 256), 256, GEMM_SMEM>>>(ah, bt + OFF_INTER, biP, c0,
                                                    hptr, cptr, hsh, 1024, 1024);

    // ---- fc2 (A = h in g_HSh) ----
    tcgemm<<<dim3(4, 256), 256, GEMM_SMEM>>>(hsh, bt + OFF_FC2, fc, bfc2, MROWS, 512, 512, 512);

    // ---- LN2 accumulate into out ----
    ln_kernel<<<256, 512>>>(fc, nullptr, g2, b2, out, nullptr, 1);
}